// round 9
// baseline (speedup 1.0000x reference)
#include <cuda_runtime.h>
#include <cuda_bf16.h>
#include <cstdint>

#define BB 4096
#define MM 327
#define NN 800
#define NB (BB*NN)              // 3,276,800 per state buffer
#define NROWS 968               // 22*44 padded pixel rows
#define NHWC_STRIDE (NROWS*32)  // floats per image in NHWC buffers
#define SROW0 48
#define SROWS 1086              // 48 guard + 968 data + 70 guard rows
#define ASTRIDE 20              // words per row in smem A ({20q+c} distinct mod 32)
#define BSTRIDE 40              // words per icpair in smem B ({40c+q} distinct mod 32)
#define BWORDS (9*16*BSTRIDE)   // 5760 words per (set,half)
#define WBF_BLOCKS 46

typedef unsigned long long ull;

// ---------------- device scratch (static, allowed) ----------------
__device__ float g_PhiTPhi[NN*NN];
__device__ float g_PhiTb[NB];
__device__ float g_Xbuf[2*NB];
__device__ float g_Lbuf[2*NB];
__device__ float g_zerobuf[NB];
__device__ float g_zflat[NB];
__device__ float g_hatx[NB];
__device__ float g_gemm[NB];
__device__ float g_nA[(size_t)BB*NHWC_STRIDE];   // NHWC feature buffer A
__device__ float g_nB[(size_t)BB*NHWC_STRIDE];   // NHWC feature buffer B
__device__ uint32_t g_wpk[2*2*BWORDS];           // [set][hi/lo][BWORDS] packed bf16x2

__constant__ int c_dtap[9] = {-45, -44, -43, -1, 0, 1, 43, 44, 45};

// ---------------- helpers ----------------
__device__ __forceinline__ uint32_t pkbf2(__nv_bfloat16 e0, __nv_bfloat16 e1) {
    return ((uint32_t)__bfloat16_as_ushort(e1) << 16) | (uint32_t)__bfloat16_as_ushort(e0);
}
__device__ __forceinline__ uint32_t cvt2bf(float hi, float lo) {
    uint32_t r;
    asm("cvt.rn.satfinite.bf16x2.f32 %0, %1, %2;" : "=r"(r) : "f"(hi), "f"(lo));
    return r;
}

__device__ __forceinline__ void mma_bf16(float* d, const uint32_t* a, uint32_t b0, uint32_t b1) {
    asm volatile(
        "mma.sync.aligned.m16n8k16.row.col.f32.bf16.bf16.f32 "
        "{%0,%1,%2,%3}, {%4,%5,%6,%7}, {%8,%9}, {%0,%1,%2,%3};"
        : "+f"(d[0]), "+f"(d[1]), "+f"(d[2]), "+f"(d[3])
        : "r"(a[0]), "r"(a[1]), "r"(a[2]), "r"(a[3]), "r"(b0), "r"(b1));
}

__device__ __forceinline__ void ldAfrag(uint32_t* a, const uint32_t* Aarr, int baserow,
                                        int ks, int q, int c) {
    int tap = ks >> 1, icb = (ks & 1) * 8;
    const uint32_t* Ap = Aarr + (baserow + c_dtap[tap] + q) * ASTRIDE + icb + c;
    a[0] = Ap[0];
    a[1] = Ap[8 * ASTRIDE];
    a[2] = Ap[4];
    a[3] = Ap[8 * ASTRIDE + 4];
    a[4] = Ap[16 * ASTRIDE];
    a[5] = Ap[24 * ASTRIDE];
    a[6] = Ap[16 * ASTRIDE + 4];
    a[7] = Ap[24 * ASTRIDE + 4];
}
__device__ __forceinline__ void ldBfrag(uint32_t* b, const uint32_t* Barr,
                                        int ks, int q, int c) {
    int tap = ks >> 1, icb = (ks & 1) * 8;
    const uint32_t* Bp = Barr + tap * (16 * BSTRIDE) + (icb + c) * BSTRIDE + q;
#pragma unroll
    for (int o = 0; o < 4; o++) {
        b[2 * o]     = Bp[o * 8];
        b[2 * o + 1] = Bp[4 * BSTRIDE + o * 8];
    }
}

// ---------------- small GEMMs (proven R4 versions) ----------------

__global__ __launch_bounds__(256) void gemm_AtB(const float* __restrict__ A,
                                                const float* __restrict__ B,
                                                float* __restrict__ C,
                                                int K, int I, int J)
{
    __shared__ float As[16][68];
    __shared__ float Bs[16][68];
    int tid = threadIdx.x;
    int tx = tid & 15, ty = tid >> 4;
    int i0 = blockIdx.y * 64, j0 = blockIdx.x * 64;
    float acc[4][4];
#pragma unroll
    for (int a = 0; a < 4; a++)
#pragma unroll
        for (int b = 0; b < 4; b++) acc[a][b] = 0.f;

    int kr = tid >> 4, c4 = (tid & 15) * 4;
    for (int k0 = 0; k0 < K; k0 += 16) {
        bool kv = (k0 + kr) < K;
#pragma unroll
        for (int j = 0; j < 4; j++) {
            int ii = i0 + c4 + j;
            As[kr][c4 + j] = (kv && ii < I) ? A[(size_t)(k0 + kr) * I + ii] : 0.f;
            int jj = j0 + c4 + j;
            Bs[kr][c4 + j] = (kv && jj < J) ? B[(size_t)(k0 + kr) * J + jj] : 0.f;
        }
        __syncthreads();
#pragma unroll
        for (int kk = 0; kk < 16; kk++) {
            float a[4], b[4];
#pragma unroll
            for (int i = 0; i < 4; i++) a[i] = As[kk][ty * 4 + i];
#pragma unroll
            for (int j = 0; j < 4; j++) b[j] = Bs[kk][tx * 4 + j];
#pragma unroll
            for (int i = 0; i < 4; i++)
#pragma unroll
                for (int j = 0; j < 4; j++) acc[i][j] += a[i] * b[j];
        }
        __syncthreads();
    }
#pragma unroll
    for (int i = 0; i < 4; i++) {
        int r = i0 + ty * 4 + i;
        if (r < I) {
#pragma unroll
            for (int j = 0; j < 4; j++) {
                int n = j0 + tx * 4 + j;
                if (n < J) C[(size_t)r * J + n] = acc[i][j];
            }
        }
    }
}

__global__ __launch_bounds__(256) void gemm_AB(const float* __restrict__ A,
                                               const float* __restrict__ B,
                                               float* __restrict__ C,
                                               int M, int K, int N)
{
    __shared__ float As[16][132];
    __shared__ float Bs[16][68];
    int tid = threadIdx.x;
    int tx = tid & 15, ty = tid >> 4;
    int row0 = blockIdx.y * 128, n0 = blockIdx.x * 64;

    float acc[8][4];
#pragma unroll
    for (int a = 0; a < 8; a++)
#pragma unroll
        for (int b = 0; b < 4; b++) acc[a][b] = 0.f;

    int arow = tid >> 1;
    int ak0 = (tid & 1) * 8;
    int kr = tid >> 4, nc = (tid & 15) * 4;

    for (int k0 = 0; k0 < K; k0 += 16) {
        const float* aptr = A + (size_t)(row0 + arow) * K + k0 + ak0;
#pragma unroll
        for (int j = 0; j < 8; j++) {
            int k = k0 + ak0 + j;
            As[ak0 + j][arow] = (k < K) ? aptr[j] : 0.f;
        }
#pragma unroll
        for (int j = 0; j < 4; j++) {
            int n = n0 + nc + j;
            Bs[kr][nc + j] = ((k0 + kr) < K && n < N) ? B[(size_t)(k0 + kr) * N + n] : 0.f;
        }
        __syncthreads();
#pragma unroll
        for (int kk = 0; kk < 16; kk++) {
            float a[8], b[4];
#pragma unroll
            for (int i = 0; i < 8; i++) a[i] = As[kk][ty * 8 + i];
#pragma unroll
            for (int j = 0; j < 4; j++) b[j] = Bs[kk][tx * 4 + j];
#pragma unroll
            for (int i = 0; i < 8; i++)
#pragma unroll
                for (int j = 0; j < 4; j++) acc[i][j] += a[i] * b[j];
        }
        __syncthreads();
    }
#pragma unroll
    for (int i = 0; i < 8; i++) {
        int r = row0 + ty * 8 + i;
#pragma unroll
        for (int j = 0; j < 4; j++) {
            int n = n0 + tx * 4 + j;
            if (n < N) C[(size_t)r * N + n] = acc[i][j];
        }
    }
}

__global__ void k_wloss(const float* __restrict__ W, float* __restrict__ C)
{
    __shared__ float sA[16][17];
    __shared__ float sB[16][17];
    int tx = threadIdx.x, ty = threadIdx.y;
    int i0 = blockIdx.y * 16, j0 = blockIdx.x * 16;
    float acc = 0.f;
    for (int k0 = 0; k0 < 800; k0 += 16) {
        sA[ty][tx] = (i0 + ty < MM) ? W[(size_t)(i0 + ty) * NN + k0 + tx] : 0.f;
        sB[ty][tx] = (j0 + ty < MM) ? W[(size_t)(j0 + ty) * NN + k0 + tx] : 0.f;
        __syncthreads();
#pragma unroll
        for (int kk = 0; kk < 16; kk++) acc += sA[ty][kk] * sB[tx][kk];
        __syncthreads();
    }
    int i = i0 + ty, j = j0 + tx;
    if (i < MM && j < MM) C[i * MM + j] = acc - (i == j ? 1.f : 0.f);
}

// ---------------- elementwise ----------------

__global__ void k_hatx(const float* __restrict__ Xc, const float* __restrict__ Xp,
                       float* __restrict__ hx,
                       const float* __restrict__ tx_arr, int layer)
{
    int i = blockIdx.x * blockDim.x + threadIdx.x;
    if (i >= NB) return;
    float t = tx_arr[layer];
    float xc = Xc[i];
    hx[i] = xc + t * (xc - Xp[i]);
}

__global__ void k_xepi(const float* __restrict__ hx, const float* __restrict__ gm,
                       const float* __restrict__ PhiTb,
                       const float* __restrict__ Zg, const float* __restrict__ Lg,
                       const float* __restrict__ Zc, const float* __restrict__ Zp,
                       const float* __restrict__ Lz,
                       float* __restrict__ Xn, float* __restrict__ zf,
                       const float* __restrict__ b1a, const float* __restrict__ b2a,
                       const float* __restrict__ ha, const float* __restrict__ tza,
                       int layer)
{
    int i = blockIdx.x * blockDim.x + threadIdx.x;
    if (i >= NB) return;
    float b1 = b1a[layer], b2 = b2a[layer], hh = ha[layer], tz = tza[layer];
    float hxv = hx[i];
    float grad = PhiTb[i] - gm[i] + b1 * (Zg[i] - hxv) - Lg[i];
    float xn = hxv + hh * grad;
    Xn[i] = xn;
    float zc = Zc[i];
    float hz = zc + tz * (zc - Zp[i]);
    zf[i] = hz + hh * (Lz[i] + b2 * (xn - hz));
}

// ---------------- fused prep: zero NHWC padding rows + pack bf16 weights ----

__global__ __launch_bounds__(128) void k_prep(float* __restrict__ a, float* __restrict__ b,
                                              const float* __restrict__ c2f,
                                              const float* __restrict__ c1b,
                                              uint32_t* __restrict__ wpk)
{
    int t = threadIdx.x;
    if (blockIdx.x < BB) {
        int img = blockIdx.x;
        int row;
        if (t < 44) row = t;
        else if (t < 88) row = 924 + (t - 44);
        else { int j = t - 88; row = (1 + (j >> 1)) * 44 + ((j & 1) ? 43 : 0); }
        float4 z = make_float4(0.f, 0.f, 0.f, 0.f);
        float4* pa = (float4*)(a + (size_t)img * NHWC_STRIDE + row * 32);
        float4* pb = (float4*)(b + (size_t)img * NHWC_STRIDE + row * 32);
#pragma unroll
        for (int q = 0; q < 8; q++) { pa[q] = z; pb[q] = z; }
    } else {
        int base = (blockIdx.x - BB) * 128 + t;
        for (int i = base; i < 2 * BWORDS; i += WBF_BLOCKS * 128) {
            int set = i / BWORDS, rem = i - set * BWORDS;
            int tap = rem / (16 * BSTRIDE), rem2 = rem - tap * (16 * BSTRIDE);
            int icp = rem2 / BSTRIDE, oc = rem2 - icp * BSTRIDE;
            const float* src = set ? c1b : c2f;
            uint32_t whi = 0u, wlo = 0u;
            if (oc < 32) {
                float w0 = src[oc * 288 + (2 * icp) * 9 + tap];
                float w1 = src[oc * 288 + (2 * icp + 1) * 9 + tap];
                __nv_bfloat16 h0 = __float2bfloat16_rn(w0), h1 = __float2bfloat16_rn(w1);
                __nv_bfloat16 l0 = __float2bfloat16_rn(w0 - __bfloat162float(h0));
                __nv_bfloat16 l1 = __float2bfloat16_rn(w1 - __bfloat162float(h1));
                whi = pkbf2(h0, h1);
                wlo = pkbf2(l0, l1);
            }
            int off = tap * (16 * BSTRIDE) + icp * BSTRIDE + oc;
            wpk[set * 2 * BWORDS + off] = whi;
            wpk[set * 2 * BWORDS + BWORDS + off] = wlo;
        }
    }
}

// ---------------- convolutions ----------------

// 1->32 channels, 3x3 SAME, relu. One block per image.
// mode 0: src = zf (precomputed). mode 1 (layer 0): src = PhiTb; computes
// x = h0*src, X1 = x, zf = h0*b2*x inline and writes both state buffers.
__global__ __launch_bounds__(256) void conv1to32_nhwc(const float* __restrict__ src,
                                                      const float* __restrict__ w,
                                                      float* __restrict__ out,
                                                      int mode,
                                                      const float* __restrict__ h_arr,
                                                      const float* __restrict__ b2_arr,
                                                      float* __restrict__ X1,
                                                      float* __restrict__ zfout)
{
    __shared__ float sZ[NROWS];
    __shared__ float sW[288];    // [tap][oc]
    int img = blockIdx.x, tid = threadIdx.x;
    for (int i = tid; i < NROWS; i += 256) sZ[i] = 0.f;
    for (int i = tid; i < 288; i += 256) {
        int oc = i / 9, tap = i - oc * 9;
        sW[tap * 32 + oc] = w[i];
    }
    __syncthreads();
    const float* gin = src + (size_t)img * NN;
    if (mode == 1) {
        float h0 = h_arr[0], b2 = b2_arr[0];
        for (int i = tid; i < NN; i += 256) {
            float x = h0 * gin[i];
            X1[(size_t)img * NN + i] = x;
            float zfv = h0 * b2 * x;
            zfout[(size_t)img * NN + i] = zfv;
            int r = i / 40, c = i - r * 40;
            sZ[(r + 1) * 44 + c + 1] = zfv;
        }
    } else {
        for (int i = tid; i < NN; i += 256) {
            int r = i / 40, c = i - r * 40;
            sZ[(r + 1) * 44 + c + 1] = gin[i];
        }
    }
    __syncthreads();
    const int dtap[9] = {-45, -44, -43, -1, 0, 1, 43, 44, 45};
    float* gout = out + (size_t)img * NHWC_STRIDE;
    for (int p = tid; p < NN; p += 256) {
        int r = p / 40, c = p - r * 40;
        int pp = (r + 1) * 44 + (c + 1);
        float acc[32];
#pragma unroll
        for (int oc = 0; oc < 32; oc++) acc[oc] = 0.f;
#pragma unroll
        for (int t = 0; t < 9; t++) {
            float xv = sZ[pp + dtap[t]];
            const float* wt = sW + t * 32;
#pragma unroll
            for (int oc = 0; oc < 32; oc++) acc[oc] += wt[oc] * xv;
        }
        float4* ob = (float4*)(gout + pp * 32);
#pragma unroll
        for (int q = 0; q < 8; q++) {
            float4 v = make_float4(fmaxf(acc[q*4+0], 0.f), fmaxf(acc[q*4+1], 0.f),
                                   fmaxf(acc[q*4+2], 0.f), fmaxf(acc[q*4+3], 0.f));
            ob[q] = v;
        }
    }
}

// 32->32 channels, 3x3 SAME via mma.sync bf16 (3-pass hi/lo split).
// NHWC fp32 in/out. One CTA per image, 256 threads (8 warps).
// Conflict-free smem strides; warp computes a PAIR of 32-row units sharing
// B fragments; depth-1 register pipeline overlaps LDS with mma.
__global__ __launch_bounds__(256) void conv32_mma(const float* __restrict__ in,
                                                  const uint32_t* __restrict__ wpk,
                                                  float* __restrict__ outp,
                                                  const float* __restrict__ thr_arr,
                                                  int layer, int do_soft, int do_relu)
{
    extern __shared__ uint32_t smw[];
    uint32_t* sAhi = smw;                       // SROWS*ASTRIDE
    uint32_t* sAlo = smw + SROWS * ASTRIDE;
    uint32_t* sBhi = smw + 2 * SROWS * ASTRIDE; // BWORDS
    uint32_t* sBlo = sBhi + BWORDS;
    int img = blockIdx.x, tid = threadIdx.x;

    // zero guard rows [0,48) and [1016,1086)
    for (int i = tid; i < 48 * ASTRIDE; i += 256) { sAhi[i] = 0u; sAlo[i] = 0u; }
    for (int i = tid; i < 70 * ASTRIDE; i += 256) {
        sAhi[1016 * ASTRIDE + i] = 0u; sAlo[1016 * ASTRIDE + i] = 0u;
    }
    // weights
    for (int i = tid; i < BWORDS; i += 256) { sBhi[i] = wpk[i]; sBlo[i] = wpk[BWORDS + i]; }

    // main fill: fp32 NHWC -> (soft) -> bf16 hi/lo packed pairs
    float sthr = do_soft ? fabsf(thr_arr[layer]) : 0.f;
    const float4* g4 = (const float4*)(in + (size_t)img * NHWC_STRIDE);
    for (int i = tid; i < NROWS * 8; i += 256) {
        float4 v = g4[i];
        if (do_soft) {
#pragma unroll
            for (int j = 0; j < 4; j++) {
                float x = (&v.x)[j];
                float a = fabsf(x) - sthr;
                (&v.x)[j] = (a > 0.f) ? (x > 0.f ? a : -a) : 0.f;
            }
        }
        int row = i >> 3, qq = i & 7;
        int base = (SROW0 + row) * ASTRIDE + qq * 2;
        uint32_t hi01 = cvt2bf(v.y, v.x);
        uint32_t hi23 = cvt2bf(v.w, v.z);
        float h0 = __uint_as_float(hi01 << 16);
        float h1 = __uint_as_float(hi01 & 0xFFFF0000u);
        float h2 = __uint_as_float(hi23 << 16);
        float h3 = __uint_as_float(hi23 & 0xFFFF0000u);
        uint32_t lo01 = cvt2bf(v.y - h1, v.x - h0);
        uint32_t lo23 = cvt2bf(v.w - h3, v.z - h2);
        sAhi[base]     = hi01;
        sAhi[base + 1] = hi23;
        sAlo[base]     = lo01;
        sAlo[base + 1] = lo23;
    }
    __syncthreads();

    int warp = tid >> 5, lane = tid & 31;
    int q = lane >> 2, c = lane & 3;
    float* gout = outp + (size_t)img * NHWC_STRIDE;

    for (int up = 0; up < 2; up++) {
        int u1 = warp + up * 8;          // 0..15
        int u2 = u1 + 16;                // 16..31
        bool v2 = (u2 < 31);
        int r1 = SROW0 + u1 * 32;
        int r2 = SROW0 + (v2 ? u2 : u1) * 32;

        float acc[2][2][4][4];
#pragma unroll
        for (int uu = 0; uu < 2; uu++)
#pragma unroll
            for (int s = 0; s < 2; s++)
#pragma unroll
                for (int o = 0; o < 4; o++)
#pragma unroll
                    for (int j = 0; j < 4; j++) acc[uu][s][o][j] = 0.f;

#pragma unroll
        for (int pass = 0; pass < 3; pass++) {
            const uint32_t* Aarr = (pass == 2) ? sAlo : sAhi;
            const uint32_t* Barr = (pass == 1) ? sBlo : sBhi;
            uint32_t Af[2][2][8], Bf[2][8];
            ldAfrag(Af[0][0], Aarr, r1, 0, q, c);
            ldAfrag(Af[0][1], Aarr, r2, 0, q, c);
            ldBfrag(Bf[0], Barr, 0, q, c);
#pragma unroll
            for (int ks = 0; ks < 18; ks++) {
                int cur = ks & 1, nxt = cur ^ 1;
                if (ks < 17) {
                    ldAfrag(Af[nxt][0], Aarr, r1, ks + 1, q, c);
                    ldAfrag(Af[nxt][1], Aarr, r2, ks + 1, q, c);
                    ldBfrag(Bf[nxt], Barr, ks + 1, q, c);
                }
#pragma unroll
                for (int o = 0; o < 4; o++) {
                    uint32_t b0 = Bf[cur][2 * o], b1 = Bf[cur][2 * o + 1];
                    mma_bf16(acc[0][0][o], Af[cur][0] + 0, b0, b1);
                    mma_bf16(acc[0][1][o], Af[cur][0] + 4, b0, b1);
                    mma_bf16(acc[1][0][o], Af[cur][1] + 0, b0, b1);
                    mma_bf16(acc[1][1][o], Af[cur][1] + 4, b0, b1);
                }
            }
        }

        // epilogue for both units
#pragma unroll
        for (int uu = 0; uu < 2; uu++) {
            if (uu == 1 && !v2) break;
            int u = uu ? u2 : u1;
#pragma unroll
            for (int s = 0; s < 2; s++) {
                int grow0 = u * 32 + s * 16 + q;
#pragma unroll
                for (int half = 0; half < 2; half++) {
                    int grow = grow0 + half * 8;
                    int rr = grow / 44, cc = grow - rr * 44;
                    bool valid = (grow < NROWS) && rr >= 1 && rr <= 20 && cc >= 1 && cc <= 40;
                    if (valid) {
                        float* ob = gout + grow * 32 + c * 2;
#pragma unroll
                        for (int o = 0; o < 4; o++) {
                            float x0 = acc[uu][s][o][half * 2 + 0];
                            float x1 = acc[uu][s][o][half * 2 + 1];
                            if (do_relu) { x0 = fmaxf(x0, 0.f); x1 = fmaxf(x1, 0.f); }
                            *(float2*)(ob + o * 8) = make_float2(x0, x1);
                        }
                    }
                }
            }
        }
    }
}

// 32->1 channels, 3x3 SAME, NHWC input. variant 0: Z_new + fused L-update.
// variant 1: (conv - z_flat) into syms.
__global__ __launch_bounds__(512) void conv32to1_nhwc(const float* __restrict__ in,
                                                      const float* __restrict__ w288,
                                                      float* __restrict__ outp,
                                                      const float* __restrict__ zf,
                                                      float* __restrict__ Ln,
                                                      const float* __restrict__ Lc,
                                                      const float* __restrict__ Lp,
                                                      const float* __restrict__ Xn,
                                                      const float* __restrict__ h_arr,
                                                      const float* __restrict__ b1_arr,
                                                      const float* __restrict__ tL_arr,
                                                      int layer, int variant)
{
    extern __shared__ float smemf[];
    float* sIn = smemf;                 // 968*32
    float* sW  = smemf + NROWS * 32;    // [tap][ic]
    int img = blockIdx.x, tid = threadIdx.x;
    const float4* g4 = (const float4*)(in + (size_t)img * NHWC_STRIDE);
    float4* s4 = (float4*)sIn;
    for (int i = tid; i < NROWS * 8; i += 512) s4[i] = g4[i];
    for (int i = tid; i < 288; i += 512) {
        int ic = i / 9, tap = i - ic * 9;
        sW[tap * 32 + ic] = w288[i];
    }
    __syncthreads();

    const int dtap[9] = {-45, -44, -43, -1, 0, 1, 43, 44, 45};
    size_t base = (size_t)img * NN;
    for (int p = tid; p < NN; p += 512) {
        int r = p / 40, c = p - r * 40;
        int pp = (r + 1) * 44 + (c + 1);
        float acc = 0.f;
#pragma unroll
        for (int t = 0; t < 9; t++) {
            const float4* a4 = (const float4*)(sIn + (pp + dtap[t]) * 32);
            const float4* wv = (const float4*)(sW + t * 32);
#pragma unroll
            for (int qq = 0; qq < 8; qq++) {
                float4 x = a4[qq], ww = wv[qq];
                acc += x.x * ww.x + x.y * ww.y + x.z * ww.z + x.w * ww.w;
            }
        }
        if (variant == 0) {
            outp[base + p] = acc;
            float lc = Lc[base + p], lp = Lp[base + p];
            float hatL = lc + tL_arr[layer] * (lc - lp);
            Ln[base + p] = hatL + h_arr[layer] * b1_arr[layer] * (Xn[base + p] - acc);
        } else {
            outp[base + p] = acc - zf[base + p];
        }
    }
}

// ---------------- host ----------------

extern "C" void kernel_launch(void* const* d_in, const int* in_sizes, int n_in,
                              void* d_out, int out_size)
{
    const float* y    = (const float*)d_in[0];
    const float* W    = (const float*)d_in[2];
    const float* beta1 = (const float*)d_in[3];
    const float* beta2 = (const float*)d_in[4];
    const float* h_   = (const float*)d_in[5];
    const float* sthr = (const float*)d_in[6];
    const float* thx  = (const float*)d_in[7];
    const float* thz  = (const float*)d_in[8];
    const float* thL  = (const float*)d_in[9];
    const float* c1f  = (const float*)d_in[10];
    const float* c2f  = (const float*)d_in[11];
    const float* c1b  = (const float*)d_in[12];
    const float* c2b  = (const float*)d_in[13];

    float* out = (float*)d_out;
    float* Zs = out;
    float* syms = out + (size_t)9 * NB;
    float* wlo = out + (size_t)18 * NB;

    float *pPhiTPhi, *pPhiTb, *pX, *pL, *pZero, *pZf, *pHx, *pGm, *pNA, *pNB;
    uint32_t* pWPK;
    cudaGetSymbolAddress((void**)&pPhiTPhi, g_PhiTPhi);
    cudaGetSymbolAddress((void**)&pPhiTb, g_PhiTb);
    cudaGetSymbolAddress((void**)&pX, g_Xbuf);
    cudaGetSymbolAddress((void**)&pL, g_Lbuf);
    cudaGetSymbolAddress((void**)&pZero, g_zerobuf);
    cudaGetSymbolAddress((void**)&pZf, g_zflat);
    cudaGetSymbolAddress((void**)&pHx, g_hatx);
    cudaGetSymbolAddress((void**)&pGm, g_gemm);
    cudaGetSymbolAddress((void**)&pNA, g_nA);
    cudaGetSymbolAddress((void**)&pNB, g_nB);
    cudaGetSymbolAddress((void**)&pWPK, g_wpk);

    const int SMMAW = (2 * SROWS * ASTRIDE + 2 * BWORDS) * 4;  // 219,840 B
    const int SM1   = (NROWS * 32 + 288) * 4;                  // 125,056 B
    cudaFuncSetAttribute(conv32_mma, cudaFuncAttributeMaxDynamicSharedMemorySize, SMMAW);
    cudaFuncSetAttribute(conv32to1_nhwc, cudaFuncAttributeMaxDynamicSharedMemorySize, SM1);

    cudaMemsetAsync(pZero, 0, (size_t)NB * 4);

    float* Xslot[2] = {pX, pX + NB};
    float* Lslot[2] = {pL, pL + NB};

    // prep + layer-0 front (ordered so the 4th kernel launch is conv32_mma,
    // which is what the profiler's fixed skip-count captures)
    k_prep<<<BB + WBF_BLOCKS, 128>>>(pNA, pNB, c2f, c1b, pWPK);
    gemm_AB<<<dim3(13, 32), 256>>>(y, W, pPhiTb, BB, MM, NN);

    int xcur = 0, xprev = -1;
    int lcur = 0, lprev = -1;

    for (int i = 0; i < 9; i++) {
        float* Xn;
        if (i == 0) {
            Xn = Xslot[0];
            // conv1to32 in layer-0 mode computes X1 and zf inline from PhiTb
            conv1to32_nhwc<<<BB, 256>>>(pPhiTb, c1f, pNA, 1, h_, beta2, Xn, pZf);
            xcur = 0; xprev = -1;
        } else {
            const float* Xc = Xslot[xcur];
            const float* Xp = (xprev < 0) ? pZero : Xslot[xprev];
            const float* Lc_ = Lslot[lcur];
            const float* Zc = Zs + (size_t)(i - 1) * NB;
            const float* Zp = (i >= 2) ? Zs + (size_t)(i - 2) * NB : pZero;
            const float* Zg = (i >= 2) ? Zc : pZero;
            const float* Lg = (i >= 2) ? Lc_ : pZero;
            const float* Lz = (i >= 2) ? Lc_ : pZero;
            int xnew = (xprev < 0) ? 1 : xprev;
            Xn = Xslot[xnew];
            k_hatx<<<NB / 256, 256>>>(Xc, Xp, pHx, thx, i);
            gemm_AB<<<dim3(13, 32), 256>>>(pHx, pPhiTPhi, pGm, BB, NN, NN);
            k_xepi<<<NB / 256, 256>>>(pHx, pGm, pPhiTb, Zg, Lg, Zc, Zp, Lz,
                                      Xn, pZf, beta1, beta2, h_, thz, i);
            xprev = xcur; xcur = xnew;
            conv1to32_nhwc<<<BB, 256>>>(pZf, c1f, pNA, 0, h_, beta2, nullptr, nullptr);
        }

        conv32_mma<<<BB, 256, SMMAW>>>(pNA, pWPK,              pNB, sthr, i, 0, 0); // x_fwd
        conv32_mma<<<BB, 256, SMMAW>>>(pNB, pWPK + 2 * BWORDS, pNA, sthr, i, 1, 1); // t1
        {
            const float* Lc_ = (i == 0) ? pZero : Lslot[lcur];
            const float* Lp_ = (i == 0) ? pZero : ((lprev < 0) ? pZero : Lslot[lprev]);
            int lnew = (i == 0) ? 0 : ((lprev < 0) ? 1 : lprev);
            conv32to1_nhwc<<<BB, 512, SM1>>>(pNA, c2b, Zs + (size_t)i * NB, nullptr,
                                             Lslot[lnew], Lc_, Lp_, Xn,
                                             h_, beta1, thL, i, 0);
            if (i > 0) { lprev = lcur; lcur = lnew; }
            else { lcur = 0; lprev = -1; }
        }
        conv32_mma<<<BB, 256, SMMAW>>>(pNB, pWPK + 2 * BWORDS, pNA, sthr, i, 0, 1); // t2
        conv32to1_nhwc<<<BB, 512, SM1>>>(pNA, c2b, syms + (size_t)i * NB, pZf,
                                         nullptr, nullptr, nullptr, nullptr,
                                         h_, beta1, thL, i, 1);

        if (i == 0) {
            // PhiTPhi first consumed by layer 1's gemm; deferred here so the
            // profiler's capture window lands on conv32_mma above.
            gemm_AtB<<<dim3(13, 13), 256>>>(W, W, pPhiTPhi, MM, NN, NN);
        }
    }

    k_wloss<<<dim3(21, 21), dim3(16, 16)>>>(W, wlo);
}

// round 10
// speedup vs baseline: 1.5543x; 1.5543x over previous
#include <cuda_runtime.h>
#include <cuda_bf16.h>
#include <cstdint>

#define BB 4096
#define MM 327
#define NN 800
#define NB (BB*NN)              // 3,276,800 per state buffer
#define NROWS 968               // 22*44 padded pixel rows
#define NHWC_STRIDE (NROWS*32)  // floats per image in NHWC buffers
#define SROW0 48
#define SROWS 1086              // 48 guard + 968 data + 70 guard rows
#define ASTRIDE 20              // words per row in smem A ({20q+c} distinct mod 32)
#define BSTRIDE 40              // words per icpair in smem B ({40c+q} distinct mod 32)
#define BWORDS (9*16*BSTRIDE)   // 5760 words per (set,half)
#define WBF_BLOCKS 46

typedef unsigned long long ull;

// ---------------- device scratch (static, allowed) ----------------
__device__ float g_PhiTPhi[NN*NN];
__device__ float g_PhiTb[NB];
__device__ float g_Xbuf[2*NB];
__device__ float g_Lbuf[2*NB];
__device__ float g_zerobuf[NB];
__device__ float g_zflat[NB];
__device__ float g_hatx[NB];
__device__ float g_gemm[NB];
__device__ float g_nA[(size_t)BB*NHWC_STRIDE];   // NHWC feature buffer A
__device__ float g_nB[(size_t)BB*NHWC_STRIDE];   // NHWC feature buffer B
__device__ uint32_t g_wpk[2*2*BWORDS];           // [set][hi/lo][BWORDS] packed bf16x2

__constant__ int c_dtap[9] = {-45, -44, -43, -1, 0, 1, 43, 44, 45};

// ---------------- helpers ----------------
__device__ __forceinline__ uint32_t pkbf2(__nv_bfloat16 e0, __nv_bfloat16 e1) {
    return ((uint32_t)__bfloat16_as_ushort(e1) << 16) | (uint32_t)__bfloat16_as_ushort(e0);
}
__device__ __forceinline__ uint32_t cvt2bf(float hi, float lo) {
    uint32_t r;
    asm("cvt.rn.satfinite.bf16x2.f32 %0, %1, %2;" : "=r"(r) : "f"(hi), "f"(lo));
    return r;
}

__device__ __forceinline__ void mma_bf16(float* d, const uint32_t* a, uint32_t b0, uint32_t b1) {
    asm volatile(
        "mma.sync.aligned.m16n8k16.row.col.f32.bf16.bf16.f32 "
        "{%0,%1,%2,%3}, {%4,%5,%6,%7}, {%8,%9}, {%0,%1,%2,%3};"
        : "+f"(d[0]), "+f"(d[1]), "+f"(d[2]), "+f"(d[3])
        : "r"(a[0]), "r"(a[1]), "r"(a[2]), "r"(a[3]), "r"(b0), "r"(b1));
}

__device__ __forceinline__ void ldAfrag(uint32_t* a, const uint32_t* Aarr, int baserow,
                                        int ks, int q, int c) {
    int tap = ks >> 1, icb = (ks & 1) * 8;
    const uint32_t* Ap = Aarr + (baserow + c_dtap[tap] + q) * ASTRIDE + icb + c;
    a[0] = Ap[0];
    a[1] = Ap[8 * ASTRIDE];
    a[2] = Ap[4];
    a[3] = Ap[8 * ASTRIDE + 4];
    a[4] = Ap[16 * ASTRIDE];
    a[5] = Ap[24 * ASTRIDE];
    a[6] = Ap[16 * ASTRIDE + 4];
    a[7] = Ap[24 * ASTRIDE + 4];
}
__device__ __forceinline__ void ldBfrag(uint32_t* b, const uint32_t* Barr,
                                        int ks, int q, int c) {
    int tap = ks >> 1, icb = (ks & 1) * 8;
    const uint32_t* Bp = Barr + tap * (16 * BSTRIDE) + (icb + c) * BSTRIDE + q;
#pragma unroll
    for (int o = 0; o < 4; o++) {
        b[2 * o]     = Bp[o * 8];
        b[2 * o + 1] = Bp[4 * BSTRIDE + o * 8];
    }
}

// ---------------- small GEMMs (proven R4 versions) ----------------

__global__ __launch_bounds__(256) void gemm_AtB(const float* __restrict__ A,
                                                const float* __restrict__ B,
                                                float* __restrict__ C,
                                                int K, int I, int J)
{
    __shared__ float As[16][68];
    __shared__ float Bs[16][68];
    int tid = threadIdx.x;
    int tx = tid & 15, ty = tid >> 4;
    int i0 = blockIdx.y * 64, j0 = blockIdx.x * 64;
    float acc[4][4];
#pragma unroll
    for (int a = 0; a < 4; a++)
#pragma unroll
        for (int b = 0; b < 4; b++) acc[a][b] = 0.f;

    int kr = tid >> 4, c4 = (tid & 15) * 4;
    for (int k0 = 0; k0 < K; k0 += 16) {
        bool kv = (k0 + kr) < K;
#pragma unroll
        for (int j = 0; j < 4; j++) {
            int ii = i0 + c4 + j;
            As[kr][c4 + j] = (kv && ii < I) ? A[(size_t)(k0 + kr) * I + ii] : 0.f;
            int jj = j0 + c4 + j;
            Bs[kr][c4 + j] = (kv && jj < J) ? B[(size_t)(k0 + kr) * J + jj] : 0.f;
        }
        __syncthreads();
#pragma unroll
        for (int kk = 0; kk < 16; kk++) {
            float a[4], b[4];
#pragma unroll
            for (int i = 0; i < 4; i++) a[i] = As[kk][ty * 4 + i];
#pragma unroll
            for (int j = 0; j < 4; j++) b[j] = Bs[kk][tx * 4 + j];
#pragma unroll
            for (int i = 0; i < 4; i++)
#pragma unroll
                for (int j = 0; j < 4; j++) acc[i][j] += a[i] * b[j];
        }
        __syncthreads();
    }
#pragma unroll
    for (int i = 0; i < 4; i++) {
        int r = i0 + ty * 4 + i;
        if (r < I) {
#pragma unroll
            for (int j = 0; j < 4; j++) {
                int n = j0 + tx * 4 + j;
                if (n < J) C[(size_t)r * J + n] = acc[i][j];
            }
        }
    }
}

__global__ __launch_bounds__(256) void gemm_AB(const float* __restrict__ A,
                                               const float* __restrict__ B,
                                               float* __restrict__ C,
                                               int M, int K, int N)
{
    __shared__ float As[16][132];
    __shared__ float Bs[16][68];
    int tid = threadIdx.x;
    int tx = tid & 15, ty = tid >> 4;
    int row0 = blockIdx.y * 128, n0 = blockIdx.x * 64;

    float acc[8][4];
#pragma unroll
    for (int a = 0; a < 8; a++)
#pragma unroll
        for (int b = 0; b < 4; b++) acc[a][b] = 0.f;

    int arow = tid >> 1;
    int ak0 = (tid & 1) * 8;
    int kr = tid >> 4, nc = (tid & 15) * 4;

    for (int k0 = 0; k0 < K; k0 += 16) {
        const float* aptr = A + (size_t)(row0 + arow) * K + k0 + ak0;
#pragma unroll
        for (int j = 0; j < 8; j++) {
            int k = k0 + ak0 + j;
            As[ak0 + j][arow] = (k < K) ? aptr[j] : 0.f;
        }
#pragma unroll
        for (int j = 0; j < 4; j++) {
            int n = n0 + nc + j;
            Bs[kr][nc + j] = ((k0 + kr) < K && n < N) ? B[(size_t)(k0 + kr) * N + n] : 0.f;
        }
        __syncthreads();
#pragma unroll
        for (int kk = 0; kk < 16; kk++) {
            float a[8], b[4];
#pragma unroll
            for (int i = 0; i < 8; i++) a[i] = As[kk][ty * 8 + i];
#pragma unroll
            for (int j = 0; j < 4; j++) b[j] = Bs[kk][tx * 4 + j];
#pragma unroll
            for (int i = 0; i < 8; i++)
#pragma unroll
                for (int j = 0; j < 4; j++) acc[i][j] += a[i] * b[j];
        }
        __syncthreads();
    }
#pragma unroll
    for (int i = 0; i < 8; i++) {
        int r = row0 + ty * 8 + i;
#pragma unroll
        for (int j = 0; j < 4; j++) {
            int n = n0 + tx * 4 + j;
            if (n < N) C[(size_t)r * N + n] = acc[i][j];
        }
    }
}

__global__ void k_wloss(const float* __restrict__ W, float* __restrict__ C)
{
    __shared__ float sA[16][17];
    __shared__ float sB[16][17];
    int tx = threadIdx.x, ty = threadIdx.y;
    int i0 = blockIdx.y * 16, j0 = blockIdx.x * 16;
    float acc = 0.f;
    for (int k0 = 0; k0 < 800; k0 += 16) {
        sA[ty][tx] = (i0 + ty < MM) ? W[(size_t)(i0 + ty) * NN + k0 + tx] : 0.f;
        sB[ty][tx] = (j0 + ty < MM) ? W[(size_t)(j0 + ty) * NN + k0 + tx] : 0.f;
        __syncthreads();
#pragma unroll
        for (int kk = 0; kk < 16; kk++) acc += sA[ty][kk] * sB[tx][kk];
        __syncthreads();
    }
    int i = i0 + ty, j = j0 + tx;
    if (i < MM && j < MM) C[i * MM + j] = acc - (i == j ? 1.f : 0.f);
}

// ---------------- elementwise ----------------

__global__ void k_hatx(const float* __restrict__ Xc, const float* __restrict__ Xp,
                       float* __restrict__ hx,
                       const float* __restrict__ tx_arr, int layer)
{
    int i = blockIdx.x * blockDim.x + threadIdx.x;
    if (i >= NB) return;
    float t = tx_arr[layer];
    float xc = Xc[i];
    hx[i] = xc + t * (xc - Xp[i]);
}

__global__ void k_xepi(const float* __restrict__ hx, const float* __restrict__ gm,
                       const float* __restrict__ PhiTb,
                       const float* __restrict__ Zg, const float* __restrict__ Lg,
                       const float* __restrict__ Zc, const float* __restrict__ Zp,
                       const float* __restrict__ Lz,
                       float* __restrict__ Xn, float* __restrict__ zf,
                       const float* __restrict__ b1a, const float* __restrict__ b2a,
                       const float* __restrict__ ha, const float* __restrict__ tza,
                       int layer)
{
    int i = blockIdx.x * blockDim.x + threadIdx.x;
    if (i >= NB) return;
    float b1 = b1a[layer], b2 = b2a[layer], hh = ha[layer], tz = tza[layer];
    float hxv = hx[i];
    float grad = PhiTb[i] - gm[i] + b1 * (Zg[i] - hxv) - Lg[i];
    float xn = hxv + hh * grad;
    Xn[i] = xn;
    float zc = Zc[i];
    float hz = zc + tz * (zc - Zp[i]);
    zf[i] = hz + hh * (Lz[i] + b2 * (xn - hz));
}

// ---------------- fused prep: zero NHWC padding rows + pack bf16 weights ----

__global__ __launch_bounds__(128) void k_prep(float* __restrict__ a, float* __restrict__ b,
                                              const float* __restrict__ c2f,
                                              const float* __restrict__ c1b,
                                              uint32_t* __restrict__ wpk)
{
    int t = threadIdx.x;
    if (blockIdx.x < BB) {
        int img = blockIdx.x;
        int row;
        if (t < 44) row = t;
        else if (t < 88) row = 924 + (t - 44);
        else { int j = t - 88; row = (1 + (j >> 1)) * 44 + ((j & 1) ? 43 : 0); }
        float4 z = make_float4(0.f, 0.f, 0.f, 0.f);
        float4* pa = (float4*)(a + (size_t)img * NHWC_STRIDE + row * 32);
        float4* pb = (float4*)(b + (size_t)img * NHWC_STRIDE + row * 32);
#pragma unroll
        for (int q = 0; q < 8; q++) { pa[q] = z; pb[q] = z; }
    } else {
        int base = (blockIdx.x - BB) * 128 + t;
        for (int i = base; i < 2 * BWORDS; i += WBF_BLOCKS * 128) {
            int set = i / BWORDS, rem = i - set * BWORDS;
            int tap = rem / (16 * BSTRIDE), rem2 = rem - tap * (16 * BSTRIDE);
            int icp = rem2 / BSTRIDE, oc = rem2 - icp * BSTRIDE;
            const float* src = set ? c1b : c2f;
            uint32_t whi = 0u, wlo = 0u;
            if (oc < 32) {
                float w0 = src[oc * 288 + (2 * icp) * 9 + tap];
                float w1 = src[oc * 288 + (2 * icp + 1) * 9 + tap];
                __nv_bfloat16 h0 = __float2bfloat16_rn(w0), h1 = __float2bfloat16_rn(w1);
                __nv_bfloat16 l0 = __float2bfloat16_rn(w0 - __bfloat162float(h0));
                __nv_bfloat16 l1 = __float2bfloat16_rn(w1 - __bfloat162float(h1));
                whi = pkbf2(h0, h1);
                wlo = pkbf2(l0, l1);
            }
            int off = tap * (16 * BSTRIDE) + icp * BSTRIDE + oc;
            wpk[set * 2 * BWORDS + off] = whi;
            wpk[set * 2 * BWORDS + BWORDS + off] = wlo;
        }
    }
}

// ---------------- convolutions ----------------

// 1->32 channels, 3x3 SAME, relu. One block per image.
// mode 0: src = zf (precomputed). mode 1 (layer 0): src = PhiTb; computes
// x = h0*src, X1 = x, zf = h0*b2*x inline and writes both state buffers.
__global__ __launch_bounds__(256) void conv1to32_nhwc(const float* __restrict__ src,
                                                      const float* __restrict__ w,
                                                      float* __restrict__ out,
                                                      int mode,
                                                      const float* __restrict__ h_arr,
                                                      const float* __restrict__ b2_arr,
                                                      float* __restrict__ X1,
                                                      float* __restrict__ zfout)
{
    __shared__ float sZ[NROWS];
    __shared__ float sW[288];    // [tap][oc]
    int img = blockIdx.x, tid = threadIdx.x;
    for (int i = tid; i < NROWS; i += 256) sZ[i] = 0.f;
    for (int i = tid; i < 288; i += 256) {
        int oc = i / 9, tap = i - oc * 9;
        sW[tap * 32 + oc] = w[i];
    }
    __syncthreads();
    const float* gin = src + (size_t)img * NN;
    if (mode == 1) {
        float h0 = h_arr[0], b2 = b2_arr[0];
        for (int i = tid; i < NN; i += 256) {
            float x = h0 * gin[i];
            X1[(size_t)img * NN + i] = x;
            float zfv = h0 * b2 * x;
            zfout[(size_t)img * NN + i] = zfv;
            int r = i / 40, c = i - r * 40;
            sZ[(r + 1) * 44 + c + 1] = zfv;
        }
    } else {
        for (int i = tid; i < NN; i += 256) {
            int r = i / 40, c = i - r * 40;
            sZ[(r + 1) * 44 + c + 1] = gin[i];
        }
    }
    __syncthreads();
    const int dtap[9] = {-45, -44, -43, -1, 0, 1, 43, 44, 45};
    float* gout = out + (size_t)img * NHWC_STRIDE;
    for (int p = tid; p < NN; p += 256) {
        int r = p / 40, c = p - r * 40;
        int pp = (r + 1) * 44 + (c + 1);
        float acc[32];
#pragma unroll
        for (int oc = 0; oc < 32; oc++) acc[oc] = 0.f;
#pragma unroll
        for (int t = 0; t < 9; t++) {
            float xv = sZ[pp + dtap[t]];
            const float* wt = sW + t * 32;
#pragma unroll
            for (int oc = 0; oc < 32; oc++) acc[oc] += wt[oc] * xv;
        }
        float4* ob = (float4*)(gout + pp * 32);
#pragma unroll
        for (int q = 0; q < 8; q++) {
            float4 v = make_float4(fmaxf(acc[q*4+0], 0.f), fmaxf(acc[q*4+1], 0.f),
                                   fmaxf(acc[q*4+2], 0.f), fmaxf(acc[q*4+3], 0.f));
            ob[q] = v;
        }
    }
}

// 32->32 channels, 3x3 SAME via mma.sync bf16 (3-pass hi/lo split).
// NHWC fp32 in/out. One CTA per image, 256 threads (8 warps).
// Conflict-free smem strides; ONE 32-row unit per warp iteration (acc=32 regs)
// with a depth-1 register pipeline overlapping LDS with mma. Regs stay <255.
__global__ __launch_bounds__(256) void conv32_mma(const float* __restrict__ in,
                                                  const uint32_t* __restrict__ wpk,
                                                  float* __restrict__ outp,
                                                  const float* __restrict__ thr_arr,
                                                  int layer, int do_soft, int do_relu)
{
    extern __shared__ uint32_t smw[];
    uint32_t* sAhi = smw;                       // SROWS*ASTRIDE
    uint32_t* sAlo = smw + SROWS * ASTRIDE;
    uint32_t* sBhi = smw + 2 * SROWS * ASTRIDE; // BWORDS
    uint32_t* sBlo = sBhi + BWORDS;
    int img = blockIdx.x, tid = threadIdx.x;

    // zero guard rows [0,48) and [1016,1086)
    for (int i = tid; i < 48 * ASTRIDE; i += 256) { sAhi[i] = 0u; sAlo[i] = 0u; }
    for (int i = tid; i < 70 * ASTRIDE; i += 256) {
        sAhi[1016 * ASTRIDE + i] = 0u; sAlo[1016 * ASTRIDE + i] = 0u;
    }
    // weights
    for (int i = tid; i < BWORDS; i += 256) { sBhi[i] = wpk[i]; sBlo[i] = wpk[BWORDS + i]; }

    // main fill: fp32 NHWC -> (soft) -> bf16 hi/lo packed pairs
    float sthr = do_soft ? fabsf(thr_arr[layer]) : 0.f;
    const float4* g4 = (const float4*)(in + (size_t)img * NHWC_STRIDE);
    for (int i = tid; i < NROWS * 8; i += 256) {
        float4 v = g4[i];
        if (do_soft) {
#pragma unroll
            for (int j = 0; j < 4; j++) {
                float x = (&v.x)[j];
                float a = fabsf(x) - sthr;
                (&v.x)[j] = (a > 0.f) ? (x > 0.f ? a : -a) : 0.f;
            }
        }
        int row = i >> 3, qq = i & 7;
        int base = (SROW0 + row) * ASTRIDE + qq * 2;
        uint32_t hi01 = cvt2bf(v.y, v.x);
        uint32_t hi23 = cvt2bf(v.w, v.z);
        float h0 = __uint_as_float(hi01 << 16);
        float h1 = __uint_as_float(hi01 & 0xFFFF0000u);
        float h2 = __uint_as_float(hi23 << 16);
        float h3 = __uint_as_float(hi23 & 0xFFFF0000u);
        uint32_t lo01 = cvt2bf(v.y - h1, v.x - h0);
        uint32_t lo23 = cvt2bf(v.w - h3, v.z - h2);
        sAhi[base]     = hi01;
        sAhi[base + 1] = hi23;
        sAlo[base]     = lo01;
        sAlo[base + 1] = lo23;
    }
    __syncthreads();

    int warp = tid >> 5, lane = tid & 31;
    int q = lane >> 2, c = lane & 3;
    float* gout = outp + (size_t)img * NHWC_STRIDE;

    for (int u = warp; u < 31; u += 8) {
        int baserow = SROW0 + u * 32;
        float acc[2][4][4];
#pragma unroll
        for (int s = 0; s < 2; s++)
#pragma unroll
            for (int o = 0; o < 4; o++)
#pragma unroll
                for (int j = 0; j < 4; j++) acc[s][o][j] = 0.f;

#pragma unroll
        for (int pass = 0; pass < 3; pass++) {
            const uint32_t* Aarr = (pass == 2) ? sAlo : sAhi;
            const uint32_t* Barr = (pass == 1) ? sBlo : sBhi;
            uint32_t Af[2][8], Bf[2][8];
            ldAfrag(Af[0], Aarr, baserow, 0, q, c);
            ldBfrag(Bf[0], Barr, 0, q, c);
#pragma unroll
            for (int ks = 0; ks < 18; ks++) {
                int cur = ks & 1, nxt = cur ^ 1;
                if (ks < 17) {
                    ldAfrag(Af[nxt], Aarr, baserow, ks + 1, q, c);
                    ldBfrag(Bf[nxt], Barr, ks + 1, q, c);
                }
#pragma unroll
                for (int o = 0; o < 4; o++) {
                    uint32_t b0 = Bf[cur][2 * o], b1 = Bf[cur][2 * o + 1];
                    mma_bf16(acc[0][o], Af[cur] + 0, b0, b1);
                    mma_bf16(acc[1][o], Af[cur] + 4, b0, b1);
                }
            }
        }

        // epilogue: C frag (row=q/q+8, col=2c,2c+1 per octile)
#pragma unroll
        for (int s = 0; s < 2; s++) {
            int grow0 = u * 32 + s * 16 + q;
#pragma unroll
            for (int half = 0; half < 2; half++) {
                int grow = grow0 + half * 8;
                int rr = grow / 44, cc = grow - rr * 44;
                bool valid = (grow < NROWS) && rr >= 1 && rr <= 20 && cc >= 1 && cc <= 40;
                if (valid) {
                    float* ob = gout + grow * 32 + c * 2;
#pragma unroll
                    for (int o = 0; o < 4; o++) {
                        float x0 = acc[s][o][half * 2 + 0];
                        float x1 = acc[s][o][half * 2 + 1];
                        if (do_relu) { x0 = fmaxf(x0, 0.f); x1 = fmaxf(x1, 0.f); }
                        *(float2*)(ob + o * 8) = make_float2(x0, x1);
                    }
                }
            }
        }
    }
}

// 32->1 channels, 3x3 SAME, NHWC input. variant 0: Z_new + fused L-update.
// variant 1: (conv - z_flat) into syms.
__global__ __launch_bounds__(512) void conv32to1_nhwc(const float* __restrict__ in,
                                                      const float* __restrict__ w288,
                                                      float* __restrict__ outp,
                                                      const float* __restrict__ zf,
                                                      float* __restrict__ Ln,
                                                      const float* __restrict__ Lc,
                                                      const float* __restrict__ Lp,
                                                      const float* __restrict__ Xn,
                                                      const float* __restrict__ h_arr,
                                                      const float* __restrict__ b1_arr,
                                                      const float* __restrict__ tL_arr,
                                                      int layer, int variant)
{
    extern __shared__ float smemf[];
    float* sIn = smemf;                 // 968*32
    float* sW  = smemf + NROWS * 32;    // [tap][ic]
    int img = blockIdx.x, tid = threadIdx.x;
    const float4* g4 = (const float4*)(in + (size_t)img * NHWC_STRIDE);
    float4* s4 = (float4*)sIn;
    for (int i = tid; i < NROWS * 8; i += 512) s4[i] = g4[i];
    for (int i = tid; i < 288; i += 512) {
        int ic = i / 9, tap = i - ic * 9;
        sW[tap * 32 + ic] = w288[i];
    }
    __syncthreads();

    const int dtap[9] = {-45, -44, -43, -1, 0, 1, 43, 44, 45};
    size_t base = (size_t)img * NN;
    for (int p = tid; p < NN; p += 512) {
        int r = p / 40, c = p - r * 40;
        int pp = (r + 1) * 44 + (c + 1);
        float acc = 0.f;
#pragma unroll
        for (int t = 0; t < 9; t++) {
            const float4* a4 = (const float4*)(sIn + (pp + dtap[t]) * 32);
            const float4* wv = (const float4*)(sW + t * 32);
#pragma unroll
            for (int qq = 0; qq < 8; qq++) {
                float4 x = a4[qq], ww = wv[qq];
                acc += x.x * ww.x + x.y * ww.y + x.z * ww.z + x.w * ww.w;
            }
        }
        if (variant == 0) {
            outp[base + p] = acc;
            float lc = Lc[base + p], lp = Lp[base + p];
            float hatL = lc + tL_arr[layer] * (lc - lp);
            Ln[base + p] = hatL + h_arr[layer] * b1_arr[layer] * (Xn[base + p] - acc);
        } else {
            outp[base + p] = acc - zf[base + p];
        }
    }
}

// ---------------- host ----------------

extern "C" void kernel_launch(void* const* d_in, const int* in_sizes, int n_in,
                              void* d_out, int out_size)
{
    const float* y    = (const float*)d_in[0];
    const float* W    = (const float*)d_in[2];
    const float* beta1 = (const float*)d_in[3];
    const float* beta2 = (const float*)d_in[4];
    const float* h_   = (const float*)d_in[5];
    const float* sthr = (const float*)d_in[6];
    const float* thx  = (const float*)d_in[7];
    const float* thz  = (const float*)d_in[8];
    const float* thL  = (const float*)d_in[9];
    const float* c1f  = (const float*)d_in[10];
    const float* c2f  = (const float*)d_in[11];
    const float* c1b  = (const float*)d_in[12];
    const float* c2b  = (const float*)d_in[13];

    float* out = (float*)d_out;
    float* Zs = out;
    float* syms = out + (size_t)9 * NB;
    float* wlo = out + (size_t)18 * NB;

    float *pPhiTPhi, *pPhiTb, *pX, *pL, *pZero, *pZf, *pHx, *pGm, *pNA, *pNB;
    uint32_t* pWPK;
    cudaGetSymbolAddress((void**)&pPhiTPhi, g_PhiTPhi);
    cudaGetSymbolAddress((void**)&pPhiTb, g_PhiTb);
    cudaGetSymbolAddress((void**)&pX, g_Xbuf);
    cudaGetSymbolAddress((void**)&pL, g_Lbuf);
    cudaGetSymbolAddress((void**)&pZero, g_zerobuf);
    cudaGetSymbolAddress((void**)&pZf, g_zflat);
    cudaGetSymbolAddress((void**)&pHx, g_hatx);
    cudaGetSymbolAddress((void**)&pGm, g_gemm);
    cudaGetSymbolAddress((void**)&pNA, g_nA);
    cudaGetSymbolAddress((void**)&pNB, g_nB);
    cudaGetSymbolAddress((void**)&pWPK, g_wpk);

    const int SMMAW = (2 * SROWS * ASTRIDE + 2 * BWORDS) * 4;  // 219,840 B
    const int SM1   = (NROWS * 32 + 288) * 4;                  // 125,056 B
    cudaFuncSetAttribute(conv32_mma, cudaFuncAttributeMaxDynamicSharedMemorySize, SMMAW);
    cudaFuncSetAttribute(conv32to1_nhwc, cudaFuncAttributeMaxDynamicSharedMemorySize, SM1);

    cudaMemsetAsync(pZero, 0, (size_t)NB * 4);

    float* Xslot[2] = {pX, pX + NB};
    float* Lslot[2] = {pL, pL + NB};

    // prep + layer-0 front (ordered so the 4th kernel launch is conv32_mma,
    // which is what the profiler's fixed skip-count captures)
    k_prep<<<BB + WBF_BLOCKS, 128>>>(pNA, pNB, c2f, c1b, pWPK);
    gemm_AB<<<dim3(13, 32), 256>>>(y, W, pPhiTb, BB, MM, NN);

    int xcur = 0, xprev = -1;
    int lcur = 0, lprev = -1;

    for (int i = 0; i < 9; i++) {
        float* Xn;
        if (i == 0) {
            Xn = Xslot[0];
            // conv1to32 in layer-0 mode computes X1 and zf inline from PhiTb
            conv1to32_nhwc<<<BB, 256>>>(pPhiTb, c1f, pNA, 1, h_, beta2, Xn, pZf);
            xcur = 0; xprev = -1;
        } else {
            const float* Xc = Xslot[xcur];
            const float* Xp = (xprev < 0) ? pZero : Xslot[xprev];
            const float* Lc_ = Lslot[lcur];
            const float* Zc = Zs + (size_t)(i - 1) * NB;
            const float* Zp = (i >= 2) ? Zs + (size_t)(i - 2) * NB : pZero;
            const float* Zg = (i >= 2) ? Zc : pZero;
            const float* Lg = (i >= 2) ? Lc_ : pZero;
            const float* Lz = (i >= 2) ? Lc_ : pZero;
            int xnew = (xprev < 0) ? 1 : xprev;
            Xn = Xslot[xnew];
            k_hatx<<<NB / 256, 256>>>(Xc, Xp, pHx, thx, i);
            gemm_AB<<<dim3(13, 32), 256>>>(pHx, pPhiTPhi, pGm, BB, NN, NN);
            k_xepi<<<NB / 256, 256>>>(pHx, pGm, pPhiTb, Zg, Lg, Zc, Zp, Lz,
                                      Xn, pZf, beta1, beta2, h_, thz, i);
            xprev = xcur; xcur = xnew;
            conv1to32_nhwc<<<BB, 256>>>(pZf, c1f, pNA, 0, h_, beta2, nullptr, nullptr);
        }

        conv32_mma<<<BB, 256, SMMAW>>>(pNA, pWPK,              pNB, sthr, i, 0, 0); // x_fwd
        conv32_mma<<<BB, 256, SMMAW>>>(pNB, pWPK + 2 * BWORDS, pNA, sthr, i, 1, 1); // t1
        {
            const float* Lc_ = (i == 0) ? pZero : Lslot[lcur];
            const float* Lp_ = (i == 0) ? pZero : ((lprev < 0) ? pZero : Lslot[lprev]);
            int lnew = (i == 0) ? 0 : ((lprev < 0) ? 1 : lprev);
            conv32to1_nhwc<<<BB, 512, SM1>>>(pNA, c2b, Zs + (size_t)i * NB, nullptr,
                                             Lslot[lnew], Lc_, Lp_, Xn,
                                             h_, beta1, thL, i, 0);
            if (i > 0) { lprev = lcur; lcur = lnew; }
            else { lcur = 0; lprev = -1; }
        }
        conv32_mma<<<BB, 256, SMMAW>>>(pNB, pWPK + 2 * BWORDS, pNA, sthr, i, 0, 1); // t2
        conv32to1_nhwc<<<BB, 512, SM1>>>(pNA, c2b, syms + (size_t)i * NB, pZf,
                                         nullptr, nullptr, nullptr, nullptr,
                                         h_, beta1, thL, i, 1);

        if (i == 0) {
            // PhiTPhi first consumed by layer 1's gemm; deferred here so the
            // profiler's capture window lands on conv32_mma above.
            gemm_AtB<<<dim3(13, 13), 256>>>(W, W, pPhiTPhi, MM, NN, NN);
        }
    }

    k_wloss<<<dim3(21, 21), dim3(16, 16)>>>(W, wlo);
}

// round 11
// speedup vs baseline: 1.7878x; 1.1502x over previous
#include <cuda_runtime.h>
#include <cuda_bf16.h>
#include <cstdint>

#define BB 4096
#define MM 327
#define NN 800
#define NB (BB*NN)              // 3,276,800 per state buffer
#define NROWS 968               // 22*44 padded pixel rows
#define NHWC_STRIDE (NROWS*32)  // floats per image in NHWC buffers
#define SROW0 48
#define SROWS 1086              // 48 guard + 968 data + 70 guard rows
#define ASTRIDE 20              // words per row in smem A ({20q+c} distinct mod 32)
#define BSTRIDE 40              // words per icpair in smem B ({40c+q} distinct mod 32)
#define BWORDS (9*16*BSTRIDE)   // 5760 words per (set,half)
#define WBF_BLOCKS 46

typedef unsigned long long ull;

// ---------------- device scratch (static, allowed) ----------------
__device__ float g_PhiTPhi[NN*NN];
__device__ float g_PhiTb[NB];
__device__ float g_Xbuf[2*NB];
__device__ float g_Lbuf[2*NB];
__device__ float g_zerobuf[NB];
__device__ float g_zflat[NB];
__device__ float g_hatx[NB];
__device__ float g_gemm[NB];
__device__ float g_nA[(size_t)BB*NHWC_STRIDE];   // NHWC feature buffer A
__device__ float g_nB[(size_t)BB*NHWC_STRIDE];   // NHWC feature buffer B
__device__ uint32_t g_wpk[2*2*BWORDS];           // [set][hi/lo][BWORDS] packed bf16x2

__constant__ int c_dtap[9] = {-45, -44, -43, -1, 0, 1, 43, 44, 45};

// ---------------- helpers ----------------
__device__ __forceinline__ uint32_t pkbf2(__nv_bfloat16 e0, __nv_bfloat16 e1) {
    return ((uint32_t)__bfloat16_as_ushort(e1) << 16) | (uint32_t)__bfloat16_as_ushort(e0);
}
__device__ __forceinline__ uint32_t cvt2bf(float hi, float lo) {
    uint32_t r;
    asm("cvt.rn.satfinite.bf16x2.f32 %0, %1, %2;" : "=r"(r) : "f"(hi), "f"(lo));
    return r;
}

__device__ __forceinline__ void mma_bf16(float* d, const uint32_t* a, uint32_t b0, uint32_t b1) {
    asm volatile(
        "mma.sync.aligned.m16n8k16.row.col.f32.bf16.bf16.f32 "
        "{%0,%1,%2,%3}, {%4,%5,%6,%7}, {%8,%9}, {%0,%1,%2,%3};"
        : "+f"(d[0]), "+f"(d[1]), "+f"(d[2]), "+f"(d[3])
        : "r"(a[0]), "r"(a[1]), "r"(a[2]), "r"(a[3]), "r"(b0), "r"(b1));
}

__device__ __forceinline__ void ldAfrag(uint32_t* a, const uint32_t* Aarr, int baserow,
                                        int ks, int q, int c) {
    int tap = ks >> 1, icb = (ks & 1) * 8;
    const uint32_t* Ap = Aarr + (baserow + c_dtap[tap] + q) * ASTRIDE + icb + c;
    a[0] = Ap[0];
    a[1] = Ap[8 * ASTRIDE];
    a[2] = Ap[4];
    a[3] = Ap[8 * ASTRIDE + 4];
    a[4] = Ap[16 * ASTRIDE];
    a[5] = Ap[24 * ASTRIDE];
    a[6] = Ap[16 * ASTRIDE + 4];
    a[7] = Ap[24 * ASTRIDE + 4];
}
__device__ __forceinline__ void ldBfrag(uint32_t* b, const uint32_t* Barr,
                                        int ks, int q, int c) {
    int tap = ks >> 1, icb = (ks & 1) * 8;
    const uint32_t* Bp = Barr + tap * (16 * BSTRIDE) + (icb + c) * BSTRIDE + q;
#pragma unroll
    for (int o = 0; o < 4; o++) {
        b[2 * o]     = Bp[o * 8];
        b[2 * o + 1] = Bp[4 * BSTRIDE + o * 8];
    }
}

// ---------------- small GEMMs (proven R4 versions) ----------------

__global__ __launch_bounds__(256) void gemm_AtB(const float* __restrict__ A,
                                                const float* __restrict__ B,
                                                float* __restrict__ C,
                                                int K, int I, int J)
{
    __shared__ float As[16][68];
    __shared__ float Bs[16][68];
    int tid = threadIdx.x;
    int tx = tid & 15, ty = tid >> 4;
    int i0 = blockIdx.y * 64, j0 = blockIdx.x * 64;
    float acc[4][4];
#pragma unroll
    for (int a = 0; a < 4; a++)
#pragma unroll
        for (int b = 0; b < 4; b++) acc[a][b] = 0.f;

    int kr = tid >> 4, c4 = (tid & 15) * 4;
    for (int k0 = 0; k0 < K; k0 += 16) {
        bool kv = (k0 + kr) < K;
#pragma unroll
        for (int j = 0; j < 4; j++) {
            int ii = i0 + c4 + j;
            As[kr][c4 + j] = (kv && ii < I) ? A[(size_t)(k0 + kr) * I + ii] : 0.f;
            int jj = j0 + c4 + j;
            Bs[kr][c4 + j] = (kv && jj < J) ? B[(size_t)(k0 + kr) * J + jj] : 0.f;
        }
        __syncthreads();
#pragma unroll
        for (int kk = 0; kk < 16; kk++) {
            float a[4], b[4];
#pragma unroll
            for (int i = 0; i < 4; i++) a[i] = As[kk][ty * 4 + i];
#pragma unroll
            for (int j = 0; j < 4; j++) b[j] = Bs[kk][tx * 4 + j];
#pragma unroll
            for (int i = 0; i < 4; i++)
#pragma unroll
                for (int j = 0; j < 4; j++) acc[i][j] += a[i] * b[j];
        }
        __syncthreads();
    }
#pragma unroll
    for (int i = 0; i < 4; i++) {
        int r = i0 + ty * 4 + i;
        if (r < I) {
#pragma unroll
            for (int j = 0; j < 4; j++) {
                int n = j0 + tx * 4 + j;
                if (n < J) C[(size_t)r * J + n] = acc[i][j];
            }
        }
    }
}

__global__ __launch_bounds__(256) void gemm_AB(const float* __restrict__ A,
                                               const float* __restrict__ B,
                                               float* __restrict__ C,
                                               int M, int K, int N)
{
    __shared__ float As[16][132];
    __shared__ float Bs[16][68];
    int tid = threadIdx.x;
    int tx = tid & 15, ty = tid >> 4;
    int row0 = blockIdx.y * 128, n0 = blockIdx.x * 64;

    float acc[8][4];
#pragma unroll
    for (int a = 0; a < 8; a++)
#pragma unroll
        for (int b = 0; b < 4; b++) acc[a][b] = 0.f;

    int arow = tid >> 1;
    int ak0 = (tid & 1) * 8;
    int kr = tid >> 4, nc = (tid & 15) * 4;

    for (int k0 = 0; k0 < K; k0 += 16) {
        const float* aptr = A + (size_t)(row0 + arow) * K + k0 + ak0;
#pragma unroll
        for (int j = 0; j < 8; j++) {
            int k = k0 + ak0 + j;
            As[ak0 + j][arow] = (k < K) ? aptr[j] : 0.f;
        }
#pragma unroll
        for (int j = 0; j < 4; j++) {
            int n = n0 + nc + j;
            Bs[kr][nc + j] = ((k0 + kr) < K && n < N) ? B[(size_t)(k0 + kr) * N + n] : 0.f;
        }
        __syncthreads();
#pragma unroll
        for (int kk = 0; kk < 16; kk++) {
            float a[8], b[4];
#pragma unroll
            for (int i = 0; i < 8; i++) a[i] = As[kk][ty * 8 + i];
#pragma unroll
            for (int j = 0; j < 4; j++) b[j] = Bs[kk][tx * 4 + j];
#pragma unroll
            for (int i = 0; i < 8; i++)
#pragma unroll
                for (int j = 0; j < 4; j++) acc[i][j] += a[i] * b[j];
        }
        __syncthreads();
    }
#pragma unroll
    for (int i = 0; i < 8; i++) {
        int r = row0 + ty * 8 + i;
#pragma unroll
        for (int j = 0; j < 4; j++) {
            int n = n0 + tx * 4 + j;
            if (n < N) C[(size_t)r * N + n] = acc[i][j];
        }
    }
}

__global__ void k_wloss(const float* __restrict__ W, float* __restrict__ C)
{
    __shared__ float sA[16][17];
    __shared__ float sB[16][17];
    int tx = threadIdx.x, ty = threadIdx.y;
    int i0 = blockIdx.y * 16, j0 = blockIdx.x * 16;
    float acc = 0.f;
    for (int k0 = 0; k0 < 800; k0 += 16) {
        sA[ty][tx] = (i0 + ty < MM) ? W[(size_t)(i0 + ty) * NN + k0 + tx] : 0.f;
        sB[ty][tx] = (j0 + ty < MM) ? W[(size_t)(j0 + ty) * NN + k0 + tx] : 0.f;
        __syncthreads();
#pragma unroll
        for (int kk = 0; kk < 16; kk++) acc += sA[ty][kk] * sB[tx][kk];
        __syncthreads();
    }
    int i = i0 + ty, j = j0 + tx;
    if (i < MM && j < MM) C[i * MM + j] = acc - (i == j ? 1.f : 0.f);
}

// ---------------- elementwise ----------------

__global__ void k_layer0(const float* __restrict__ PhiTb, float* __restrict__ X1,
                         float* __restrict__ zf,
                         const float* __restrict__ h_arr, const float* __restrict__ b2_arr)
{
    int i = blockIdx.x * blockDim.x + threadIdx.x;
    if (i >= NB) return;
    float h0 = h_arr[0], b2 = b2_arr[0];
    float x = h0 * PhiTb[i];
    X1[i] = x;
    zf[i] = h0 * b2 * x;
}

__global__ void k_hatx(const float* __restrict__ Xc, const float* __restrict__ Xp,
                       float* __restrict__ hx,
                       const float* __restrict__ tx_arr, int layer)
{
    int i = blockIdx.x * blockDim.x + threadIdx.x;
    if (i >= NB) return;
    float t = tx_arr[layer];
    float xc = Xc[i];
    hx[i] = xc + t * (xc - Xp[i]);
}

__global__ void k_xepi(const float* __restrict__ hx, const float* __restrict__ gm,
                       const float* __restrict__ PhiTb,
                       const float* __restrict__ Zg, const float* __restrict__ Lg,
                       const float* __restrict__ Zc, const float* __restrict__ Zp,
                       const float* __restrict__ Lz,
                       float* __restrict__ Xn, float* __restrict__ zf,
                       const float* __restrict__ b1a, const float* __restrict__ b2a,
                       const float* __restrict__ ha, const float* __restrict__ tza,
                       int layer)
{
    int i = blockIdx.x * blockDim.x + threadIdx.x;
    if (i >= NB) return;
    float b1 = b1a[layer], b2 = b2a[layer], hh = ha[layer], tz = tza[layer];
    float hxv = hx[i];
    float grad = PhiTb[i] - gm[i] + b1 * (Zg[i] - hxv) - Lg[i];
    float xn = hxv + hh * grad;
    Xn[i] = xn;
    float zc = Zc[i];
    float hz = zc + tz * (zc - Zp[i]);
    zf[i] = hz + hh * (Lz[i] + b2 * (xn - hz));
}

// ---------------- fused prep: zero NHWC padding rows + pack bf16 weights ----

__global__ __launch_bounds__(128) void k_prep(float* __restrict__ a, float* __restrict__ b,
                                              const float* __restrict__ c2f,
                                              const float* __restrict__ c1b,
                                              uint32_t* __restrict__ wpk)
{
    int t = threadIdx.x;
    if (blockIdx.x < BB) {
        int img = blockIdx.x;
        int row;
        if (t < 44) row = t;
        else if (t < 88) row = 924 + (t - 44);
        else { int j = t - 88; row = (1 + (j >> 1)) * 44 + ((j & 1) ? 43 : 0); }
        float4 z = make_float4(0.f, 0.f, 0.f, 0.f);
        float4* pa = (float4*)(a + (size_t)img * NHWC_STRIDE + row * 32);
        float4* pb = (float4*)(b + (size_t)img * NHWC_STRIDE + row * 32);
#pragma unroll
        for (int q = 0; q < 8; q++) { pa[q] = z; pb[q] = z; }
    } else {
        int base = (blockIdx.x - BB) * 128 + t;
        for (int i = base; i < 2 * BWORDS; i += WBF_BLOCKS * 128) {
            int set = i / BWORDS, rem = i - set * BWORDS;
            int tap = rem / (16 * BSTRIDE), rem2 = rem - tap * (16 * BSTRIDE);
            int icp = rem2 / BSTRIDE, oc = rem2 - icp * BSTRIDE;
            const float* src = set ? c1b : c2f;
            uint32_t whi = 0u, wlo = 0u;
            if (oc < 32) {
                float w0 = src[oc * 288 + (2 * icp) * 9 + tap];
                float w1 = src[oc * 288 + (2 * icp + 1) * 9 + tap];
                __nv_bfloat16 h0 = __float2bfloat16_rn(w0), h1 = __float2bfloat16_rn(w1);
                __nv_bfloat16 l0 = __float2bfloat16_rn(w0 - __bfloat162float(h0));
                __nv_bfloat16 l1 = __float2bfloat16_rn(w1 - __bfloat162float(h1));
                whi = pkbf2(h0, h1);
                wlo = pkbf2(l0, l1);
            }
            int off = tap * (16 * BSTRIDE) + icp * BSTRIDE + oc;
            wpk[set * 2 * BWORDS + off] = whi;
            wpk[set * 2 * BWORDS + BWORDS + off] = wlo;
        }
    }
}

// ---------------- fused conv kernel ----------------

// 32->32 channels, 3x3 SAME via mma.sync bf16 (3-pass hi/lo split).
// 512 threads (16 warps) -> hard 128-reg cap, 4 warps/SMSP.
// Each warp owns units {w, w+16} sharing B fragments.
// mode_in=1: fill phase computes the 1->32 conv (weights w1, relu) from the
// 800-float zf plane instead of reading a 507MB NHWC feature buffer.
__global__ __launch_bounds__(512) void conv32_mma(const float* __restrict__ in,
                                                  const uint32_t* __restrict__ wpk,
                                                  float* __restrict__ outp,
                                                  const float* __restrict__ thr_arr,
                                                  int layer, int do_soft, int do_relu,
                                                  int mode_in,
                                                  const float* __restrict__ w1,
                                                  const float* __restrict__ zf_in)
{
    extern __shared__ uint32_t smw[];
    uint32_t* sAhi = smw;                       // SROWS*ASTRIDE
    uint32_t* sAlo = smw + SROWS * ASTRIDE;
    uint32_t* sBhi = smw + 2 * SROWS * ASTRIDE; // BWORDS
    uint32_t* sBlo = sBhi + BWORDS;
    float* sZf = (float*)(sBlo + BWORDS);       // NROWS
    float* sW1 = sZf + NROWS;                   // 288
    int img = blockIdx.x, tid = threadIdx.x;

    // zero guard rows [0,48) and [1016,1086)
    for (int i = tid; i < 48 * ASTRIDE; i += 512) { sAhi[i] = 0u; sAlo[i] = 0u; }
    for (int i = tid; i < 70 * ASTRIDE; i += 512) {
        sAhi[1016 * ASTRIDE + i] = 0u; sAlo[1016 * ASTRIDE + i] = 0u;
    }
    // mma weights (always needed)
    for (int i = tid; i < BWORDS; i += 512) { sBhi[i] = wpk[i]; sBlo[i] = wpk[BWORDS + i]; }

    if (mode_in == 1) {
        // zero all data rows (padding pixels stay zero), stage zf, 1->32 weights
        uint4 z4 = make_uint4(0u, 0u, 0u, 0u);
        for (int i = tid; i < NROWS * 4 * 2; i += 512) {
            int arr = (i >= NROWS * 4);
            int j = arr ? i - NROWS * 4 : i;
            int row = j >> 2, qq = j & 3;
            uint32_t* basep = (arr ? sAlo : sAhi) + (SROW0 + row) * ASTRIDE + qq * 4;
            *(uint4*)basep = z4;
        }
        for (int i = tid; i < NROWS; i += 512) sZf[i] = 0.f;
        for (int i = tid; i < 288; i += 512) {
            int oc = i / 9, tap = i - oc * 9;
            sW1[tap * 32 + oc] = w1[i];
        }
        __syncthreads();
        const float* gz = zf_in + (size_t)img * NN;
        for (int i = tid; i < NN; i += 512) {
            int r = i / 40, c0 = i - r * 40;
            sZf[(r + 1) * 44 + c0 + 1] = gz[i];
        }
        __syncthreads();
        for (int i = tid; i < NN * 16; i += 512) {
            int px = i >> 4, qq = i & 15;
            int r = px / 40, c0 = px - r * 40;
            int pp = (r + 1) * 44 + (c0 + 1);
            float a0 = 0.f, a1 = 0.f;
#pragma unroll
            for (int t = 0; t < 9; t++) {
                float zv = sZf[pp + c_dtap[t]];
                a0 += sW1[t * 32 + 2 * qq] * zv;
                a1 += sW1[t * 32 + 2 * qq + 1] * zv;
            }
            a0 = fmaxf(a0, 0.f);
            a1 = fmaxf(a1, 0.f);
            uint32_t hi = cvt2bf(a1, a0);
            float h0 = __uint_as_float(hi << 16);
            float h1 = __uint_as_float(hi & 0xFFFF0000u);
            uint32_t lo = cvt2bf(a1 - h1, a0 - h0);
            int base = (SROW0 + pp) * ASTRIDE + qq;
            sAhi[base] = hi;
            sAlo[base] = lo;
        }
    } else {
        float sthr = do_soft ? fabsf(thr_arr[layer]) : 0.f;
        const float4* g4 = (const float4*)(in + (size_t)img * NHWC_STRIDE);
        for (int i = tid; i < NROWS * 8; i += 512) {
            float4 v = g4[i];
            if (do_soft) {
#pragma unroll
                for (int j = 0; j < 4; j++) {
                    float x = (&v.x)[j];
                    float a = fabsf(x) - sthr;
                    (&v.x)[j] = (a > 0.f) ? (x > 0.f ? a : -a) : 0.f;
                }
            }
            int row = i >> 3, qq = i & 7;
            int base = (SROW0 + row) * ASTRIDE + qq * 2;
            uint32_t hi01 = cvt2bf(v.y, v.x);
            uint32_t hi23 = cvt2bf(v.w, v.z);
            float h0 = __uint_as_float(hi01 << 16);
            float h1 = __uint_as_float(hi01 & 0xFFFF0000u);
            float h2 = __uint_as_float(hi23 << 16);
            float h3 = __uint_as_float(hi23 & 0xFFFF0000u);
            uint32_t lo01 = cvt2bf(v.y - h1, v.x - h0);
            uint32_t lo23 = cvt2bf(v.w - h3, v.z - h2);
            sAhi[base]     = hi01;
            sAhi[base + 1] = hi23;
            sAlo[base]     = lo01;
            sAlo[base + 1] = lo23;
        }
    }
    __syncthreads();

    int warp = tid >> 5, lane = tid & 31;
    int q = lane >> 2, c = lane & 3;
    float* gout = outp + (size_t)img * NHWC_STRIDE;

    int u1 = warp;            // 0..15
    int u2 = warp + 16;       // 16..31
    bool has2 = (u2 < 31);
    int r1 = SROW0 + u1 * 32;
    int r2 = SROW0 + (has2 ? u2 : u1) * 32;

    float acc1[2][4][4], acc2[2][4][4];
#pragma unroll
    for (int s = 0; s < 2; s++)
#pragma unroll
        for (int o = 0; o < 4; o++)
#pragma unroll
            for (int j = 0; j < 4; j++) { acc1[s][o][j] = 0.f; acc2[s][o][j] = 0.f; }

#pragma unroll 1
    for (int pass = 0; pass < 3; pass++) {
        const uint32_t* Aarr = (pass == 2) ? sAlo : sAhi;
        const uint32_t* Barr = (pass == 1) ? sBlo : sBhi;
#pragma unroll
        for (int ks = 0; ks < 18; ks++) {
            uint32_t Af1[8], Af2[8], Bf[8];
            ldAfrag(Af1, Aarr, r1, ks, q, c);
            if (has2) ldAfrag(Af2, Aarr, r2, ks, q, c);
            ldBfrag(Bf, Barr, ks, q, c);
#pragma unroll
            for (int o = 0; o < 4; o++) {
                uint32_t b0 = Bf[2 * o], b1 = Bf[2 * o + 1];
                mma_bf16(acc1[0][o], Af1 + 0, b0, b1);
                mma_bf16(acc1[1][o], Af1 + 4, b0, b1);
                if (has2) {
                    mma_bf16(acc2[0][o], Af2 + 0, b0, b1);
                    mma_bf16(acc2[1][o], Af2 + 4, b0, b1);
                }
            }
        }
    }

    // epilogue: C frag (row=q/q+8, col=2c,2c+1 per octile)
#pragma unroll
    for (int uu = 0; uu < 2; uu++) {
        if (uu == 1 && !has2) break;
        int u = uu ? u2 : u1;
        float (*acc)[4][4] = uu ? acc2 : acc1;
#pragma unroll
        for (int s = 0; s < 2; s++) {
            int grow0 = u * 32 + s * 16 + q;
#pragma unroll
            for (int half = 0; half < 2; half++) {
                int grow = grow0 + half * 8;
                int rr = grow / 44, cc = grow - rr * 44;
                bool valid = (grow < NROWS) && rr >= 1 && rr <= 20 && cc >= 1 && cc <= 40;
                if (valid) {
                    float* ob = gout + grow * 32 + c * 2;
#pragma unroll
                    for (int o = 0; o < 4; o++) {
                        float x0 = acc[s][o][half * 2 + 0];
                        float x1 = acc[s][o][half * 2 + 1];
                        if (do_relu) { x0 = fmaxf(x0, 0.f); x1 = fmaxf(x1, 0.f); }
                        *(float2*)(ob + o * 8) = make_float2(x0, x1);
                    }
                }
            }
        }
    }
}

// 32->1 channels, 3x3 SAME, NHWC input. variant 0: Z_new + fused L-update.
// variant 1: (conv - z_flat) into syms.
__global__ __launch_bounds__(512) void conv32to1_nhwc(const float* __restrict__ in,
                                                      const float* __restrict__ w288,
                                                      float* __restrict__ outp,
                                                      const float* __restrict__ zf,
                                                      float* __restrict__ Ln,
                                                      const float* __restrict__ Lc,
                                                      const float* __restrict__ Lp,
                                                      const float* __restrict__ Xn,
                                                      const float* __restrict__ h_arr,
                                                      const float* __restrict__ b1_arr,
                                                      const float* __restrict__ tL_arr,
                                                      int layer, int variant)
{
    extern __shared__ float smemf[];
    float* sIn = smemf;                 // 968*32
    float* sW  = smemf + NROWS * 32;    // [tap][ic]
    int img = blockIdx.x, tid = threadIdx.x;
    const float4* g4 = (const float4*)(in + (size_t)img * NHWC_STRIDE);
    float4* s4 = (float4*)sIn;
    for (int i = tid; i < NROWS * 8; i += 512) s4[i] = g4[i];
    for (int i = tid; i < 288; i += 512) {
        int ic = i / 9, tap = i - ic * 9;
        sW[tap * 32 + ic] = w288[i];
    }
    __syncthreads();

    const int dtap[9] = {-45, -44, -43, -1, 0, 1, 43, 44, 45};
    size_t base = (size_t)img * NN;
    for (int p = tid; p < NN; p += 512) {
        int r = p / 40, c = p - r * 40;
        int pp = (r + 1) * 44 + (c + 1);
        float acc = 0.f;
#pragma unroll
        for (int t = 0; t < 9; t++) {
            const float4* a4 = (const float4*)(sIn + (pp + dtap[t]) * 32);
            const float4* wv = (const float4*)(sW + t * 32);
#pragma unroll
            for (int qq = 0; qq < 8; qq++) {
                float4 x = a4[qq], ww = wv[qq];
                acc += x.x * ww.x + x.y * ww.y + x.z * ww.z + x.w * ww.w;
            }
        }
        if (variant == 0) {
            outp[base + p] = acc;
            float lc = Lc[base + p], lp = Lp[base + p];
            float hatL = lc + tL_arr[layer] * (lc - lp);
            Ln[base + p] = hatL + h_arr[layer] * b1_arr[layer] * (Xn[base + p] - acc);
        } else {
            outp[base + p] = acc - zf[base + p];
        }
    }
}

// ---------------- host ----------------

extern "C" void kernel_launch(void* const* d_in, const int* in_sizes, int n_in,
                              void* d_out, int out_size)
{
    const float* y    = (const float*)d_in[0];
    const float* W    = (const float*)d_in[2];
    const float* beta1 = (const float*)d_in[3];
    const float* beta2 = (const float*)d_in[4];
    const float* h_   = (const float*)d_in[5];
    const float* sthr = (const float*)d_in[6];
    const float* thx  = (const float*)d_in[7];
    const float* thz  = (const float*)d_in[8];
    const float* thL  = (const float*)d_in[9];
    const float* c1f  = (const float*)d_in[10];
    const float* c2f  = (const float*)d_in[11];
    const float* c1b  = (const float*)d_in[12];
    const float* c2b  = (const float*)d_in[13];

    float* out = (float*)d_out;
    float* Zs = out;
    float* syms = out + (size_t)9 * NB;
    float* wlo = out + (size_t)18 * NB;

    float *pPhiTPhi, *pPhiTb, *pX, *pL, *pZero, *pZf, *pHx, *pGm, *pNA, *pNB;
    uint32_t* pWPK;
    cudaGetSymbolAddress((void**)&pPhiTPhi, g_PhiTPhi);
    cudaGetSymbolAddress((void**)&pPhiTb, g_PhiTb);
    cudaGetSymbolAddress((void**)&pX, g_Xbuf);
    cudaGetSymbolAddress((void**)&pL, g_Lbuf);
    cudaGetSymbolAddress((void**)&pZero, g_zerobuf);
    cudaGetSymbolAddress((void**)&pZf, g_zflat);
    cudaGetSymbolAddress((void**)&pHx, g_hatx);
    cudaGetSymbolAddress((void**)&pGm, g_gemm);
    cudaGetSymbolAddress((void**)&pNA, g_nA);
    cudaGetSymbolAddress((void**)&pNB, g_nB);
    cudaGetSymbolAddress((void**)&pWPK, g_wpk);

    const int SMMAW = (2 * SROWS * ASTRIDE + 2 * BWORDS + NROWS + 288) * 4;  // 224,864 B
    const int SM1   = (NROWS * 32 + 288) * 4;                                // 125,056 B
    cudaFuncSetAttribute(conv32_mma, cudaFuncAttributeMaxDynamicSharedMemorySize, SMMAW);
    cudaFuncSetAttribute(conv32to1_nhwc, cudaFuncAttributeMaxDynamicSharedMemorySize, SM1);

    cudaMemsetAsync(pZero, 0, (size_t)NB * 4);

    float* Xslot[2] = {pX, pX + NB};
    float* Lslot[2] = {pL, pL + NB};

    // launch order keeps conv32_mma within the profiler capture window
    k_prep<<<BB + WBF_BLOCKS, 128>>>(pNA, pNB, c2f, c1b, pWPK);
    gemm_AB<<<dim3(13, 32), 256>>>(y, W, pPhiTb, BB, MM, NN);

    int xcur = 0, xprev = -1;
    int lcur = 0, lprev = -1;

    for (int i = 0; i < 9; i++) {
        float* Xn;
        if (i == 0) {
            Xn = Xslot[0];
            k_layer0<<<NB / 256, 256>>>(pPhiTb, Xn, pZf, h_, beta2);
            xcur = 0; xprev = -1;
        } else {
            const float* Xc = Xslot[xcur];
            const float* Xp = (xprev < 0) ? pZero : Xslot[xprev];
            const float* Lc_ = Lslot[lcur];
            const float* Zc = Zs + (size_t)(i - 1) * NB;
            const float* Zp = (i >= 2) ? Zs + (size_t)(i - 2) * NB : pZero;
            const float* Zg = (i >= 2) ? Zc : pZero;
            const float* Lg = (i >= 2) ? Lc_ : pZero;
            const float* Lz = (i >= 2) ? Lc_ : pZero;
            int xnew = (xprev < 0) ? 1 : xprev;
            Xn = Xslot[xnew];
            k_hatx<<<NB / 256, 256>>>(Xc, Xp, pHx, thx, i);
            gemm_AB<<<dim3(13, 32), 256>>>(pHx, pPhiTPhi, pGm, BB, NN, NN);
            k_xepi<<<NB / 256, 256>>>(pHx, pGm, pPhiTb, Zg, Lg, Zc, Zp, Lz,
                                      Xn, pZf, beta1, beta2, h_, thz, i);
            xprev = xcur; xcur = xnew;
        }

        // x_fwd: fused 1->32 conv (from zf) + 32->32 mma conv
        conv32_mma<<<BB, 512, SMMAW>>>(nullptr, pWPK, pNB, sthr, i, 0, 0,
                                       1, c1f, pZf);
        // t1: soft-threshold + 32->32 mma conv + relu
        conv32_mma<<<BB, 512, SMMAW>>>(pNB, pWPK + 2 * BWORDS, pNA, sthr, i, 1, 1,
                                       0, nullptr, nullptr);
        {
            const float* Lc_ = (i == 0) ? pZero : Lslot[lcur];
            const float* Lp_ = (i == 0) ? pZero : ((lprev < 0) ? pZero : Lslot[lprev]);
            int lnew = (i == 0) ? 0 : ((lprev < 0) ? 1 : lprev);
            conv32to1_nhwc<<<BB, 512, SM1>>>(pNA, c2b, Zs + (size_t)i * NB, nullptr,
                                             Lslot[lnew], Lc_, Lp_, Xn,
                                             h_, beta1, thL, i, 0);
            if (i > 0) { lprev = lcur; lcur = lnew; }
            else { lcur = 0; lprev = -1; }
        }
        // t2: 32->32 mma conv + relu (no soft)
        conv32_mma<<<BB, 512, SMMAW>>>(pNB, pWPK + 2 * BWORDS, pNA, sthr, i, 0, 1,
                                       0, nullptr, nullptr);
        conv32to1_nhwc<<<BB, 512, SM1>>>(pNA, c2b, syms + (size_t)i * NB, pZf,
                                         nullptr, nullptr, nullptr, nullptr,
                                         h_, beta1, thL, i, 1);

        if (i == 0) {
            gemm_AtB<<<dim3(13, 13), 256>>>(W, W, pPhiTPhi, MM, NN, NN);
        }
    }

    k_wloss<<<dim3(21, 21), dim3(16, 16)>>>(W, wlo);
}

// round 13
// speedup vs baseline: 2.7162x; 1.5193x over previous
#include <cuda_runtime.h>
#include <cuda_bf16.h>
#include <cstdint>

#define BB 4096
#define MM 327
#define NN 800
#define NB (BB*NN)              // 3,276,800 per state buffer
#define NROWS 968               // 22*44 padded pixel rows
#define NHWC_STRIDE (NROWS*32)  // floats per image in NHWC buffers
#define SROW0 48
#define SROWS 1086              // 48 guard + 968 data + 70 guard rows
#define ASTRIDE 20              // words per row in smem A ({20q+c} distinct mod 32)
#define BSTRIDE 40              // words per icpair in smem B ({40c+q} distinct mod 32)
#define BWORDS (9*16*BSTRIDE)   // 5760 words per (set,half)
#define WBF_BLOCKS 46
#define SOSTRIDE 36             // fp32 out rows in smem (mult of 4 for float4)

typedef unsigned long long ull;

// ---------------- device scratch (static, allowed) ----------------
__device__ float g_PhiTPhi[NN*NN];
__device__ float g_PhiTb[NB];
__device__ float g_Xbuf[2*NB];
__device__ float g_Lbuf[2*NB];
__device__ float g_zerobuf[NB];
__device__ float g_zflat[NB];
__device__ float g_hatx[NB];
__device__ float g_gemm[NB];
__device__ float g_nB[(size_t)BB*NHWC_STRIDE];   // NHWC feature buffer (x_fwd)
__device__ uint32_t g_wpk[2*2*BWORDS];           // [set][hi/lo][BWORDS] packed bf16x2

__constant__ int c_dtap[9] = {-45, -44, -43, -1, 0, 1, 43, 44, 45};

// ---------------- helpers ----------------
__device__ __forceinline__ uint32_t pkbf2(__nv_bfloat16 e0, __nv_bfloat16 e1) {
    return ((uint32_t)__bfloat16_as_ushort(e1) << 16) | (uint32_t)__bfloat16_as_ushort(e0);
}
__device__ __forceinline__ uint32_t cvt2bf(float hi, float lo) {
    uint32_t r;
    asm("cvt.rn.satfinite.bf16x2.f32 %0, %1, %2;" : "=r"(r) : "f"(hi), "f"(lo));
    return r;
}

__device__ __forceinline__ void mma_bf16(float* d, const uint32_t* a, uint32_t b0, uint32_t b1) {
    asm volatile(
        "mma.sync.aligned.m16n8k16.row.col.f32.bf16.bf16.f32 "
        "{%0,%1,%2,%3}, {%4,%5,%6,%7}, {%8,%9}, {%0,%1,%2,%3};"
        : "+f"(d[0]), "+f"(d[1]), "+f"(d[2]), "+f"(d[3])
        : "r"(a[0]), "r"(a[1]), "r"(a[2]), "r"(a[3]), "r"(b0), "r"(b1));
}

__device__ __forceinline__ void ldAfrag(uint32_t* a, const uint32_t* Aarr, int baserow,
                                        int ks, int q, int c) {
    int tap = ks >> 1, icb = (ks & 1) * 8;
    const uint32_t* Ap = Aarr + (baserow + c_dtap[tap] + q) * ASTRIDE + icb + c;
    a[0] = Ap[0];
    a[1] = Ap[8 * ASTRIDE];
    a[2] = Ap[4];
    a[3] = Ap[8 * ASTRIDE + 4];
    a[4] = Ap[16 * ASTRIDE];
    a[5] = Ap[24 * ASTRIDE];
    a[6] = Ap[16 * ASTRIDE + 4];
    a[7] = Ap[24 * ASTRIDE + 4];
}
__device__ __forceinline__ void ldBfrag(uint32_t* b, const uint32_t* Barr,
                                        int ks, int q, int c) {
    int tap = ks >> 1, icb = (ks & 1) * 8;
    const uint32_t* Bp = Barr + tap * (16 * BSTRIDE) + (icb + c) * BSTRIDE + q;
#pragma unroll
    for (int o = 0; o < 4; o++) {
        b[2 * o]     = Bp[o * 8];
        b[2 * o + 1] = Bp[4 * BSTRIDE + o * 8];
    }
}

// ---------------- small GEMMs ----------------

__global__ __launch_bounds__(256) void gemm_AtB(const float* __restrict__ A,
                                                const float* __restrict__ B,
                                                float* __restrict__ C,
                                                int K, int I, int J)
{
    __shared__ float As[16][68];
    __shared__ float Bs[16][68];
    int tid = threadIdx.x;
    int tx = tid & 15, ty = tid >> 4;
    int i0 = blockIdx.y * 64, j0 = blockIdx.x * 64;
    float acc[4][4];
#pragma unroll
    for (int a = 0; a < 4; a++)
#pragma unroll
        for (int b = 0; b < 4; b++) acc[a][b] = 0.f;

    int kr = tid >> 4, c4 = (tid & 15) * 4;
    for (int k0 = 0; k0 < K; k0 += 16) {
        bool kv = (k0 + kr) < K;
#pragma unroll
        for (int j = 0; j < 4; j++) {
            int ii = i0 + c4 + j;
            As[kr][c4 + j] = (kv && ii < I) ? A[(size_t)(k0 + kr) * I + ii] : 0.f;
            int jj = j0 + c4 + j;
            Bs[kr][c4 + j] = (kv && jj < J) ? B[(size_t)(k0 + kr) * J + jj] : 0.f;
        }
        __syncthreads();
#pragma unroll
        for (int kk = 0; kk < 16; kk++) {
            float a[4], b[4];
#pragma unroll
            for (int i = 0; i < 4; i++) a[i] = As[kk][ty * 4 + i];
#pragma unroll
            for (int j = 0; j < 4; j++) b[j] = Bs[kk][tx * 4 + j];
#pragma unroll
            for (int i = 0; i < 4; i++)
#pragma unroll
                for (int j = 0; j < 4; j++) acc[i][j] += a[i] * b[j];
        }
        __syncthreads();
    }
#pragma unroll
    for (int i = 0; i < 4; i++) {
        int r = i0 + ty * 4 + i;
        if (r < I) {
#pragma unroll
            for (int j = 0; j < 4; j++) {
                int n = j0 + tx * 4 + j;
                if (n < J) C[(size_t)r * J + n] = acc[i][j];
            }
        }
    }
}

__global__ __launch_bounds__(256) void gemm_AB(const float* __restrict__ A,
                                               const float* __restrict__ B,
                                               float* __restrict__ C,
                                               int M, int K, int N)
{
    __shared__ float As[16][132];
    __shared__ float Bs[16][68];
    int tid = threadIdx.x;
    int tx = tid & 15, ty = tid >> 4;
    int row0 = blockIdx.y * 128, n0 = blockIdx.x * 64;

    float acc[8][4];
#pragma unroll
    for (int a = 0; a < 8; a++)
#pragma unroll
        for (int b = 0; b < 4; b++) acc[a][b] = 0.f;

    int arow = tid >> 1;
    int ak0 = (tid & 1) * 8;
    int kr = tid >> 4, nc = (tid & 15) * 4;

    for (int k0 = 0; k0 < K; k0 += 16) {
        const float* aptr = A + (size_t)(row0 + arow) * K + k0 + ak0;
#pragma unroll
        for (int j = 0; j < 8; j++) {
            int k = k0 + ak0 + j;
            As[ak0 + j][arow] = (k < K) ? aptr[j] : 0.f;
        }
#pragma unroll
        for (int j = 0; j < 4; j++) {
            int n = n0 + nc + j;
            Bs[kr][nc + j] = ((k0 + kr) < K && n < N) ? B[(size_t)(k0 + kr) * N + n] : 0.f;
        }
        __syncthreads();
#pragma unroll
        for (int kk = 0; kk < 16; kk++) {
            float a[8], b[4];
#pragma unroll
            for (int i = 0; i < 8; i++) a[i] = As[kk][ty * 8 + i];
#pragma unroll
            for (int j = 0; j < 4; j++) b[j] = Bs[kk][tx * 4 + j];
#pragma unroll
            for (int i = 0; i < 8; i++)
#pragma unroll
                for (int j = 0; j < 4; j++) acc[i][j] += a[i] * b[j];
        }
        __syncthreads();
    }
#pragma unroll
    for (int i = 0; i < 8; i++) {
        int r = row0 + ty * 8 + i;
#pragma unroll
        for (int j = 0; j < 4; j++) {
            int n = n0 + tx * 4 + j;
            if (n < N) C[(size_t)r * N + n] = acc[i][j];
        }
    }
}

__global__ void k_wloss(const float* __restrict__ W, float* __restrict__ C)
{
    __shared__ float sA[16][17];
    __shared__ float sB[16][17];
    int tx = threadIdx.x, ty = threadIdx.y;
    int i0 = blockIdx.y * 16, j0 = blockIdx.x * 16;
    float acc = 0.f;
    for (int k0 = 0; k0 < 800; k0 += 16) {
        sA[ty][tx] = (i0 + ty < MM) ? W[(size_t)(i0 + ty) * NN + k0 + tx] : 0.f;
        sB[ty][tx] = (j0 + ty < MM) ? W[(size_t)(j0 + ty) * NN + k0 + tx] : 0.f;
        __syncthreads();
#pragma unroll
        for (int kk = 0; kk < 16; kk++) acc += sA[ty][kk] * sB[tx][kk];
        __syncthreads();
    }
    int i = i0 + ty, j = j0 + tx;
    if (i < MM && j < MM) C[i * MM + j] = acc - (i == j ? 1.f : 0.f);
}

// ---------------- elementwise ----------------

__global__ void k_layer0(const float* __restrict__ PhiTb, float* __restrict__ X1,
                         float* __restrict__ zf,
                         const float* __restrict__ h_arr, const float* __restrict__ b2_arr)
{
    int i = blockIdx.x * blockDim.x + threadIdx.x;
    if (i >= NB) return;
    float h0 = h_arr[0], b2 = b2_arr[0];
    float x = h0 * PhiTb[i];
    X1[i] = x;
    zf[i] = h0 * b2 * x;
}

__global__ void k_hatx(const float* __restrict__ Xc, const float* __restrict__ Xp,
                       float* __restrict__ hx,
                       const float* __restrict__ tx_arr, int layer)
{
    int i = blockIdx.x * blockDim.x + threadIdx.x;
    if (i >= NB) return;
    float t = tx_arr[layer];
    float xc = Xc[i];
    hx[i] = xc + t * (xc - Xp[i]);
}

__global__ void k_xepi(const float* __restrict__ hx, const float* __restrict__ gm,
                       const float* __restrict__ PhiTb,
                       const float* __restrict__ Zg, const float* __restrict__ Lg,
                       const float* __restrict__ Zc, const float* __restrict__ Zp,
                       const float* __restrict__ Lz,
                       float* __restrict__ Xn, float* __restrict__ zf,
                       const float* __restrict__ b1a, const float* __restrict__ b2a,
                       const float* __restrict__ ha, const float* __restrict__ tza,
                       int layer)
{
    int i = blockIdx.x * blockDim.x + threadIdx.x;
    if (i >= NB) return;
    float b1 = b1a[layer], b2 = b2a[layer], hh = ha[layer], tz = tza[layer];
    float hxv = hx[i];
    float grad = PhiTb[i] - gm[i] + b1 * (Zg[i] - hxv) - Lg[i];
    float xn = hxv + hh * grad;
    Xn[i] = xn;
    float zc = Zc[i];
    float hz = zc + tz * (zc - Zp[i]);
    zf[i] = hz + hh * (Lz[i] + b2 * (xn - hz));
}

// ---------------- fused prep: zero NHWC padding rows + pack bf16 weights ----

__global__ __launch_bounds__(128) void k_prep(float* __restrict__ b,
                                              const float* __restrict__ c2f,
                                              const float* __restrict__ c1b,
                                              uint32_t* __restrict__ wpk)
{
    int t = threadIdx.x;
    if (blockIdx.x < BB) {
        int img = blockIdx.x;
        int row;
        if (t < 44) row = t;
        else if (t < 88) row = 924 + (t - 44);
        else { int j = t - 88; row = (1 + (j >> 1)) * 44 + ((j & 1) ? 43 : 0); }
        float4 z = make_float4(0.f, 0.f, 0.f, 0.f);
        float4* pb = (float4*)(b + (size_t)img * NHWC_STRIDE + row * 32);
#pragma unroll
        for (int q = 0; q < 8; q++) pb[q] = z;
    } else {
        int base = (blockIdx.x - BB) * 128 + t;
        for (int i = base; i < 2 * BWORDS; i += WBF_BLOCKS * 128) {
            int set = i / BWORDS, rem = i - set * BWORDS;
            int tap = rem / (16 * BSTRIDE), rem2 = rem - tap * (16 * BSTRIDE);
            int icp = rem2 / BSTRIDE, oc = rem2 - icp * BSTRIDE;
            const float* src = set ? c1b : c2f;
            uint32_t whi = 0u, wlo = 0u;
            if (oc < 32) {
                float w0 = src[oc * 288 + (2 * icp) * 9 + tap];
                float w1 = src[oc * 288 + (2 * icp + 1) * 9 + tap];
                __nv_bfloat16 h0 = __float2bfloat16_rn(w0), h1 = __float2bfloat16_rn(w1);
                __nv_bfloat16 l0 = __float2bfloat16_rn(w0 - __bfloat162float(h0));
                __nv_bfloat16 l1 = __float2bfloat16_rn(w1 - __bfloat162float(h1));
                whi = pkbf2(h0, h1);
                wlo = pkbf2(l0, l1);
            }
            int off = tap * (16 * BSTRIDE) + icp * BSTRIDE + oc;
            wpk[set * 2 * BWORDS + off] = whi;
            wpk[set * 2 * BWORDS + BWORDS + off] = wlo;
        }
    }
}

// ---------------- conv kernels ----------------

// x_fwd: fused 1->32 conv (from 800-float zf, relu) + 32->32 mma conv (no relu).
// Writes NHWC fp32 to gmem (consumed twice downstream). 512 threads.
__global__ __launch_bounds__(512) void conv32_fwd(const uint32_t* __restrict__ wpk,
                                                  float* __restrict__ outp,
                                                  const float* __restrict__ w1,
                                                  const float* __restrict__ zf_in)
{
    extern __shared__ uint32_t smw[];
    uint32_t* sAhi = smw;                       // SROWS*ASTRIDE
    uint32_t* sAlo = smw + SROWS * ASTRIDE;
    uint32_t* sBhi = smw + 2 * SROWS * ASTRIDE; // BWORDS
    uint32_t* sBlo = sBhi + BWORDS;
    float* sZf = (float*)(sBlo + BWORDS);       // NROWS
    float* sW1 = sZf + NROWS;                   // 288
    int img = blockIdx.x, tid = threadIdx.x;

    for (int i = tid; i < 48 * ASTRIDE; i += 512) { sAhi[i] = 0u; sAlo[i] = 0u; }
    for (int i = tid; i < 70 * ASTRIDE; i += 512) {
        sAhi[1016 * ASTRIDE + i] = 0u; sAlo[1016 * ASTRIDE + i] = 0u;
    }
    for (int i = tid; i < BWORDS; i += 512) { sBhi[i] = wpk[i]; sBlo[i] = wpk[BWORDS + i]; }

    // zero all data rows, stage zf + 1->32 weights
    uint4 z4 = make_uint4(0u, 0u, 0u, 0u);
    for (int i = tid; i < NROWS * 4 * 2; i += 512) {
        int arr = (i >= NROWS * 4);
        int j = arr ? i - NROWS * 4 : i;
        int row = j >> 2, qq = j & 3;
        uint32_t* basep = (arr ? sAlo : sAhi) + (SROW0 + row) * ASTRIDE + qq * 4;
        *(uint4*)basep = z4;
    }
    for (int i = tid; i < NROWS; i += 512) sZf[i] = 0.f;
    for (int i = tid; i < 288; i += 512) {
        int oc = i / 9, tap = i - oc * 9;
        sW1[tap * 32 + oc] = w1[i];
    }
    __syncthreads();
    const float* gz = zf_in + (size_t)img * NN;
    for (int i = tid; i < NN; i += 512) {
        int r = i / 40, c0 = i - r * 40;
        sZf[(r + 1) * 44 + c0 + 1] = gz[i];
    }
    __syncthreads();
    for (int i = tid; i < NN * 16; i += 512) {
        int px = i >> 4, qq = i & 15;
        int r = px / 40, c0 = px - r * 40;
        int pp = (r + 1) * 44 + (c0 + 1);
        float a0 = 0.f, a1 = 0.f;
#pragma unroll
        for (int t = 0; t < 9; t++) {
            float zv = sZf[pp + c_dtap[t]];
            a0 += sW1[t * 32 + 2 * qq] * zv;
            a1 += sW1[t * 32 + 2 * qq + 1] * zv;
        }
        a0 = fmaxf(a0, 0.f);
        a1 = fmaxf(a1, 0.f);
        uint32_t hi = cvt2bf(a1, a0);
        float h0 = __uint_as_float(hi << 16);
        float h1 = __uint_as_float(hi & 0xFFFF0000u);
        uint32_t lo = cvt2bf(a1 - h1, a0 - h0);
        int base = (SROW0 + pp) * ASTRIDE + qq;
        sAhi[base] = hi;
        sAlo[base] = lo;
    }
    __syncthreads();

    int warp = tid >> 5, lane = tid & 31;
    int q = lane >> 2, c = lane & 3;
    float* gout = outp + (size_t)img * NHWC_STRIDE;

    int u1 = warp, u2 = warp + 16;
    bool has2 = (u2 < 31);
    int r1 = SROW0 + u1 * 32;
    int r2 = SROW0 + (has2 ? u2 : u1) * 32;

    float acc1[2][4][4], acc2[2][4][4];
#pragma unroll
    for (int s = 0; s < 2; s++)
#pragma unroll
        for (int o = 0; o < 4; o++)
#pragma unroll
            for (int j = 0; j < 4; j++) { acc1[s][o][j] = 0.f; acc2[s][o][j] = 0.f; }

#pragma unroll 1
    for (int pass = 0; pass < 3; pass++) {
        const uint32_t* Aarr = (pass == 2) ? sAlo : sAhi;
        const uint32_t* Barr = (pass == 1) ? sBlo : sBhi;
#pragma unroll
        for (int ks = 0; ks < 18; ks++) {
            uint32_t Af1[8], Af2[8], Bf[8];
            ldAfrag(Af1, Aarr, r1, ks, q, c);
            if (has2) ldAfrag(Af2, Aarr, r2, ks, q, c);
            ldBfrag(Bf, Barr, ks, q, c);
#pragma unroll
            for (int o = 0; o < 4; o++) {
                uint32_t b0 = Bf[2 * o], b1 = Bf[2 * o + 1];
                mma_bf16(acc1[0][o], Af1 + 0, b0, b1);
                mma_bf16(acc1[1][o], Af1 + 4, b0, b1);
                if (has2) {
                    mma_bf16(acc2[0][o], Af2 + 0, b0, b1);
                    mma_bf16(acc2[1][o], Af2 + 4, b0, b1);
                }
            }
        }
    }

#pragma unroll
    for (int uu = 0; uu < 2; uu++) {
        if (uu == 1 && !has2) break;
        int u = uu ? u2 : u1;
        float (*acc)[4][4] = uu ? acc2 : acc1;
#pragma unroll
        for (int s = 0; s < 2; s++) {
            int grow0 = u * 32 + s * 16 + q;
#pragma unroll
            for (int half = 0; half < 2; half++) {
                int grow = grow0 + half * 8;
                int rr = grow / 44, cc = grow - rr * 44;
                bool valid = (grow < NROWS) && rr >= 1 && rr <= 20 && cc >= 1 && cc <= 40;
                if (valid) {
                    float* ob = gout + grow * 32 + c * 2;
#pragma unroll
                    for (int o = 0; o < 4; o++) {
                        float x0 = acc[s][o][half * 2 + 0];
                        float x1 = acc[s][o][half * 2 + 1];
                        *(float2*)(ob + o * 8) = make_float2(x0, x1);
                    }
                }
            }
        }
    }
}

// t1/t2: fill (optional soft) + 32->32 mma conv + relu -> smem fp32,
// then fused 32->1 conv. variant 0: Z + L-update. variant 1: conv - zf -> syms.
__global__ __launch_bounds__(512) void conv32_fused(const float* __restrict__ in,
                                                    const uint32_t* __restrict__ wpk,
                                                    const float* __restrict__ thr_arr,
                                                    int layer, int do_soft, int variant,
                                                    float* __restrict__ outp,
                                                    const float* __restrict__ zf,
                                                    float* __restrict__ Ln,
                                                    const float* __restrict__ Lc,
                                                    const float* __restrict__ Lp,
                                                    const float* __restrict__ Xn,
                                                    const float* __restrict__ h_arr,
                                                    const float* __restrict__ b1_arr,
                                                    const float* __restrict__ tL_arr,
                                                    const float* __restrict__ w288)
{
    extern __shared__ uint32_t smw[];
    uint32_t* sAhi = smw;                       // SROWS*ASTRIDE
    uint32_t* sAlo = smw + SROWS * ASTRIDE;
    uint32_t* sBhi = smw + 2 * SROWS * ASTRIDE; // BWORDS
    uint32_t* sBlo = sBhi + BWORDS;
    float* sWc = (float*)(sBlo + BWORDS);       // 288 ([tap][ic])
    float* sOut = (float*)smw;                  // overlays A region after mma
    int img = blockIdx.x, tid = threadIdx.x;

    for (int i = tid; i < 48 * ASTRIDE; i += 512) { sAhi[i] = 0u; sAlo[i] = 0u; }
    for (int i = tid; i < 70 * ASTRIDE; i += 512) {
        sAhi[1016 * ASTRIDE + i] = 0u; sAlo[1016 * ASTRIDE + i] = 0u;
    }
    for (int i = tid; i < BWORDS; i += 512) { sBhi[i] = wpk[i]; sBlo[i] = wpk[BWORDS + i]; }
    for (int i = tid; i < 288; i += 512) {
        int ic = i / 9, tap = i - ic * 9;
        sWc[tap * 32 + ic] = w288[i];
    }

    float sthr = do_soft ? fabsf(thr_arr[layer]) : 0.f;
    const float4* g4 = (const float4*)(in + (size_t)img * NHWC_STRIDE);
    for (int i = tid; i < NROWS * 8; i += 512) {
        float4 v = g4[i];
        if (do_soft) {
#pragma unroll
            for (int j = 0; j < 4; j++) {
                float x = (&v.x)[j];
                float a = fabsf(x) - sthr;
                (&v.x)[j] = (a > 0.f) ? (x > 0.f ? a : -a) : 0.f;
            }
        }
        int row = i >> 3, qq = i & 7;
        int base = (SROW0 + row) * ASTRIDE + qq * 2;
        uint32_t hi01 = cvt2bf(v.y, v.x);
        uint32_t hi23 = cvt2bf(v.w, v.z);
        float h0 = __uint_as_float(hi01 << 16);
        float h1 = __uint_as_float(hi01 & 0xFFFF0000u);
        float h2 = __uint_as_float(hi23 << 16);
        float h3 = __uint_as_float(hi23 & 0xFFFF0000u);
        uint32_t lo01 = cvt2bf(v.y - h1, v.x - h0);
        uint32_t lo23 = cvt2bf(v.w - h3, v.z - h2);
        sAhi[base]     = hi01;
        sAhi[base + 1] = hi23;
        sAlo[base]     = lo01;
        sAlo[base + 1] = lo23;
    }
    __syncthreads();

    int warp = tid >> 5, lane = tid & 31;
    int q = lane >> 2, c = lane & 3;

    int u1 = warp, u2 = warp + 16;
    bool has2 = (u2 < 31);
    int r1 = SROW0 + u1 * 32;
    int r2 = SROW0 + (has2 ? u2 : u1) * 32;

    float acc1[2][4][4], acc2[2][4][4];
#pragma unroll
    for (int s = 0; s < 2; s++)
#pragma unroll
        for (int o = 0; o < 4; o++)
#pragma unroll
            for (int j = 0; j < 4; j++) { acc1[s][o][j] = 0.f; acc2[s][o][j] = 0.f; }

#pragma unroll 1
    for (int pass = 0; pass < 3; pass++) {
        const uint32_t* Aarr = (pass == 2) ? sAlo : sAhi;
        const uint32_t* Barr = (pass == 1) ? sBlo : sBhi;
#pragma unroll
        for (int ks = 0; ks < 18; ks++) {
            uint32_t Af1[8], Af2[8], Bf[8];
            ldAfrag(Af1, Aarr, r1, ks, q, c);
            if (has2) ldAfrag(Af2, Aarr, r2, ks, q, c);
            ldBfrag(Bf, Barr, ks, q, c);
#pragma unroll
            for (int o = 0; o < 4; o++) {
                uint32_t b0 = Bf[2 * o], b1 = Bf[2 * o + 1];
                mma_bf16(acc1[0][o], Af1 + 0, b0, b1);
                mma_bf16(acc1[1][o], Af1 + 4, b0, b1);
                if (has2) {
                    mma_bf16(acc2[0][o], Af2 + 0, b0, b1);
                    mma_bf16(acc2[1][o], Af2 + 4, b0, b1);
                }
            }
        }
    }

    // all warps done reading sA -> safe to overlay sOut
    __syncthreads();

    // zero ALL sOut rows (stale A-operand bits otherwise leak through taps:
    // cc=41/42 are read by the 32->1 conv but never written by the epilogue)
    {
        float4 z = make_float4(0.f, 0.f, 0.f, 0.f);
        for (int i = tid; i < NROWS * 9; i += 512)
            ((float4*)sOut)[i] = z;
    }
    __syncthreads();

    // epilogue: relu + store fp32 to sOut (valid pixels only)
#pragma unroll
    for (int uu = 0; uu < 2; uu++) {
        if (uu == 1 && !has2) break;
        int u = uu ? u2 : u1;
        float (*acc)[4][4] = uu ? acc2 : acc1;
#pragma unroll
        for (int s = 0; s < 2; s++) {
            int grow0 = u * 32 + s * 16 + q;
#pragma unroll
            for (int half = 0; half < 2; half++) {
                int grow = grow0 + half * 8;
                int rr = grow / 44, cc = grow - rr * 44;
                bool valid = (grow < NROWS) && rr >= 1 && rr <= 20 && cc >= 1 && cc <= 40;
                if (valid) {
                    float* ob = sOut + grow * SOSTRIDE + c * 2;
#pragma unroll
                    for (int o = 0; o < 4; o++) {
                        float x0 = fmaxf(acc[s][o][half * 2 + 0], 0.f);
                        float x1 = fmaxf(acc[s][o][half * 2 + 1], 0.f);
                        *(float2*)(ob + o * 8) = make_float2(x0, x1);
                    }
                }
            }
        }
    }
    __syncthreads();

    // fused 32->1 conv + output math
    size_t base = (size_t)img * NN;
    for (int p = tid; p < NN; p += 512) {
        int r = p / 40, c0 = p - r * 40;
        int pp = (r + 1) * 44 + (c0 + 1);
        float acc = 0.f;
#pragma unroll
        for (int t = 0; t < 9; t++) {
            const float4* a4 = (const float4*)(sOut + (pp + c_dtap[t]) * SOSTRIDE);
            const float4* wv = (const float4*)(sWc + t * 32);
#pragma unroll
            for (int qq = 0; qq < 8; qq++) {
                float4 x = a4[qq], ww = wv[qq];
                acc += x.x * ww.x + x.y * ww.y + x.z * ww.z + x.w * ww.w;
            }
        }
        if (variant == 0) {
            outp[base + p] = acc;
            float lc = Lc[base + p], lp = Lp[base + p];
            float hatL = lc + tL_arr[layer] * (lc - lp);
            Ln[base + p] = hatL + h_arr[layer] * b1_arr[layer] * (Xn[base + p] - acc);
        } else {
            outp[base + p] = acc - zf[base + p];
        }
    }
}

// ---------------- host ----------------

extern "C" void kernel_launch(void* const* d_in, const int* in_sizes, int n_in,
                              void* d_out, int out_size)
{
    const float* y    = (const float*)d_in[0];
    const float* W    = (const float*)d_in[2];
    const float* beta1 = (const float*)d_in[3];
    const float* beta2 = (const float*)d_in[4];
    const float* h_   = (const float*)d_in[5];
    const float* sthr = (const float*)d_in[6];
    const float* thx  = (const float*)d_in[7];
    const float* thz  = (const float*)d_in[8];
    const float* thL  = (const float*)d_in[9];
    const float* c1f  = (const float*)d_in[10];
    const float* c2f  = (const float*)d_in[11];
    const float* c1b  = (const float*)d_in[12];
    const float* c2b  = (const float*)d_in[13];

    float* out = (float*)d_out;
    float* Zs = out;
    float* syms = out + (size_t)9 * NB;
    float* wlo = out + (size_t)18 * NB;

    float *pPhiTPhi, *pPhiTb, *pX, *pL, *pZero, *pZf, *pHx, *pGm, *pNB;
    uint32_t* pWPK;
    cudaGetSymbolAddress((void**)&pPhiTPhi, g_PhiTPhi);
    cudaGetSymbolAddress((void**)&pPhiTb, g_PhiTb);
    cudaGetSymbolAddress((void**)&pX, g_Xbuf);
    cudaGetSymbolAddress((void**)&pL, g_Lbuf);
    cudaGetSymbolAddress((void**)&pZero, g_zerobuf);
    cudaGetSymbolAddress((void**)&pZf, g_zflat);
    cudaGetSymbolAddress((void**)&pHx, g_hatx);
    cudaGetSymbolAddress((void**)&pGm, g_gemm);
    cudaGetSymbolAddress((void**)&pNB, g_nB);
    cudaGetSymbolAddress((void**)&pWPK, g_wpk);

    const int SMMAW = (2 * SROWS * ASTRIDE + 2 * BWORDS + NROWS + 288) * 4;  // 224,864 B
    cudaFuncSetAttribute(conv32_fwd, cudaFuncAttributeMaxDynamicSharedMemorySize, SMMAW);
    cudaFuncSetAttribute(conv32_fused, cudaFuncAttributeMaxDynamicSharedMemorySize, SMMAW);

    cudaMemsetAsync(pZero, 0, (size_t)NB * 4);

    float* Xslot[2] = {pX, pX + NB};
    float* Lslot[2] = {pL, pL + NB};

    k_prep<<<BB + WBF_BLOCKS, 128>>>(pNB, c2f, c1b, pWPK);
    gemm_AB<<<dim3(13, 32), 256>>>(y, W, pPhiTb, BB, MM, NN);

    int xcur = 0, xprev = -1;
    int lcur = 0, lprev = -1;

    for (int i = 0; i < 9; i++) {
        float* Xn;
        if (i == 0) {
            Xn = Xslot[0];
            k_layer0<<<NB / 256, 256>>>(pPhiTb, Xn, pZf, h_, beta2);
            xcur = 0; xprev = -1;
        } else {
            const float* Xc = Xslot[xcur];
            const float* Xp = (xprev < 0) ? pZero : Xslot[xprev];
            const float* Lc_ = Lslot[lcur];
            const float* Zc = Zs + (size_t)(i - 1) * NB;
            const float* Zp = (i >= 2) ? Zs + (size_t)(i - 2) * NB : pZero;
            const float* Zg = (i >= 2) ? Zc : pZero;
            const float* Lg = (i >= 2) ? Lc_ : pZero;
            const float* Lz = (i >= 2) ? Lc_ : pZero;
            int xnew = (xprev < 0) ? 1 : xprev;
            Xn = Xslot[xnew];
            k_hatx<<<NB / 256, 256>>>(Xc, Xp, pHx, thx, i);
            gemm_AB<<<dim3(13, 32), 256>>>(pHx, pPhiTPhi, pGm, BB, NN, NN);
            k_xepi<<<NB / 256, 256>>>(pHx, pGm, pPhiTb, Zg, Lg, Zc, Zp, Lz,
                                      Xn, pZf, beta1, beta2, h_, thz, i);
            xprev = xcur; xcur = xnew;
        }

        // x_fwd: fused 1->32 + 32->32 mma conv -> NHWC gmem
        conv32_fwd<<<BB, 512, SMMAW>>>(pWPK, pNB, c1f, pZf);

        // t1 + 32->1 + L-update -> Zs, Ln
        {
            const float* Lc_ = (i == 0) ? pZero : Lslot[lcur];
            const float* Lp_ = (i == 0) ? pZero : ((lprev < 0) ? pZero : Lslot[lprev]);
            int lnew = (i == 0) ? 0 : ((lprev < 0) ? 1 : lprev);
            conv32_fused<<<BB, 512, SMMAW>>>(pNB, pWPK + 2 * BWORDS, sthr, i, 1, 0,
                                             Zs + (size_t)i * NB, nullptr,
                                             Lslot[lnew], Lc_, Lp_, Xn,
                                             h_, beta1, thL, c2b);
            if (i > 0) { lprev = lcur; lcur = lnew; }
            else { lcur = 0; lprev = -1; }
        }

        // t2 + 32->1 - zf -> syms
        conv32_fused<<<BB, 512, SMMAW>>>(pNB, pWPK + 2 * BWORDS, sthr, i, 0, 1,
                                         syms + (size_t)i * NB, pZf,
                                         nullptr, nullptr, nullptr, nullptr,
                                         h_, beta1, thL, c2b);

        if (i == 0) {
            gemm_AtB<<<dim3(13, 13), 256>>>(W, W, pPhiTPhi, MM, NN, NN);
        }
    }

    k_wloss<<<dim3(21, 21), dim3(16, 16)>>>(W, wlo);
}

// round 14
// speedup vs baseline: 2.7375x; 1.0078x over previous
#include <cuda_runtime.h>
#include <cuda_bf16.h>
#include <cstdint>

#define BB 4096
#define MM 327
#define NN 800
#define NB (BB*NN)              // 3,276,800 per state buffer
#define NROWS 968               // 22*44 padded pixel rows
#define NHWC_STRIDE (NROWS*32)  // floats per image in NHWC buffers
#define SROW0 48
#define SROWS 1086              // 48 guard + 968 data + 70 guard rows
#define ASTRIDE 20              // words per row in smem A ({20q+c} distinct mod 32)
#define BSTRIDE 40              // words per icpair in smem B ({40c+q} distinct mod 32)
#define BWORDS (9*16*BSTRIDE)   // 5760 words per (set,half)
#define WBF_BLOCKS 46
#define SOSTRIDE 36             // fp32 out rows in smem (mult of 4 for float4)

// gemm_mma tile params
#define GASTR 20                // A smem stride words
#define GBSTR 136               // B smem stride words (128 + 8; 136%32=8 -> conflict-free)

typedef unsigned long long ull;

// ---------------- device scratch (static, allowed) ----------------
__device__ float g_PhiTPhi[NN*NN];
__device__ float g_PhiTb[NB];
__device__ float g_Xbuf[2*NB];
__device__ float g_Lbuf[2*NB];
__device__ float g_zerobuf[NB];
__device__ float g_zflat[NB];
__device__ float g_hatx[NB];
__device__ float g_gemm[NB];
__device__ float g_nB[(size_t)BB*NHWC_STRIDE];   // NHWC feature buffer (x_fwd)
__device__ uint32_t g_wpk[2*2*BWORDS];           // [set][hi/lo][BWORDS] packed bf16x2

__constant__ int c_dtap[9] = {-45, -44, -43, -1, 0, 1, 43, 44, 45};

// ---------------- helpers ----------------
__device__ __forceinline__ uint32_t pkbf2(__nv_bfloat16 e0, __nv_bfloat16 e1) {
    return ((uint32_t)__bfloat16_as_ushort(e1) << 16) | (uint32_t)__bfloat16_as_ushort(e0);
}
__device__ __forceinline__ uint32_t cvt2bf(float hi, float lo) {
    uint32_t r;
    asm("cvt.rn.satfinite.bf16x2.f32 %0, %1, %2;" : "=r"(r) : "f"(hi), "f"(lo));
    return r;
}

__device__ __forceinline__ void mma_bf16(float* d, const uint32_t* a, uint32_t b0, uint32_t b1) {
    asm volatile(
        "mma.sync.aligned.m16n8k16.row.col.f32.bf16.bf16.f32 "
        "{%0,%1,%2,%3}, {%4,%5,%6,%7}, {%8,%9}, {%0,%1,%2,%3};"
        : "+f"(d[0]), "+f"(d[1]), "+f"(d[2]), "+f"(d[3])
        : "r"(a[0]), "r"(a[1]), "r"(a[2]), "r"(a[3]), "r"(b0), "r"(b1));
}

__device__ __forceinline__ void ldAfrag(uint32_t* a, const uint32_t* Aarr, int baserow,
                                        int ks, int q, int c) {
    int tap = ks >> 1, icb = (ks & 1) * 8;
    const uint32_t* Ap = Aarr + (baserow + c_dtap[tap] + q) * ASTRIDE + icb + c;
    a[0] = Ap[0];
    a[1] = Ap[8 * ASTRIDE];
    a[2] = Ap[4];
    a[3] = Ap[8 * ASTRIDE + 4];
    a[4] = Ap[16 * ASTRIDE];
    a[5] = Ap[24 * ASTRIDE];
    a[6] = Ap[16 * ASTRIDE + 4];
    a[7] = Ap[24 * ASTRIDE + 4];
}
__device__ __forceinline__ void ldBfrag(uint32_t* b, const uint32_t* Barr,
                                        int ks, int q, int c) {
    int tap = ks >> 1, icb = (ks & 1) * 8;
    const uint32_t* Bp = Barr + tap * (16 * BSTRIDE) + (icb + c) * BSTRIDE + q;
#pragma unroll
    for (int o = 0; o < 4; o++) {
        b[2 * o]     = Bp[o * 8];
        b[2 * o + 1] = Bp[4 * BSTRIDE + o * 8];
    }
}

// shared mma mainloop for the conv kernels (2 units per warp sharing B)
__device__ __forceinline__ void conv_mma_loop(const uint32_t* sAhi, const uint32_t* sAlo,
                                              const uint32_t* sBhi, const uint32_t* sBlo,
                                              int r1, int r2, bool has2, int q, int c,
                                              float acc1[2][4][4], float acc2[2][4][4])
{
#pragma unroll
    for (int s = 0; s < 2; s++)
#pragma unroll
        for (int o = 0; o < 4; o++)
#pragma unroll
            for (int j = 0; j < 4; j++) { acc1[s][o][j] = 0.f; acc2[s][o][j] = 0.f; }

#pragma unroll 1
    for (int pass = 0; pass < 3; pass++) {
        const uint32_t* Aarr = (pass == 2) ? sAlo : sAhi;
        const uint32_t* Barr = (pass == 1) ? sBlo : sBhi;
#pragma unroll
        for (int ks = 0; ks < 18; ks++) {
            uint32_t Af1[8], Af2[8], Bf[8];
            ldAfrag(Af1, Aarr, r1, ks, q, c);
            if (has2) ldAfrag(Af2, Aarr, r2, ks, q, c);
            ldBfrag(Bf, Barr, ks, q, c);
#pragma unroll
            for (int o = 0; o < 4; o++) {
                uint32_t b0 = Bf[2 * o], b1 = Bf[2 * o + 1];
                mma_bf16(acc1[0][o], Af1 + 0, b0, b1);
                mma_bf16(acc1[1][o], Af1 + 4, b0, b1);
                if (has2) {
                    mma_bf16(acc2[0][o], Af2 + 0, b0, b1);
                    mma_bf16(acc2[1][o], Af2 + 4, b0, b1);
                }
            }
        }
    }
}

// fill sA (bf16 hi/lo) from NHWC gmem with optional soft-threshold
__device__ __forceinline__ void conv_fill_A(uint32_t* sAhi, uint32_t* sAlo,
                                            const float* in, int img, int tid,
                                            int do_soft, float sthr)
{
    const float4* g4 = (const float4*)(in + (size_t)img * NHWC_STRIDE);
    for (int i = tid; i < NROWS * 8; i += 512) {
        float4 v = g4[i];
        if (do_soft) {
#pragma unroll
            for (int j = 0; j < 4; j++) {
                float x = (&v.x)[j];
                float a = fabsf(x) - sthr;
                (&v.x)[j] = (a > 0.f) ? (x > 0.f ? a : -a) : 0.f;
            }
        }
        int row = i >> 3, qq = i & 7;
        int base = (SROW0 + row) * ASTRIDE + qq * 2;
        uint32_t hi01 = cvt2bf(v.y, v.x);
        uint32_t hi23 = cvt2bf(v.w, v.z);
        float h0 = __uint_as_float(hi01 << 16);
        float h1 = __uint_as_float(hi01 & 0xFFFF0000u);
        float h2 = __uint_as_float(hi23 << 16);
        float h3 = __uint_as_float(hi23 & 0xFFFF0000u);
        uint32_t lo01 = cvt2bf(v.y - h1, v.x - h0);
        uint32_t lo23 = cvt2bf(v.w - h3, v.z - h2);
        sAhi[base]     = hi01;
        sAhi[base + 1] = hi23;
        sAlo[base]     = lo01;
        sAlo[base + 1] = lo23;
    }
}

// epilogue to smem fp32 (relu) at SOSTRIDE
__device__ __forceinline__ void conv_epi_smem(float* sOut, float acc1[2][4][4],
                                              float acc2[2][4][4], int u1, int u2,
                                              bool has2, int q, int c)
{
#pragma unroll
    for (int uu = 0; uu < 2; uu++) {
        if (uu == 1 && !has2) break;
        int u = uu ? u2 : u1;
        float (*acc)[4][4] = uu ? acc2 : acc1;
#pragma unroll
        for (int s = 0; s < 2; s++) {
            int grow0 = u * 32 + s * 16 + q;
#pragma unroll
            for (int half = 0; half < 2; half++) {
                int grow = grow0 + half * 8;
                int rr = grow / 44, cc = grow - rr * 44;
                bool valid = (grow < NROWS) && rr >= 1 && rr <= 20 && cc >= 1 && cc <= 40;
                if (valid) {
                    float* ob = sOut + grow * SOSTRIDE + c * 2;
#pragma unroll
                    for (int o = 0; o < 4; o++) {
                        float x0 = fmaxf(acc[s][o][half * 2 + 0], 0.f);
                        float x1 = fmaxf(acc[s][o][half * 2 + 1], 0.f);
                        *(float2*)(ob + o * 8) = make_float2(x0, x1);
                    }
                }
            }
        }
    }
}

// ---------------- small GEMMs ----------------

__global__ __launch_bounds__(256) void gemm_AtB(const float* __restrict__ A,
                                                const float* __restrict__ B,
                                                float* __restrict__ C,
                                                int K, int I, int J)
{
    __shared__ float As[16][68];
    __shared__ float Bs[16][68];
    int tid = threadIdx.x;
    int tx = tid & 15, ty = tid >> 4;
    int i0 = blockIdx.y * 64, j0 = blockIdx.x * 64;
    float acc[4][4];
#pragma unroll
    for (int a = 0; a < 4; a++)
#pragma unroll
        for (int b = 0; b < 4; b++) acc[a][b] = 0.f;

    int kr = tid >> 4, c4 = (tid & 15) * 4;
    for (int k0 = 0; k0 < K; k0 += 16) {
        bool kv = (k0 + kr) < K;
#pragma unroll
        for (int j = 0; j < 4; j++) {
            int ii = i0 + c4 + j;
            As[kr][c4 + j] = (kv && ii < I) ? A[(size_t)(k0 + kr) * I + ii] : 0.f;
            int jj = j0 + c4 + j;
            Bs[kr][c4 + j] = (kv && jj < J) ? B[(size_t)(k0 + kr) * J + jj] : 0.f;
        }
        __syncthreads();
#pragma unroll
        for (int kk = 0; kk < 16; kk++) {
            float a[4], b[4];
#pragma unroll
            for (int i = 0; i < 4; i++) a[i] = As[kk][ty * 4 + i];
#pragma unroll
            for (int j = 0; j < 4; j++) b[j] = Bs[kk][tx * 4 + j];
#pragma unroll
            for (int i = 0; i < 4; i++)
#pragma unroll
                for (int j = 0; j < 4; j++) acc[i][j] += a[i] * b[j];
        }
        __syncthreads();
    }
#pragma unroll
    for (int i = 0; i < 4; i++) {
        int r = i0 + ty * 4 + i;
        if (r < I) {
#pragma unroll
            for (int j = 0; j < 4; j++) {
                int n = j0 + tx * 4 + j;
                if (n < J) C[(size_t)r * J + n] = acc[i][j];
            }
        }
    }
}

// bf16 3-pass split GEMM: C[M,N] = A[M,K] * B[K,N], fp32 in/out.
// 128x128 tile, 512 threads (16 warps as 4x4, warp = m32 x n32).
__global__ __launch_bounds__(512) void gemm_mma(const float* __restrict__ A,
                                                const float* __restrict__ B,
                                                float* __restrict__ C,
                                                int M, int K, int N)
{
    __shared__ uint32_t sAhi[128 * GASTR];
    __shared__ uint32_t sAlo[128 * GASTR];
    __shared__ uint32_t sBhi[16 * GBSTR];
    __shared__ uint32_t sBlo[16 * GBSTR];

    int tid = threadIdx.x;
    int warp = tid >> 5, lane = tid & 31;
    int q = lane >> 2, c = lane & 3;
    int m0 = blockIdx.y * 128, n0 = blockIdx.x * 128;
    int wm = (warp >> 2) * 32, wn = (warp & 3) * 32;

    float acc[2][4][4];
#pragma unroll
    for (int s = 0; s < 2; s++)
#pragma unroll
        for (int o = 0; o < 4; o++)
#pragma unroll
            for (int j = 0; j < 4; j++) acc[s][o][j] = 0.f;

    for (int k0 = 0; k0 < K; k0 += 32) {
        // A: 128 rows x 16 k-pair words
        for (int i = tid; i < 2048; i += 512) {
            int m = i >> 4, w = i & 15;
            int k = k0 + 2 * w;
            const float* ar = A + (size_t)(m0 + m) * K;
            float x0 = (k < K) ? ar[k] : 0.f;
            float x1 = (k + 1 < K) ? ar[k + 1] : 0.f;
            uint32_t hi = cvt2bf(x1, x0);
            float h0 = __uint_as_float(hi << 16);
            float h1 = __uint_as_float(hi & 0xFFFF0000u);
            uint32_t lo = cvt2bf(x1 - h1, x0 - h0);
            sAhi[m * GASTR + w] = hi;
            sAlo[m * GASTR + w] = lo;
        }
        // B: 16 k-pair rows x 128 n
        for (int i = tid; i < 2048; i += 512) {
            int kp = i >> 7, n = i & 127;
            int k = k0 + 2 * kp;
            int nn = n0 + n;
            float x0 = (k < K && nn < N) ? B[(size_t)k * N + nn] : 0.f;
            float x1 = (k + 1 < K && nn < N) ? B[(size_t)(k + 1) * N + nn] : 0.f;
            uint32_t hi = cvt2bf(x1, x0);
            float h0 = __uint_as_float(hi << 16);
            float h1 = __uint_as_float(hi & 0xFFFF0000u);
            uint32_t lo = cvt2bf(x1 - h1, x0 - h0);
            sBhi[kp * GBSTR + n] = hi;
            sBlo[kp * GBSTR + n] = lo;
        }
        __syncthreads();

#pragma unroll 1
        for (int pass = 0; pass < 3; pass++) {
            const uint32_t* Aarr = (pass == 2) ? sAlo : sAhi;
            const uint32_t* Barr = (pass == 1) ? sBlo : sBhi;
#pragma unroll
            for (int ks = 0; ks < 2; ks++) {
                int icb = ks * 8;
                uint32_t Af[8], Bf[8];
#pragma unroll
                for (int s = 0; s < 2; s++) {
                    const uint32_t* Ap = Aarr + (wm + s * 16 + q) * GASTR + icb + c;
                    Af[s * 4 + 0] = Ap[0];
                    Af[s * 4 + 1] = Ap[8 * GASTR];
                    Af[s * 4 + 2] = Ap[4];
                    Af[s * 4 + 3] = Ap[8 * GASTR + 4];
                }
                const uint32_t* Bp = Barr + (icb + c) * GBSTR + wn + q;
#pragma unroll
                for (int o = 0; o < 4; o++) {
                    Bf[2 * o]     = Bp[o * 8];
                    Bf[2 * o + 1] = Bp[4 * GBSTR + o * 8];
                }
#pragma unroll
                for (int o = 0; o < 4; o++) {
                    mma_bf16(acc[0][o], Af + 0, Bf[2 * o], Bf[2 * o + 1]);
                    mma_bf16(acc[1][o], Af + 4, Bf[2 * o], Bf[2 * o + 1]);
                }
            }
        }
        __syncthreads();
    }

#pragma unroll
    for (int s = 0; s < 2; s++) {
#pragma unroll
        for (int half = 0; half < 2; half++) {
            int row = m0 + wm + s * 16 + q + half * 8;
            float* crow = C + (size_t)row * N;
#pragma unroll
            for (int o = 0; o < 4; o++) {
                int col = n0 + wn + o * 8 + c * 2;
                if (col < N)
                    *(float2*)(crow + col) =
                        make_float2(acc[s][o][half * 2 + 0], acc[s][o][half * 2 + 1]);
            }
        }
    }
}

__global__ void k_wloss(const float* __restrict__ W, float* __restrict__ C)
{
    __shared__ float sA[16][17];
    __shared__ float sB[16][17];
    int tx = threadIdx.x, ty = threadIdx.y;
    int i0 = blockIdx.y * 16, j0 = blockIdx.x * 16;
    float acc = 0.f;
    for (int k0 = 0; k0 < 800; k0 += 16) {
        sA[ty][tx] = (i0 + ty < MM) ? W[(size_t)(i0 + ty) * NN + k0 + tx] : 0.f;
        sB[ty][tx] = (j0 + ty < MM) ? W[(size_t)(j0 + ty) * NN + k0 + tx] : 0.f;
        __syncthreads();
#pragma unroll
        for (int kk = 0; kk < 16; kk++) acc += sA[ty][kk] * sB[tx][kk];
        __syncthreads();
    }
    int i = i0 + ty, j = j0 + tx;
    if (i < MM && j < MM) C[i * MM + j] = acc - (i == j ? 1.f : 0.f);
}

// ---------------- elementwise ----------------

__global__ void k_layer0(const float* __restrict__ PhiTb, float* __restrict__ X1,
                         float* __restrict__ zf,
                         const float* __restrict__ h_arr, const float* __restrict__ b2_arr)
{
    int i = blockIdx.x * blockDim.x + threadIdx.x;
    if (i >= NB) return;
    float h0 = h_arr[0], b2 = b2_arr[0];
    float x = h0 * PhiTb[i];
    X1[i] = x;
    zf[i] = h0 * b2 * x;
}

__global__ void k_hatx(const float* __restrict__ Xc, const float* __restrict__ Xp,
                       float* __restrict__ hx,
                       const float* __restrict__ tx_arr, int layer)
{
    int i = blockIdx.x * blockDim.x + threadIdx.x;
    if (i >= NB) return;
    float t = tx_arr[layer];
    float xc = Xc[i];
    hx[i] = xc + t * (xc - Xp[i]);
}

__global__ void k_xepi(const float* __restrict__ hx, const float* __restrict__ gm,
                       const float* __restrict__ PhiTb,
                       const float* __restrict__ Zg, const float* __restrict__ Lg,
                       const float* __restrict__ Zc, const float* __restrict__ Zp,
                       const float* __restrict__ Lz,
                       float* __restrict__ Xn, float* __restrict__ zf,
                       const float* __restrict__ b1a, const float* __restrict__ b2a,
                       const float* __restrict__ ha, const float* __restrict__ tza,
                       int layer)
{
    int i = blockIdx.x * blockDim.x + threadIdx.x;
    if (i >= NB) return;
    float b1 = b1a[layer], b2 = b2a[layer], hh = ha[layer], tz = tza[layer];
    float hxv = hx[i];
    float grad = PhiTb[i] - gm[i] + b1 * (Zg[i] - hxv) - Lg[i];
    float xn = hxv + hh * grad;
    Xn[i] = xn;
    float zc = Zc[i];
    float hz = zc + tz * (zc - Zp[i]);
    zf[i] = hz + hh * (Lz[i] + b2 * (xn - hz));
}

// ---------------- fused prep: zero NHWC padding rows + pack bf16 weights ----

__global__ __launch_bounds__(128) void k_prep(float* __restrict__ b,
                                              const float* __restrict__ c2f,
                                              const float* __restrict__ c1b,
                                              uint32_t* __restrict__ wpk)
{
    int t = threadIdx.x;
    if (blockIdx.x < BB) {
        int img = blockIdx.x;
        int row;
        if (t < 44) row = t;
        else if (t < 88) row = 924 + (t - 44);
        else { int j = t - 88; row = (1 + (j >> 1)) * 44 + ((j & 1) ? 43 : 0); }
        float4 z = make_float4(0.f, 0.f, 0.f, 0.f);
        float4* pb = (float4*)(b + (size_t)img * NHWC_STRIDE + row * 32);
#pragma unroll
        for (int q = 0; q < 8; q++) pb[q] = z;
    } else {
        int base = (blockIdx.x - BB) * 128 + t;
        for (int i = base; i < 2 * BWORDS; i += WBF_BLOCKS * 128) {
            int set = i / BWORDS, rem = i - set * BWORDS;
            int tap = rem / (16 * BSTRIDE), rem2 = rem - tap * (16 * BSTRIDE);
            int icp = rem2 / BSTRIDE, oc = rem2 - icp * BSTRIDE;
            const float* src = set ? c1b : c2f;
            uint32_t whi = 0u, wlo = 0u;
            if (oc < 32) {
                float w0 = src[oc * 288 + (2 * icp) * 9 + tap];
                float w1 = src[oc * 288 + (2 * icp + 1) * 9 + tap];
                __nv_bfloat16 h0 = __float2bfloat16_rn(w0), h1 = __float2bfloat16_rn(w1);
                __nv_bfloat16 l0 = __float2bfloat16_rn(w0 - __bfloat162float(h0));
                __nv_bfloat16 l1 = __float2bfloat16_rn(w1 - __bfloat162float(h1));
                whi = pkbf2(h0, h1);
                wlo = pkbf2(l0, l1);
            }
            int off = tap * (16 * BSTRIDE) + icp * BSTRIDE + oc;
            wpk[set * 2 * BWORDS + off] = whi;
            wpk[set * 2 * BWORDS + BWORDS + off] = wlo;
        }
    }
}

// ---------------- conv kernels ----------------

// x_fwd: fused 1->32 conv (from 800-float zf, relu) + 32->32 mma conv (no relu).
// Writes NHWC fp32 to gmem (consumed twice by t1t2). 512 threads.
__global__ __launch_bounds__(512) void conv32_fwd(const uint32_t* __restrict__ wpk,
                                                  float* __restrict__ outp,
                                                  const float* __restrict__ w1,
                                                  const float* __restrict__ zf_in)
{
    extern __shared__ uint32_t smw[];
    uint32_t* sAhi = smw;                       // SROWS*ASTRIDE
    uint32_t* sAlo = smw + SROWS * ASTRIDE;
    uint32_t* sBhi = smw + 2 * SROWS * ASTRIDE; // BWORDS
    uint32_t* sBlo = sBhi + BWORDS;
    float* sZf = (float*)(sBlo + BWORDS);       // NROWS
    float* sW1 = sZf + NROWS;                   // 288
    int img = blockIdx.x, tid = threadIdx.x;

    for (int i = tid; i < 48 * ASTRIDE; i += 512) { sAhi[i] = 0u; sAlo[i] = 0u; }
    for (int i = tid; i < 70 * ASTRIDE; i += 512) {
        sAhi[1016 * ASTRIDE + i] = 0u; sAlo[1016 * ASTRIDE + i] = 0u;
    }
    for (int i = tid; i < BWORDS; i += 512) { sBhi[i] = wpk[i]; sBlo[i] = wpk[BWORDS + i]; }

    // zero all data rows, stage zf + 1->32 weights
    uint4 z4 = make_uint4(0u, 0u, 0u, 0u);
    for (int i = tid; i < NROWS * 4 * 2; i += 512) {
        int arr = (i >= NROWS * 4);
        int j = arr ? i - NROWS * 4 : i;
        int row = j >> 2, qq = j & 3;
        uint32_t* basep = (arr ? sAlo : sAhi) + (SROW0 + row) * ASTRIDE + qq * 4;
        *(uint4*)basep = z4;
    }
    for (int i = tid; i < NROWS; i += 512) sZf[i] = 0.f;
    for (int i = tid; i < 288; i += 512) {
        int oc = i / 9, tap = i - oc * 9;
        sW1[tap * 32 + oc] = w1[i];
    }
    __syncthreads();
    const float* gz = zf_in + (size_t)img * NN;
    for (int i = tid; i < NN; i += 512) {
        int r = i / 40, c0 = i - r * 40;
        sZf[(r + 1) * 44 + c0 + 1] = gz[i];
    }
    __syncthreads();
    for (int i = tid; i < NN * 16; i += 512) {
        int px = i >> 4, qq = i & 15;
        int r = px / 40, c0 = px - r * 40;
        int pp = (r + 1) * 44 + (c0 + 1);
        float a0 = 0.f, a1 = 0.f;
#pragma unroll
        for (int t = 0; t < 9; t++) {
            float zv = sZf[pp + c_dtap[t]];
            a0 += sW1[t * 32 + 2 * qq] * zv;
            a1 += sW1[t * 32 + 2 * qq + 1] * zv;
        }
        a0 = fmaxf(a0, 0.f);
        a1 = fmaxf(a1, 0.f);
        uint32_t hi = cvt2bf(a1, a0);
        float h0 = __uint_as_float(hi << 16);
        float h1 = __uint_as_float(hi & 0xFFFF0000u);
        uint32_t lo = cvt2bf(a1 - h1, a0 - h0);
        int base = (SROW0 + pp) * ASTRIDE + qq;
        sAhi[base] = hi;
        sAlo[base] = lo;
    }
    __syncthreads();

    int warp = tid >> 5, lane = tid & 31;
    int q = lane >> 2, c = lane & 3;
    float* gout = outp + (size_t)img * NHWC_STRIDE;

    int u1 = warp, u2 = warp + 16;
    bool has2 = (u2 < 31);
    int r1 = SROW0 + u1 * 32;
    int r2 = SROW0 + (has2 ? u2 : u1) * 32;

    float acc1[2][4][4], acc2[2][4][4];
    conv_mma_loop(sAhi, sAlo, sBhi, sBlo, r1, r2, has2, q, c, acc1, acc2);

#pragma unroll
    for (int uu = 0; uu < 2; uu++) {
        if (uu == 1 && !has2) break;
        int u = uu ? u2 : u1;
        float (*acc)[4][4] = uu ? acc2 : acc1;
#pragma unroll
        for (int s = 0; s < 2; s++) {
            int grow0 = u * 32 + s * 16 + q;
#pragma unroll
            for (int half = 0; half < 2; half++) {
                int grow = grow0 + half * 8;
                int rr = grow / 44, cc = grow - rr * 44;
                bool valid = (grow < NROWS) && rr >= 1 && rr <= 20 && cc >= 1 && cc <= 40;
                if (valid) {
                    float* ob = gout + grow * 32 + c * 2;
#pragma unroll
                    for (int o = 0; o < 4; o++) {
                        float x0 = acc[s][o][half * 2 + 0];
                        float x1 = acc[s][o][half * 2 + 1];
                        *(float2*)(ob + o * 8) = make_float2(x0, x1);
                    }
                }
            }
        }
    }
}

// t1 + t2 fused: reads x_fwd twice (2nd read L2-hot).
// t1: soft + 32->32 mma + relu -> sOut -> 32->1 -> Zs + L-update.
// t2: 32->32 mma + relu -> sOut -> 32->1 - zf -> syms.
__global__ __launch_bounds__(512) void conv32_t1t2(const float* __restrict__ in,
                                                   const uint32_t* __restrict__ wpk,
                                                   const float* __restrict__ thr_arr,
                                                   int layer,
                                                   float* __restrict__ Zout,
                                                   float* __restrict__ Sout,
                                                   const float* __restrict__ zf,
                                                   float* __restrict__ Ln,
                                                   const float* __restrict__ Lc,
                                                   const float* __restrict__ Lp,
                                                   const float* __restrict__ Xn,
                                                   const float* __restrict__ h_arr,
                                                   const float* __restrict__ b1_arr,
                                                   const float* __restrict__ tL_arr,
                                                   const float* __restrict__ w288)
{
    extern __shared__ uint32_t smw[];
    uint32_t* sAhi = smw;
    uint32_t* sAlo = smw + SROWS * ASTRIDE;
    uint32_t* sBhi = smw + 2 * SROWS * ASTRIDE;
    uint32_t* sBlo = sBhi + BWORDS;
    float* sWc = (float*)(sBlo + BWORDS);       // 288 ([tap][ic])
    float* sOut = (float*)smw;                  // overlays A region after mma
    int img = blockIdx.x, tid = threadIdx.x;

    for (int i = tid; i < 48 * ASTRIDE; i += 512) { sAhi[i] = 0u; sAlo[i] = 0u; }
    for (int i = tid; i < 70 * ASTRIDE; i += 512) {
        sAhi[1016 * ASTRIDE + i] = 0u; sAlo[1016 * ASTRIDE + i] = 0u;
    }
    for (int i = tid; i < BWORDS; i += 512) { sBhi[i] = wpk[i]; sBlo[i] = wpk[BWORDS + i]; }
    for (int i = tid; i < 288; i += 512) {
        int ic = i / 9, tap = i - ic * 9;
        sWc[tap * 32 + ic] = w288[i];
    }

    float sthr = fabsf(thr_arr[layer]);
    conv_fill_A(sAhi, sAlo, in, img, tid, 1, sthr);
    __syncthreads();

    int warp = tid >> 5, lane = tid & 31;
    int q = lane >> 2, c = lane & 3;
    int u1 = warp, u2 = warp + 16;
    bool has2 = (u2 < 31);
    int r1 = SROW0 + u1 * 32;
    int r2 = SROW0 + (has2 ? u2 : u1) * 32;
    size_t base = (size_t)img * NN;

    float acc1[2][4][4], acc2[2][4][4];

    // ============ t1 ============
    conv_mma_loop(sAhi, sAlo, sBhi, sBlo, r1, r2, has2, q, c, acc1, acc2);
    __syncthreads();  // done reading sA

    {
        float4 z = make_float4(0.f, 0.f, 0.f, 0.f);
        for (int i = tid; i < NROWS * 9; i += 512) ((float4*)sOut)[i] = z;
    }
    __syncthreads();
    conv_epi_smem(sOut, acc1, acc2, u1, u2, has2, q, c);
    __syncthreads();

    for (int p = tid; p < NN; p += 512) {
        int r = p / 40, c0 = p - r * 40;
        int pp = (r + 1) * 44 + (c0 + 1);
        float acc = 0.f;
#pragma unroll
        for (int t = 0; t < 9; t++) {
            const float4* a4 = (const float4*)(sOut + (pp + c_dtap[t]) * SOSTRIDE);
            const float4* wv = (const float4*)(sWc + t * 32);
#pragma unroll
            for (int qq = 0; qq < 8; qq++) {
                float4 x = a4[qq], ww = wv[qq];
                acc += x.x * ww.x + x.y * ww.y + x.z * ww.z + x.w * ww.w;
            }
        }
        Zout[base + p] = acc;
        float lc = Lc[base + p], lp = Lp[base + p];
        float hatL = lc + tL_arr[layer] * (lc - lp);
        Ln[base + p] = hatL + h_arr[layer] * b1_arr[layer] * (Xn[base + p] - acc);
    }
    __syncthreads();  // all reads of sOut done before refill

    // ============ t2 ============
    conv_fill_A(sAhi, sAlo, in, img, tid, 0, 0.f);
    __syncthreads();

    conv_mma_loop(sAhi, sAlo, sBhi, sBlo, r1, r2, has2, q, c, acc1, acc2);
    __syncthreads();

    {
        float4 z = make_float4(0.f, 0.f, 0.f, 0.f);
        for (int i = tid; i < NROWS * 9; i += 512) ((float4*)sOut)[i] = z;
    }
    __syncthreads();
    conv_epi_smem(sOut, acc1, acc2, u1, u2, has2, q, c);
    __syncthreads();

    for (int p = tid; p < NN; p += 512) {
        int r = p / 40, c0 = p - r * 40;
        int pp = (r + 1) * 44 + (c0 + 1);
        float acc = 0.f;
#pragma unroll
        for (int t = 0; t < 9; t++) {
            const float4* a4 = (const float4*)(sOut + (pp + c_dtap[t]) * SOSTRIDE);
            const float4* wv = (const float4*)(sWc + t * 32);
#pragma unroll
            for (int qq = 0; qq < 8; qq++) {
                float4 x = a4[qq], ww = wv[qq];
                acc += x.x * ww.x + x.y * ww.y + x.z * ww.z + x.w * ww.w;
            }
        }
        Sout[base + p] = acc - zf[base + p];
    }
}

// ---------------- host ----------------

extern "C" void kernel_launch(void* const* d_in, const int* in_sizes, int n_in,
                              void* d_out, int out_size)
{
    const float* y    = (const float*)d_in[0];
    const float* W    = (const float*)d_in[2];
    const float* beta1 = (const float*)d_in[3];
    const float* beta2 = (const float*)d_in[4];
    const float* h_   = (const float*)d_in[5];
    const float* sthr = (const float*)d_in[6];
    const float* thx  = (const float*)d_in[7];
    const float* thz  = (const float*)d_in[8];
    const float* thL  = (const float*)d_in[9];
    const float* c1f  = (const float*)d_in[10];
    const float* c2f  = (const float*)d_in[11];
    const float* c1b  = (const float*)d_in[12];
    const float* c2b  = (const float*)d_in[13];

    float* out = (float*)d_out;
    float* Zs = out;
    float* syms = out + (size_t)9 * NB;
    float* wlo = out + (size_t)18 * NB;

    float *pPhiTPhi, *pPhiTb, *pX, *pL, *pZero, *pZf, *pHx, *pGm, *pNB;
    uint32_t* pWPK;
    cudaGetSymbolAddress((void**)&pPhiTPhi, g_PhiTPhi);
    cudaGetSymbolAddress((void**)&pPhiTb, g_PhiTb);
    cudaGetSymbolAddress((void**)&pX, g_Xbuf);
    cudaGetSymbolAddress((void**)&pL, g_Lbuf);
    cudaGetSymbolAddress((void**)&pZero, g_zerobuf);
    cudaGetSymbolAddress((void**)&pZf, g_zflat);
    cudaGetSymbolAddress((void**)&pHx, g_hatx);
    cudaGetSymbolAddress((void**)&pGm, g_gemm);
    cudaGetSymbolAddress((void**)&pNB, g_nB);
    cudaGetSymbolAddress((void**)&pWPK, g_wpk);

    const int SMMAW = (2 * SROWS * ASTRIDE + 2 * BWORDS + NROWS + 288) * 4;  // 224,864 B
    cudaFuncSetAttribute(conv32_fwd, cudaFuncAttributeMaxDynamicSharedMemorySize, SMMAW);
    cudaFuncSetAttribute(conv32_t1t2, cudaFuncAttributeMaxDynamicSharedMemorySize, SMMAW);

    cudaMemsetAsync(pZero, 0, (size_t)NB * 4);

    float* Xslot[2] = {pX, pX + NB};
    float* Lslot[2] = {pL, pL + NB};

    k_prep<<<BB + WBF_BLOCKS, 128>>>(pNB, c2f, c1b, pWPK);
    gemm_mma<<<dim3(7, 32), 512>>>(y, W, pPhiTb, BB, MM, NN);

    int xcur = 0, xprev = -1;
    int lcur = 0, lprev = -1;

    for (int i = 0; i < 9; i++) {
        float* Xn;
        if (i == 0) {
            Xn = Xslot[0];
            k_layer0<<<NB / 256, 256>>>(pPhiTb, Xn, pZf, h_, beta2);
            xcur = 0; xprev = -1;
        } else {
            const float* Xc = Xslot[xcur];
            const float* Xp = (xprev < 0) ? pZero : Xslot[xprev];
            const float* Lc_ = Lslot[lcur];
            const float* Zc = Zs + (size_t)(i - 1) * NB;
            const float* Zp = (i >= 2) ? Zs + (size_t)(i - 2) * NB : pZero;
            const float* Zg = (i >= 2) ? Zc : pZero;
            const float* Lg = (i >= 2) ? Lc_ : pZero;
            const float* Lz = (i >= 2) ? Lc_ : pZero;
            int xnew = (xprev < 0) ? 1 : xprev;
            Xn = Xslot[xnew];
            k_hatx<<<NB / 256, 256>>>(Xc, Xp, pHx, thx, i);
            gemm_mma<<<dim3(7, 32), 512>>>(pHx, pPhiTPhi, pGm, BB, NN, NN);
            k_xepi<<<NB / 256, 256>>>(pHx, pGm, pPhiTb, Zg, Lg, Zc, Zp, Lz,
                                      Xn, pZf, beta1, beta2, h_, thz, i);
            xprev = xcur; xcur = xnew;
        }

        // x_fwd: fused 1->32 + 32->32 mma conv -> NHWC gmem
        conv32_fwd<<<BB, 512, SMMAW>>>(pWPK, pNB, c1f, pZf);

        // t1 (Zs + L) and t2 (syms) in one kernel
        {
            const float* Lc_ = (i == 0) ? pZero : Lslot[lcur];
            const float* Lp_ = (i == 0) ? pZero : ((lprev < 0) ? pZero : Lslot[lprev]);
            int lnew = (i == 0) ? 0 : ((lprev < 0) ? 1 : lprev);
            conv32_t1t2<<<BB, 512, SMMAW>>>(pNB, pWPK + 2 * BWORDS, sthr, i,
                                            Zs + (size_t)i * NB,
                                            syms + (size_t)i * NB, pZf,
                                            Lslot[lnew], Lc_, Lp_, Xn,
                                            h_, beta1, thL, c2b);
            if (i > 0) { lprev = lcur; lcur = lnew; }
            else { lcur = 0; lprev = -1; }
        }

        if (i == 0) {
            gemm_AtB<<<dim3(13, 13), 256>>>(W, W, pPhiTPhi, MM, NN, NN);
        }
    }

    k_wloss<<<dim3(21, 21), dim3(16, 16)>>>(W, wlo);
}

// round 15
// speedup vs baseline: 2.8553x; 1.0430x over previous
#include <cuda_runtime.h>
#include <cuda_bf16.h>
#include <cstdint>

#define BB 4096
#define MM 327
#define NN 800
#define NB (BB*NN)              // 3,276,800 per state buffer
#define NROWS 968               // 22*44 padded pixel rows
#define XSTRIDE (NROWS*16)      // packed bf16x2 words per image (15488)
#define SROW0 48
#define SROWS 1086              // 48 guard + 968 data + 70 guard rows
#define ASTRIDE 20              // words per row in smem A ({20q+c} distinct mod 32)
#define BSTRIDE 40              // words per icpair in smem B ({40c+q} distinct mod 32)
#define BWORDS (9*16*BSTRIDE)   // 5760 words per (set,half)
#define WBF_BLOCKS 46
#define SOSTRIDE 36             // fp32 out rows in smem (mult of 4 for float4)

// gemm tile params
#define GASTR 20
#define GBSTR 136               // 128 + 8; conflict-free

typedef unsigned long long ull;

// ---------------- device scratch (static, allowed; zero-initialized) ----------
__device__ float g_PhiTPhi[NN*NN];
__device__ float g_PhiTb[NB];
__device__ float g_Xbuf[3*NB];                   // 3-slot X rotation
__device__ float g_Lbuf[2*NB];
__device__ float g_zerobuf[NB];
__device__ float g_zflat[NB];
__device__ uint32_t g_xh[(size_t)BB*XSTRIDE];    // x_fwd bf16-hi words (pads stay 0)
__device__ uint32_t g_xl[(size_t)BB*XSTRIDE];    // x_fwd bf16-lo words
__device__ uint32_t g_wpk[2*2*BWORDS];           // [set][hi/lo][BWORDS] packed bf16x2

__constant__ int c_dtap[9] = {-45, -44, -43, -1, 0, 1, 43, 44, 45};

// ---------------- helpers ----------------
__device__ __forceinline__ uint32_t pkbf2(__nv_bfloat16 e0, __nv_bfloat16 e1) {
    return ((uint32_t)__bfloat16_as_ushort(e1) << 16) | (uint32_t)__bfloat16_as_ushort(e0);
}
__device__ __forceinline__ uint32_t cvt2bf(float hi, float lo) {
    uint32_t r;
    asm("cvt.rn.satfinite.bf16x2.f32 %0, %1, %2;" : "=r"(r) : "f"(hi), "f"(lo));
    return r;
}

__device__ __forceinline__ void mma_bf16(float* d, const uint32_t* a, uint32_t b0, uint32_t b1) {
    asm volatile(
        "mma.sync.aligned.m16n8k16.row.col.f32.bf16.bf16.f32 "
        "{%0,%1,%2,%3}, {%4,%5,%6,%7}, {%8,%9}, {%0,%1,%2,%3};"
        : "+f"(d[0]), "+f"(d[1]), "+f"(d[2]), "+f"(d[3])
        : "r"(a[0]), "r"(a[1]), "r"(a[2]), "r"(a[3]), "r"(b0), "r"(b1));
}

__device__ __forceinline__ void ldAfrag(uint32_t* a, const uint32_t* Aarr, int baserow,
                                        int ks, int q, int c) {
    int tap = ks >> 1, icb = (ks & 1) * 8;
    const uint32_t* Ap = Aarr + (baserow + c_dtap[tap] + q) * ASTRIDE + icb + c;
    a[0] = Ap[0];
    a[1] = Ap[8 * ASTRIDE];
    a[2] = Ap[4];
    a[3] = Ap[8 * ASTRIDE + 4];
    a[4] = Ap[16 * ASTRIDE];
    a[5] = Ap[24 * ASTRIDE];
    a[6] = Ap[16 * ASTRIDE + 4];
    a[7] = Ap[24 * ASTRIDE + 4];
}
__device__ __forceinline__ void ldBfrag(uint32_t* b, const uint32_t* Barr,
                                        int ks, int q, int c) {
    int tap = ks >> 1, icb = (ks & 1) * 8;
    const uint32_t* Bp = Barr + tap * (16 * BSTRIDE) + (icb + c) * BSTRIDE + q;
#pragma unroll
    for (int o = 0; o < 4; o++) {
        b[2 * o]     = Bp[o * 8];
        b[2 * o + 1] = Bp[4 * BSTRIDE + o * 8];
    }
}

// shared mma mainloop for the conv kernels (2 units per warp sharing B)
__device__ __forceinline__ void conv_mma_loop(const uint32_t* sAhi, const uint32_t* sAlo,
                                              const uint32_t* sBhi, const uint32_t* sBlo,
                                              int r1, int r2, bool has2, int q, int c,
                                              float acc1[2][4][4], float acc2[2][4][4])
{
#pragma unroll
    for (int s = 0; s < 2; s++)
#pragma unroll
        for (int o = 0; o < 4; o++)
#pragma unroll
            for (int j = 0; j < 4; j++) { acc1[s][o][j] = 0.f; acc2[s][o][j] = 0.f; }

#pragma unroll 1
    for (int pass = 0; pass < 3; pass++) {
        const uint32_t* Aarr = (pass == 2) ? sAlo : sAhi;
        const uint32_t* Barr = (pass == 1) ? sBlo : sBhi;
#pragma unroll
        for (int ks = 0; ks < 18; ks++) {
            uint32_t Af1[8], Af2[8], Bf[8];
            ldAfrag(Af1, Aarr, r1, ks, q, c);
            if (has2) ldAfrag(Af2, Aarr, r2, ks, q, c);
            ldBfrag(Bf, Barr, ks, q, c);
#pragma unroll
            for (int o = 0; o < 4; o++) {
                uint32_t b0 = Bf[2 * o], b1 = Bf[2 * o + 1];
                mma_bf16(acc1[0][o], Af1 + 0, b0, b1);
                mma_bf16(acc1[1][o], Af1 + 4, b0, b1);
                if (has2) {
                    mma_bf16(acc2[0][o], Af2 + 0, b0, b1);
                    mma_bf16(acc2[1][o], Af2 + 4, b0, b1);
                }
            }
        }
    }
}

// fill sA from pre-split gmem words. do_soft=1: reconstruct, soft, resplit.
__device__ __forceinline__ void fill_from_split(uint32_t* sAhi, uint32_t* sAlo,
                                                const uint32_t* xh, const uint32_t* xl,
                                                int img, int tid, int do_soft, float sthr)
{
    const uint4* gh = (const uint4*)(xh + (size_t)img * XSTRIDE);
    const uint4* gl = (const uint4*)(xl + (size_t)img * XSTRIDE);
    for (int i = tid; i < NROWS * 4; i += 512) {
        uint4 h = gh[i];
        uint4 l = gl[i];
        if (do_soft) {
#pragma unroll
            for (int w = 0; w < 4; w++) {
                uint32_t hw = (&h.x)[w], lw = (&l.x)[w];
                float x0 = __uint_as_float(hw << 16) + __uint_as_float(lw << 16);
                float x1 = __uint_as_float(hw & 0xFFFF0000u) + __uint_as_float(lw & 0xFFFF0000u);
                float a0 = fabsf(x0) - sthr;
                x0 = (a0 > 0.f) ? (x0 > 0.f ? a0 : -a0) : 0.f;
                float a1 = fabsf(x1) - sthr;
                x1 = (a1 > 0.f) ? (x1 > 0.f ? a1 : -a1) : 0.f;
                uint32_t nh = cvt2bf(x1, x0);
                (&h.x)[w] = nh;
                (&l.x)[w] = cvt2bf(x1 - __uint_as_float(nh & 0xFFFF0000u),
                                   x0 - __uint_as_float(nh << 16));
            }
        }
        int row = i >> 2, j = i & 3;
        int base = (SROW0 + row) * ASTRIDE + 4 * j;
        *(uint4*)(sAhi + base) = h;
        *(uint4*)(sAlo + base) = l;
    }
}

// epilogue to smem fp32 (relu) at SOSTRIDE
__device__ __forceinline__ void conv_epi_smem(float* sOut, float acc1[2][4][4],
                                              float acc2[2][4][4], int u1, int u2,
                                              bool has2, int q, int c)
{
#pragma unroll
    for (int uu = 0; uu < 2; uu++) {
        if (uu == 1 && !has2) break;
        int u = uu ? u2 : u1;
        float (*acc)[4][4] = uu ? acc2 : acc1;
#pragma unroll
        for (int s = 0; s < 2; s++) {
            int grow0 = u * 32 + s * 16 + q;
#pragma unroll
            for (int half = 0; half < 2; half++) {
                int grow = grow0 + half * 8;
                int rr = grow / 44, cc = grow - rr * 44;
                bool valid = (grow < NROWS) && rr >= 1 && rr <= 20 && cc >= 1 && cc <= 40;
                if (valid) {
                    float* ob = sOut + grow * SOSTRIDE + c * 2;
#pragma unroll
                    for (int o = 0; o < 4; o++) {
                        float x0 = fmaxf(acc[s][o][half * 2 + 0], 0.f);
                        float x1 = fmaxf(acc[s][o][half * 2 + 1], 0.f);
                        *(float2*)(ob + o * 8) = make_float2(x0, x1);
                    }
                }
            }
        }
    }
}

// ---------------- GEMMs ----------------

__global__ __launch_bounds__(256) void gemm_AtB(const float* __restrict__ A,
                                                const float* __restrict__ B,
                                                float* __restrict__ C,
                                                int K, int I, int J)
{
    __shared__ float As[16][68];
    __shared__ float Bs[16][68];
    int tid = threadIdx.x;
    int tx = tid & 15, ty = tid >> 4;
    int i0 = blockIdx.y * 64, j0 = blockIdx.x * 64;
    float acc[4][4];
#pragma unroll
    for (int a = 0; a < 4; a++)
#pragma unroll
        for (int b = 0; b < 4; b++) acc[a][b] = 0.f;

    int kr = tid >> 4, c4 = (tid & 15) * 4;
    for (int k0 = 0; k0 < K; k0 += 16) {
        bool kv = (k0 + kr) < K;
#pragma unroll
        for (int j = 0; j < 4; j++) {
            int ii = i0 + c4 + j;
            As[kr][c4 + j] = (kv && ii < I) ? A[(size_t)(k0 + kr) * I + ii] : 0.f;
            int jj = j0 + c4 + j;
            Bs[kr][c4 + j] = (kv && jj < J) ? B[(size_t)(k0 + kr) * J + jj] : 0.f;
        }
        __syncthreads();
#pragma unroll
        for (int kk = 0; kk < 16; kk++) {
            float a[4], b[4];
#pragma unroll
            for (int i = 0; i < 4; i++) a[i] = As[kk][ty * 4 + i];
#pragma unroll
            for (int j = 0; j < 4; j++) b[j] = Bs[kk][tx * 4 + j];
#pragma unroll
            for (int i = 0; i < 4; i++)
#pragma unroll
                for (int j = 0; j < 4; j++) acc[i][j] += a[i] * b[j];
        }
        __syncthreads();
    }
#pragma unroll
    for (int i = 0; i < 4; i++) {
        int r = i0 + ty * 4 + i;
        if (r < I) {
#pragma unroll
            for (int j = 0; j < 4; j++) {
                int n = j0 + tx * 4 + j;
                if (n < J) C[(size_t)r * J + n] = acc[i][j];
            }
        }
    }
}

// bf16 3-pass split GEMM: C[M,N] = A[M,K] * B[K,N], fp32 in/out.
__global__ __launch_bounds__(512) void gemm_mma(const float* __restrict__ A,
                                                const float* __restrict__ B,
                                                float* __restrict__ C,
                                                int M, int K, int N)
{
    __shared__ uint32_t sAhi[128 * GASTR];
    __shared__ uint32_t sAlo[128 * GASTR];
    __shared__ uint32_t sBhi[16 * GBSTR];
    __shared__ uint32_t sBlo[16 * GBSTR];

    int tid = threadIdx.x;
    int warp = tid >> 5, lane = tid & 31;
    int q = lane >> 2, c = lane & 3;
    int m0 = blockIdx.y * 128, n0 = blockIdx.x * 128;
    int wm = (warp >> 2) * 32, wn = (warp & 3) * 32;

    float acc[2][4][4];
#pragma unroll
    for (int s = 0; s < 2; s++)
#pragma unroll
        for (int o = 0; o < 4; o++)
#pragma unroll
            for (int j = 0; j < 4; j++) acc[s][o][j] = 0.f;

    for (int k0 = 0; k0 < K; k0 += 32) {
        for (int i = tid; i < 2048; i += 512) {
            int m = i >> 4, w = i & 15;
            int k = k0 + 2 * w;
            const float* ar = A + (size_t)(m0 + m) * K;
            float x0 = (k < K) ? ar[k] : 0.f;
            float x1 = (k + 1 < K) ? ar[k + 1] : 0.f;
            uint32_t hi = cvt2bf(x1, x0);
            float h0 = __uint_as_float(hi << 16);
            float h1 = __uint_as_float(hi & 0xFFFF0000u);
            uint32_t lo = cvt2bf(x1 - h1, x0 - h0);
            sAhi[m * GASTR + w] = hi;
            sAlo[m * GASTR + w] = lo;
        }
        for (int i = tid; i < 2048; i += 512) {
            int kp = i >> 7, n = i & 127;
            int k = k0 + 2 * kp;
            int nn = n0 + n;
            float x0 = (k < K && nn < N) ? B[(size_t)k * N + nn] : 0.f;
            float x1 = (k + 1 < K && nn < N) ? B[(size_t)(k + 1) * N + nn] : 0.f;
            uint32_t hi = cvt2bf(x1, x0);
            float h0 = __uint_as_float(hi << 16);
            float h1 = __uint_as_float(hi & 0xFFFF0000u);
            uint32_t lo = cvt2bf(x1 - h1, x0 - h0);
            sBhi[kp * GBSTR + n] = hi;
            sBlo[kp * GBSTR + n] = lo;
        }
        __syncthreads();

#pragma unroll 1
        for (int pass = 0; pass < 3; pass++) {
            const uint32_t* Aarr = (pass == 2) ? sAlo : sAhi;
            const uint32_t* Barr = (pass == 1) ? sBlo : sBhi;
#pragma unroll
            for (int ks = 0; ks < 2; ks++) {
                int icb = ks * 8;
                uint32_t Af[8], Bf[8];
#pragma unroll
                for (int s = 0; s < 2; s++) {
                    const uint32_t* Ap = Aarr + (wm + s * 16 + q) * GASTR + icb + c;
                    Af[s * 4 + 0] = Ap[0];
                    Af[s * 4 + 1] = Ap[8 * GASTR];
                    Af[s * 4 + 2] = Ap[4];
                    Af[s * 4 + 3] = Ap[8 * GASTR + 4];
                }
                const uint32_t* Bp = Barr + (icb + c) * GBSTR + wn + q;
#pragma unroll
                for (int o = 0; o < 4; o++) {
                    Bf[2 * o]     = Bp[o * 8];
                    Bf[2 * o + 1] = Bp[4 * GBSTR + o * 8];
                }
#pragma unroll
                for (int o = 0; o < 4; o++) {
                    mma_bf16(acc[0][o], Af + 0, Bf[2 * o], Bf[2 * o + 1]);
                    mma_bf16(acc[1][o], Af + 4, Bf[2 * o], Bf[2 * o + 1]);
                }
            }
        }
        __syncthreads();
    }

#pragma unroll
    for (int s = 0; s < 2; s++) {
#pragma unroll
        for (int half = 0; half < 2; half++) {
            int row = m0 + wm + s * 16 + q + half * 8;
            float* crow = C + (size_t)row * N;
#pragma unroll
            for (int o = 0; o < 4; o++) {
                int col = n0 + wn + o * 8 + c * 2;
                if (col < N)
                    *(float2*)(crow + col) =
                        make_float2(acc[s][o][half * 2 + 0], acc[s][o][half * 2 + 1]);
            }
        }
    }
}

// X-step GEMM: A = hatx computed on the fly from (Xc, Xp, thx); epilogue does
// the full xepi update writing Xn and zf (no C buffer).
__global__ __launch_bounds__(512) void gemm_xstep(const float* __restrict__ Xc,
                                                  const float* __restrict__ Xp,
                                                  const float* __restrict__ B,
                                                  const float* __restrict__ PhiTb,
                                                  const float* __restrict__ Zg,
                                                  const float* __restrict__ Lg,
                                                  const float* __restrict__ Zc,
                                                  const float* __restrict__ Zp,
                                                  const float* __restrict__ Lz,
                                                  float* __restrict__ Xn,
                                                  float* __restrict__ zf,
                                                  const float* __restrict__ b1a,
                                                  const float* __restrict__ b2a,
                                                  const float* __restrict__ ha,
                                                  const float* __restrict__ tza,
                                                  const float* __restrict__ txa,
                                                  int layer)
{
    __shared__ uint32_t sAhi[128 * GASTR];
    __shared__ uint32_t sAlo[128 * GASTR];
    __shared__ uint32_t sBhi[16 * GBSTR];
    __shared__ uint32_t sBlo[16 * GBSTR];

    const int K = NN, N = NN;
    int tid = threadIdx.x;
    int warp = tid >> 5, lane = tid & 31;
    int q = lane >> 2, c = lane & 3;
    int m0 = blockIdx.y * 128, n0 = blockIdx.x * 128;
    int wm = (warp >> 2) * 32, wn = (warp & 3) * 32;
    float tx = txa[layer];

    float acc[2][4][4];
#pragma unroll
    for (int s = 0; s < 2; s++)
#pragma unroll
        for (int o = 0; o < 4; o++)
#pragma unroll
            for (int j = 0; j < 4; j++) acc[s][o][j] = 0.f;

    for (int k0 = 0; k0 < K; k0 += 32) {
        for (int i = tid; i < 2048; i += 512) {
            int m = i >> 4, w = i & 15;
            int k = k0 + 2 * w;
            size_t rb = (size_t)(m0 + m) * K;
            float x0 = 0.f, x1 = 0.f;
            if (k < K) {
                float xc = Xc[rb + k];
                x0 = xc + tx * (xc - Xp[rb + k]);
            }
            if (k + 1 < K) {
                float xc = Xc[rb + k + 1];
                x1 = xc + tx * (xc - Xp[rb + k + 1]);
            }
            uint32_t hi = cvt2bf(x1, x0);
            float h0 = __uint_as_float(hi << 16);
            float h1 = __uint_as_float(hi & 0xFFFF0000u);
            uint32_t lo = cvt2bf(x1 - h1, x0 - h0);
            sAhi[m * GASTR + w] = hi;
            sAlo[m * GASTR + w] = lo;
        }
        for (int i = tid; i < 2048; i += 512) {
            int kp = i >> 7, n = i & 127;
            int k = k0 + 2 * kp;
            int nn = n0 + n;
            float x0 = (k < K && nn < N) ? B[(size_t)k * N + nn] : 0.f;
            float x1 = (k + 1 < K && nn < N) ? B[(size_t)(k + 1) * N + nn] : 0.f;
            uint32_t hi = cvt2bf(x1, x0);
            float h0 = __uint_as_float(hi << 16);
            float h1 = __uint_as_float(hi & 0xFFFF0000u);
            uint32_t lo = cvt2bf(x1 - h1, x0 - h0);
            sBhi[kp * GBSTR + n] = hi;
            sBlo[kp * GBSTR + n] = lo;
        }
        __syncthreads();

#pragma unroll 1
        for (int pass = 0; pass < 3; pass++) {
            const uint32_t* Aarr = (pass == 2) ? sAlo : sAhi;
            const uint32_t* Barr = (pass == 1) ? sBlo : sBhi;
#pragma unroll
            for (int ks = 0; ks < 2; ks++) {
                int icb = ks * 8;
                uint32_t Af[8], Bf[8];
#pragma unroll
                for (int s = 0; s < 2; s++) {
                    const uint32_t* Ap = Aarr + (wm + s * 16 + q) * GASTR + icb + c;
                    Af[s * 4 + 0] = Ap[0];
                    Af[s * 4 + 1] = Ap[8 * GASTR];
                    Af[s * 4 + 2] = Ap[4];
                    Af[s * 4 + 3] = Ap[8 * GASTR + 4];
                }
                const uint32_t* Bp = Barr + (icb + c) * GBSTR + wn + q;
#pragma unroll
                for (int o = 0; o < 4; o++) {
                    Bf[2 * o]     = Bp[o * 8];
                    Bf[2 * o + 1] = Bp[4 * GBSTR + o * 8];
                }
#pragma unroll
                for (int o = 0; o < 4; o++) {
                    mma_bf16(acc[0][o], Af + 0, Bf[2 * o], Bf[2 * o + 1]);
                    mma_bf16(acc[1][o], Af + 4, Bf[2 * o], Bf[2 * o + 1]);
                }
            }
        }
        __syncthreads();
    }

    // fused xepi epilogue
    float b1 = b1a[layer], b2 = b2a[layer], hh = ha[layer], tz = tza[layer];
#pragma unroll
    for (int s = 0; s < 2; s++) {
#pragma unroll
        for (int half = 0; half < 2; half++) {
            int row = m0 + wm + s * 16 + q + half * 8;
            size_t rb = (size_t)row * N;
#pragma unroll
            for (int o = 0; o < 4; o++) {
                int col = n0 + wn + o * 8 + c * 2;
                if (col < N) {
                    size_t idx = rb + col;
#pragma unroll
                    for (int e = 0; e < 2; e++) {
                        size_t i2 = idx + e;
                        float gm = acc[s][o][half * 2 + e];
                        float xc = Xc[i2];
                        float hxv = xc + tx * (xc - Xp[i2]);
                        float grad = PhiTb[i2] - gm + b1 * (Zg[i2] - hxv) - Lg[i2];
                        float xn = hxv + hh * grad;
                        Xn[i2] = xn;
                        float zc = Zc[i2];
                        float hz = zc + tz * (zc - Zp[i2]);
                        zf[i2] = hz + hh * (Lz[i2] + b2 * (xn - hz));
                    }
                }
            }
        }
    }
}

__global__ void k_wloss(const float* __restrict__ W, float* __restrict__ C)
{
    __shared__ float sA[16][17];
    __shared__ float sB[16][17];
    int tx = threadIdx.x, ty = threadIdx.y;
    int i0 = blockIdx.y * 16, j0 = blockIdx.x * 16;
    float acc = 0.f;
    for (int k0 = 0; k0 < 800; k0 += 16) {
        sA[ty][tx] = (i0 + ty < MM) ? W[(size_t)(i0 + ty) * NN + k0 + tx] : 0.f;
        sB[ty][tx] = (j0 + ty < MM) ? W[(size_t)(j0 + ty) * NN + k0 + tx] : 0.f;
        __syncthreads();
#pragma unroll
        for (int kk = 0; kk < 16; kk++) acc += sA[ty][kk] * sB[tx][kk];
        __syncthreads();
    }
    int i = i0 + ty, j = j0 + tx;
    if (i < MM && j < MM) C[i * MM + j] = acc - (i == j ? 1.f : 0.f);
}

// ---------------- elementwise / prep ----------------

__global__ void k_layer0(const float* __restrict__ PhiTb, float* __restrict__ X1,
                         float* __restrict__ zf,
                         const float* __restrict__ h_arr, const float* __restrict__ b2_arr)
{
    int i = blockIdx.x * blockDim.x + threadIdx.x;
    if (i >= NB) return;
    float h0 = h_arr[0], b2 = b2_arr[0];
    float x = h0 * PhiTb[i];
    X1[i] = x;
    zf[i] = h0 * b2 * x;
}

__global__ __launch_bounds__(128) void k_prep(const float* __restrict__ c2f,
                                              const float* __restrict__ c1b,
                                              uint32_t* __restrict__ wpk)
{
    int base = blockIdx.x * 128 + threadIdx.x;
    for (int i = base; i < 2 * BWORDS; i += WBF_BLOCKS * 128) {
        int set = i / BWORDS, rem = i - set * BWORDS;
        int tap = rem / (16 * BSTRIDE), rem2 = rem - tap * (16 * BSTRIDE);
        int icp = rem2 / BSTRIDE, oc = rem2 - icp * BSTRIDE;
        const float* src = set ? c1b : c2f;
        uint32_t whi = 0u, wlo = 0u;
        if (oc < 32) {
            float w0 = src[oc * 288 + (2 * icp) * 9 + tap];
            float w1 = src[oc * 288 + (2 * icp + 1) * 9 + tap];
            __nv_bfloat16 h0 = __float2bfloat16_rn(w0), h1 = __float2bfloat16_rn(w1);
            __nv_bfloat16 l0 = __float2bfloat16_rn(w0 - __bfloat162float(h0));
            __nv_bfloat16 l1 = __float2bfloat16_rn(w1 - __bfloat162float(h1));
            whi = pkbf2(h0, h1);
            wlo = pkbf2(l0, l1);
        }
        int off = tap * (16 * BSTRIDE) + icp * BSTRIDE + oc;
        wpk[set * 2 * BWORDS + off] = whi;
        wpk[set * 2 * BWORDS + BWORDS + off] = wlo;
    }
}

// ---------------- conv kernels ----------------

// x_fwd: fused 1->32 conv (from zf, relu, weights in regs) + 32->32 mma conv.
// Writes PRE-SPLIT bf16 hi/lo word arrays (pads stay zero from static init).
__global__ __launch_bounds__(512) void conv32_fwd(const uint32_t* __restrict__ wpk,
                                                  uint32_t* __restrict__ xh,
                                                  uint32_t* __restrict__ xl,
                                                  const float* __restrict__ w1,
                                                  const float* __restrict__ zf_in)
{
    extern __shared__ uint32_t smw[];
    uint32_t* sAhi = smw;
    uint32_t* sAlo = smw + SROWS * ASTRIDE;
    uint32_t* sBhi = smw + 2 * SROWS * ASTRIDE;
    uint32_t* sBlo = sBhi + BWORDS;
    float* sZf = (float*)(sBlo + BWORDS);       // NROWS
    float* sW1 = sZf + NROWS;                   // 288
    int img = blockIdx.x, tid = threadIdx.x;

    for (int i = tid; i < 48 * ASTRIDE; i += 512) { sAhi[i] = 0u; sAlo[i] = 0u; }
    for (int i = tid; i < 70 * ASTRIDE; i += 512) {
        sAhi[1016 * ASTRIDE + i] = 0u; sAlo[1016 * ASTRIDE + i] = 0u;
    }
    for (int i = tid; i < BWORDS; i += 512) { sBhi[i] = wpk[i]; sBlo[i] = wpk[BWORDS + i]; }

    uint4 z4 = make_uint4(0u, 0u, 0u, 0u);
    for (int i = tid; i < NROWS * 4 * 2; i += 512) {
        int arr = (i >= NROWS * 4);
        int j = arr ? i - NROWS * 4 : i;
        int row = j >> 2, qq = j & 3;
        uint32_t* basep = (arr ? sAlo : sAhi) + (SROW0 + row) * ASTRIDE + qq * 4;
        *(uint4*)basep = z4;
    }
    for (int i = tid; i < NROWS; i += 512) sZf[i] = 0.f;
    for (int i = tid; i < 288; i += 512) {
        int oc = i / 9, tap = i - oc * 9;
        sW1[tap * 32 + oc] = w1[i];
    }
    __syncthreads();
    const float* gz = zf_in + (size_t)img * NN;
    for (int i = tid; i < NN; i += 512) {
        int r = i / 40, c0 = i - r * 40;
        sZf[(r + 1) * 44 + c0 + 1] = gz[i];
    }
    __syncthreads();

    // 1->32 conv: qq fixed per thread -> weights hoisted to registers
    {
        int qq = tid & 15, pxb = tid >> 4;   // pxb 0..31
        float wr[18];
#pragma unroll
        for (int t = 0; t < 9; t++) {
            wr[2 * t]     = sW1[t * 32 + 2 * qq];
            wr[2 * t + 1] = sW1[t * 32 + 2 * qq + 1];
        }
#pragma unroll 1
        for (int k2 = 0; k2 < 25; k2++) {
            int px = pxb + 32 * k2;
            int r = px / 40, c0 = px - r * 40;
            int pp = (r + 1) * 44 + (c0 + 1);
            float a0 = 0.f, a1 = 0.f;
#pragma unroll
            for (int t = 0; t < 9; t++) {
                float zv = sZf[pp + c_dtap[t]];
                a0 += wr[2 * t] * zv;
                a1 += wr[2 * t + 1] * zv;
            }
            a0 = fmaxf(a0, 0.f);
            a1 = fmaxf(a1, 0.f);
            uint32_t hi = cvt2bf(a1, a0);
            float h0 = __uint_as_float(hi << 16);
            float h1 = __uint_as_float(hi & 0xFFFF0000u);
            uint32_t lo = cvt2bf(a1 - h1, a0 - h0);
            int base = (SROW0 + pp) * ASTRIDE + qq;
            sAhi[base] = hi;
            sAlo[base] = lo;
        }
    }
    __syncthreads();

    int warp = tid >> 5, lane = tid & 31;
    int q = lane >> 2, c = lane & 3;
    uint32_t* oh = xh + (size_t)img * XSTRIDE;
    uint32_t* ol = xl + (size_t)img * XSTRIDE;

    int u1 = warp, u2 = warp + 16;
    bool has2 = (u2 < 31);
    int r1 = SROW0 + u1 * 32;
    int r2 = SROW0 + (has2 ? u2 : u1) * 32;

    float acc1[2][4][4], acc2[2][4][4];
    conv_mma_loop(sAhi, sAlo, sBhi, sBlo, r1, r2, has2, q, c, acc1, acc2);

#pragma unroll
    for (int uu = 0; uu < 2; uu++) {
        if (uu == 1 && !has2) break;
        int u = uu ? u2 : u1;
        float (*acc)[4][4] = uu ? acc2 : acc1;
#pragma unroll
        for (int s = 0; s < 2; s++) {
            int grow0 = u * 32 + s * 16 + q;
#pragma unroll
            for (int half = 0; half < 2; half++) {
                int grow = grow0 + half * 8;
                int rr = grow / 44, cc = grow - rr * 44;
                bool valid = (grow < NROWS) && rr >= 1 && rr <= 20 && cc >= 1 && cc <= 40;
                if (valid) {
                    int wbase = grow * 16 + c;   // word = c + o*4
#pragma unroll
                    for (int o = 0; o < 4; o++) {
                        float x0 = acc[s][o][half * 2 + 0];
                        float x1 = acc[s][o][half * 2 + 1];
                        uint32_t hi = cvt2bf(x1, x0);
                        float h0 = __uint_as_float(hi << 16);
                        float h1 = __uint_as_float(hi & 0xFFFF0000u);
                        uint32_t lo = cvt2bf(x1 - h1, x0 - h0);
                        oh[wbase + o * 4] = hi;
                        ol[wbase + o * 4] = lo;
                    }
                }
            }
        }
    }
}

// t1 + t2 fused, reading pre-split x_fwd.
__global__ __launch_bounds__(512) void conv32_t1t2(const uint32_t* __restrict__ xh,
                                                   const uint32_t* __restrict__ xl,
                                                   const uint32_t* __restrict__ wpk,
                                                   const float* __restrict__ thr_arr,
                                                   int layer,
                                                   float* __restrict__ Zout,
                                                   float* __restrict__ Sout,
                                                   const float* __restrict__ zf,
                                                   float* __restrict__ Ln,
                                                   const float* __restrict__ Lc,
                                                   const float* __restrict__ Lp,
                                                   const float* __restrict__ Xn,
                                                   const float* __restrict__ h_arr,
                                                   const float* __restrict__ b1_arr,
                                                   const float* __restrict__ tL_arr,
                                                   const float* __restrict__ w288)
{
    extern __shared__ uint32_t smw[];
    uint32_t* sAhi = smw;
    uint32_t* sAlo = smw + SROWS * ASTRIDE;
    uint32_t* sBhi = smw + 2 * SROWS * ASTRIDE;
    uint32_t* sBlo = sBhi + BWORDS;
    float* sWc = (float*)(sBlo + BWORDS);       // 288 ([tap][ic])
    float* sOut = (float*)smw;                  // overlays A region after mma
    int img = blockIdx.x, tid = threadIdx.x;

    for (int i = tid; i < 48 * ASTRIDE; i += 512) { sAhi[i] = 0u; sAlo[i] = 0u; }
    for (int i = tid; i < 70 * ASTRIDE; i += 512) {
        sAhi[1016 * ASTRIDE + i] = 0u; sAlo[1016 * ASTRIDE + i] = 0u;
    }
    for (int i = tid; i < BWORDS; i += 512) { sBhi[i] = wpk[i]; sBlo[i] = wpk[BWORDS + i]; }
    for (int i = tid; i < 288; i += 512) {
        int ic = i / 9, tap = i - ic * 9;
        sWc[tap * 32 + ic] = w288[i];
    }

    float sthr = fabsf(thr_arr[layer]);
    fill_from_split(sAhi, sAlo, xh, xl, img, tid, 1, sthr);
    __syncthreads();

    int warp = tid >> 5, lane = tid & 31;
    int q = lane >> 2, c = lane & 3;
    int u1 = warp, u2 = warp + 16;
    bool has2 = (u2 < 31);
    int r1 = SROW0 + u1 * 32;
    int r2 = SROW0 + (has2 ? u2 : u1) * 32;
    size_t base = (size_t)img * NN;

    float acc1[2][4][4], acc2[2][4][4];

    // ============ t1 ============
    conv_mma_loop(sAhi, sAlo, sBhi, sBlo, r1, r2, has2, q, c, acc1, acc2);
    __syncthreads();

    {
        float4 z = make_float4(0.f, 0.f, 0.f, 0.f);
        for (int i = tid; i < NROWS * 9; i += 512) ((float4*)sOut)[i] = z;
    }
    __syncthreads();
    conv_epi_smem(sOut, acc1, acc2, u1, u2, has2, q, c);
    __syncthreads();

    for (int p = tid; p < NN; p += 512) {
        int r = p / 40, c0 = p - r * 40;
        int pp = (r + 1) * 44 + (c0 + 1);
        float acc = 0.f;
#pragma unroll
        for (int t = 0; t < 9; t++) {
            const float4* a4 = (const float4*)(sOut + (pp + c_dtap[t]) * SOSTRIDE);
            const float4* wv = (const float4*)(sWc + t * 32);
#pragma unroll
            for (int qq = 0; qq < 8; qq++) {
                float4 x = a4[qq], ww = wv[qq];
                acc += x.x * ww.x + x.y * ww.y + x.z * ww.z + x.w * ww.w;
            }
        }
        Zout[base + p] = acc;
        float lc = Lc[base + p], lp = Lp[base + p];
        float hatL = lc + tL_arr[layer] * (lc - lp);
        Ln[base + p] = hatL + h_arr[layer] * b1_arr[layer] * (Xn[base + p] - acc);
    }
    __syncthreads();

    // ============ t2 ============
    fill_from_split(sAhi, sAlo, xh, xl, img, tid, 0, 0.f);
    __syncthreads();

    conv_mma_loop(sAhi, sAlo, sBhi, sBlo, r1, r2, has2, q, c, acc1, acc2);
    __syncthreads();

    {
        float4 z = make_float4(0.f, 0.f, 0.f, 0.f);
        for (int i = tid; i < NROWS * 9; i += 512) ((float4*)sOut)[i] = z;
    }
    __syncthreads();
    conv_epi_smem(sOut, acc1, acc2, u1, u2, has2, q, c);
    __syncthreads();

    for (int p = tid; p < NN; p += 512) {
        int r = p / 40, c0 = p - r * 40;
        int pp = (r + 1) * 44 + (c0 + 1);
        float acc = 0.f;
#pragma unroll
        for (int t = 0; t < 9; t++) {
            const float4* a4 = (const float4*)(sOut + (pp + c_dtap[t]) * SOSTRIDE);
            const float4* wv = (const float4*)(sWc + t * 32);
#pragma unroll
            for (int qq = 0; qq < 8; qq++) {
                float4 x = a4[qq], ww = wv[qq];
                acc += x.x * ww.x + x.y * ww.y + x.z * ww.z + x.w * ww.w;
            }
        }
        Sout[base + p] = acc - zf[base + p];
    }
}

// ---------------- host ----------------

extern "C" void kernel_launch(void* const* d_in, const int* in_sizes, int n_in,
                              void* d_out, int out_size)
{
    const float* y    = (const float*)d_in[0];
    const float* W    = (const float*)d_in[2];
    const float* beta1 = (const float*)d_in[3];
    const float* beta2 = (const float*)d_in[4];
    const float* h_   = (const float*)d_in[5];
    const float* sthr = (const float*)d_in[6];
    const float* thx  = (const float*)d_in[7];
    const float* thz  = (const float*)d_in[8];
    const float* thL  = (const float*)d_in[9];
    const float* c1f  = (const float*)d_in[10];
    const float* c2f  = (const float*)d_in[11];
    const float* c1b  = (const float*)d_in[12];
    const float* c2b  = (const float*)d_in[13];

    float* out = (float*)d_out;
    float* Zs = out;
    float* syms = out + (size_t)9 * NB;
    float* wlo = out + (size_t)18 * NB;

    float *pPhiTPhi, *pPhiTb, *pX, *pL, *pZero, *pZf;
    uint32_t *pWPK, *pXH, *pXL;
    cudaGetSymbolAddress((void**)&pPhiTPhi, g_PhiTPhi);
    cudaGetSymbolAddress((void**)&pPhiTb, g_PhiTb);
    cudaGetSymbolAddress((void**)&pX, g_Xbuf);
    cudaGetSymbolAddress((void**)&pL, g_Lbuf);
    cudaGetSymbolAddress((void**)&pZero, g_zerobuf);
    cudaGetSymbolAddress((void**)&pZf, g_zflat);
    cudaGetSymbolAddress((void**)&pXH, g_xh);
    cudaGetSymbolAddress((void**)&pXL, g_xl);
    cudaGetSymbolAddress((void**)&pWPK, g_wpk);

    const int SMMAW = (2 * SROWS * ASTRIDE + 2 * BWORDS + NROWS + 288) * 4;  // 224,864 B
    cudaFuncSetAttribute(conv32_fwd, cudaFuncAttributeMaxDynamicSharedMemorySize, SMMAW);
    cudaFuncSetAttribute(conv32_t1t2, cudaFuncAttributeMaxDynamicSharedMemorySize, SMMAW);

    cudaMemsetAsync(pZero, 0, (size_t)NB * 4);

    float* Xslot[3] = {pX, pX + NB, pX + 2 * (size_t)NB};
    float* Lslot[2] = {pL, pL + NB};

    k_prep<<<WBF_BLOCKS, 128>>>(c2f, c1b, pWPK);
    gemm_mma<<<dim3(7, 32), 512>>>(y, W, pPhiTb, BB, MM, NN);

    int xcur = 0, xprev = -1;
    int lcur = 0, lprev = -1;

    for (int i = 0; i < 9; i++) {
        float* Xn;
        if (i == 0) {
            Xn = Xslot[0];
            k_layer0<<<NB / 256, 256>>>(pPhiTb, Xn, pZf, h_, beta2);
            xcur = 0; xprev = -1;
        } else {
            const float* Xc = Xslot[xcur];
            const float* Xp = (xprev < 0) ? pZero : Xslot[xprev];
            const float* Lc_ = Lslot[lcur];
            const float* Zc = Zs + (size_t)(i - 1) * NB;
            const float* Zp = (i >= 2) ? Zs + (size_t)(i - 2) * NB : pZero;
            const float* Zg = (i >= 2) ? Zc : pZero;
            const float* Lg = (i >= 2) ? Lc_ : pZero;
            const float* Lz = (i >= 2) ? Lc_ : pZero;
            int xnew = (xprev < 0) ? 1 : (3 - xcur - xprev);
            Xn = Xslot[xnew];
            gemm_xstep<<<dim3(7, 32), 512>>>(Xc, Xp, pPhiTPhi,
                                             pPhiTb, Zg, Lg, Zc, Zp, Lz,
                                             Xn, pZf,
                                             beta1, beta2, h_, thz, thx, i);
            xprev = xcur; xcur = xnew;
        }

        conv32_fwd<<<BB, 512, SMMAW>>>(pWPK, pXH, pXL, c1f, pZf);

        {
            const float* Lc_ = (i == 0) ? pZero : Lslot[lcur];
            const float* Lp_ = (i == 0) ? pZero : ((lprev < 0) ? pZero : Lslot[lprev]);
            int lnew = (i == 0) ? 0 : ((lprev < 0) ? 1 : lprev);
            conv32_t1t2<<<BB, 512, SMMAW>>>(pXH, pXL, pWPK + 2 * BWORDS, sthr, i,
                                            Zs + (size_t)i * NB,
                                            syms + (size_t)i * NB, pZf,
                                            Lslot[lnew], Lc_, Lp_, Xn,
                                            h_, beta1, thL, c2b);
            if (i > 0) { lprev = lcur; lcur = lnew; }
            else { lcur = 0; lprev = -1; }
        }

        if (i == 0) {
            gemm_AtB<<<dim3(13, 13), 256>>>(W, W, pPhiTPhi, MM, NN, NN);
        }
    }

    k_wloss<<<dim3(21, 21), dim3(16, 16)>>>(W, wlo);
}

// round 17
// speedup vs baseline: 3.9416x; 1.3805x over previous
#include <cuda_runtime.h>
#include <cuda_bf16.h>
#include <cstdint>

#define BB 4096
#define MM 327
#define NN 800
#define NB (BB*NN)              // 3,276,800 per state buffer
#define NROWS 968               // 22*44 padded pixel rows
#define XSTRIDE (NROWS*16)      // packed bf16x2 words per image (15488)
#define SROW0 48
#define SROWS 1086              // 48 guard + 968 data + 70 guard rows (never zeroed; only invalid outputs read guards)
#define ASTRIDE 20              // words per row in smem A ({20q+c} distinct mod 32)
#define BSTRIDE 40              // words per icpair in smem B ({40c+q} distinct mod 32)
#define BWORDS (9*16*BSTRIDE)   // 5760 words per (set,half)
#define WBF_BLOCKS 46

// gemm tile params
#define GASTR 20
#define GBSTR 136               // 128 + 8; conflict-free

typedef unsigned long long ull;

// ---------------- device scratch (static, allowed; zero-initialized) ----------
__device__ float g_PhiTPhi[NN*NN];
__device__ float g_PhiTb[NB];
__device__ float g_Xbuf[3*NB];                   // 3-slot X rotation
__device__ float g_Lbuf[2*NB];
__device__ float g_zerobuf[NB];
__device__ float g_zflat[NB];
__device__ uint32_t g_xh[(size_t)BB*XSTRIDE];    // x_fwd bf16-hi words (pads stay 0)
__device__ uint32_t g_xl[(size_t)BB*XSTRIDE];    // x_fwd bf16-lo words
__device__ uint32_t g_wpk[2*2*BWORDS];           // [set][hi/lo][BWORDS] packed bf16x2

__constant__ int c_dtap[9] = {-45, -44, -43, -1, 0, 1, 43, 44, 45};

// ---------------- helpers ----------------
__device__ __forceinline__ uint32_t pkbf2(__nv_bfloat16 e0, __nv_bfloat16 e1) {
    return ((uint32_t)__bfloat16_as_ushort(e1) << 16) | (uint32_t)__bfloat16_as_ushort(e0);
}
__device__ __forceinline__ uint32_t cvt2bf(float hi, float lo) {
    uint32_t r;
    asm("cvt.rn.satfinite.bf16x2.f32 %0, %1, %2;" : "=r"(r) : "f"(hi), "f"(lo));
    return r;
}

__device__ __forceinline__ void mma_bf16(float* d, const uint32_t* a, uint32_t b0, uint32_t b1) {
    asm volatile(
        "mma.sync.aligned.m16n8k16.row.col.f32.bf16.bf16.f32 "
        "{%0,%1,%2,%3}, {%4,%5,%6,%7}, {%8,%9}, {%0,%1,%2,%3};"
        : "+f"(d[0]), "+f"(d[1]), "+f"(d[2]), "+f"(d[3])
        : "r"(a[0]), "r"(a[1]), "r"(a[2]), "r"(a[3]), "r"(b0), "r"(b1));
}

__device__ __forceinline__ void ldAfrag(uint32_t* a, const uint32_t* Aarr, int baserow,
                                        int ks, int q, int c) {
    int tap = ks >> 1, icb = (ks & 1) * 8;
    const uint32_t* Ap = Aarr + (baserow + c_dtap[tap] + q) * ASTRIDE + icb + c;
    a[0] = Ap[0];
    a[1] = Ap[8 * ASTRIDE];
    a[2] = Ap[4];
    a[3] = Ap[8 * ASTRIDE + 4];
    a[4] = Ap[16 * ASTRIDE];
    a[5] = Ap[24 * ASTRIDE];
    a[6] = Ap[16 * ASTRIDE + 4];
    a[7] = Ap[24 * ASTRIDE + 4];
}
__device__ __forceinline__ void ldBfrag(uint32_t* b, const uint32_t* Barr,
                                        int ks, int q, int c) {
    int tap = ks >> 1, icb = (ks & 1) * 8;
    const uint32_t* Bp = Barr + tap * (16 * BSTRIDE) + (icb + c) * BSTRIDE + q;
#pragma unroll
    for (int o = 0; o < 4; o++) {
        b[2 * o]     = Bp[o * 8];
        b[2 * o + 1] = Bp[4 * BSTRIDE + o * 8];
    }
}

// shared mma mainloop for the conv kernels (2 units per warp sharing B)
__device__ __forceinline__ void conv_mma_loop(const uint32_t* sAhi, const uint32_t* sAlo,
                                              const uint32_t* sBhi, const uint32_t* sBlo,
                                              int r1, int r2, bool has2, int q, int c,
                                              float acc1[2][4][4], float acc2[2][4][4])
{
#pragma unroll
    for (int s = 0; s < 2; s++)
#pragma unroll
        for (int o = 0; o < 4; o++)
#pragma unroll
            for (int j = 0; j < 4; j++) { acc1[s][o][j] = 0.f; acc2[s][o][j] = 0.f; }

#pragma unroll 1
    for (int pass = 0; pass < 3; pass++) {
        const uint32_t* Aarr = (pass == 2) ? sAlo : sAhi;
        const uint32_t* Barr = (pass == 1) ? sBlo : sBhi;
#pragma unroll
        for (int ks = 0; ks < 18; ks++) {
            uint32_t Af1[8], Af2[8], Bf[8];
            ldAfrag(Af1, Aarr, r1, ks, q, c);
            if (has2) ldAfrag(Af2, Aarr, r2, ks, q, c);
            ldBfrag(Bf, Barr, ks, q, c);
#pragma unroll
            for (int o = 0; o < 4; o++) {
                uint32_t b0 = Bf[2 * o], b1 = Bf[2 * o + 1];
                mma_bf16(acc1[0][o], Af1 + 0, b0, b1);
                mma_bf16(acc1[1][o], Af1 + 4, b0, b1);
                if (has2) {
                    mma_bf16(acc2[0][o], Af2 + 0, b0, b1);
                    mma_bf16(acc2[1][o], Af2 + 4, b0, b1);
                }
            }
        }
    }
}

// fill sA from pre-split gmem words. do_soft=1: reconstruct, soft, resplit.
__device__ __forceinline__ void fill_from_split(uint32_t* sAhi, uint32_t* sAlo,
                                                const uint32_t* xh, const uint32_t* xl,
                                                int img, int tid, int do_soft, float sthr)
{
    const uint4* gh = (const uint4*)(xh + (size_t)img * XSTRIDE);
    const uint4* gl = (const uint4*)(xl + (size_t)img * XSTRIDE);
    for (int i = tid; i < NROWS * 4; i += 512) {
        uint4 h = gh[i];
        uint4 l = gl[i];
        if (do_soft) {
#pragma unroll
            for (int w = 0; w < 4; w++) {
                uint32_t hw = (&h.x)[w], lw = (&l.x)[w];
                float x0 = __uint_as_float(hw << 16) + __uint_as_float(lw << 16);
                float x1 = __uint_as_float(hw & 0xFFFF0000u) + __uint_as_float(lw & 0xFFFF0000u);
                float a0 = fabsf(x0) - sthr;
                x0 = (a0 > 0.f) ? (x0 > 0.f ? a0 : -a0) : 0.f;
                float a1 = fabsf(x1) - sthr;
                x1 = (a1 > 0.f) ? (x1 > 0.f ? a1 : -a1) : 0.f;
                uint32_t nh = cvt2bf(x1, x0);
                (&h.x)[w] = nh;
                (&l.x)[w] = cvt2bf(x1 - __uint_as_float(nh & 0xFFFF0000u),
                                   x0 - __uint_as_float(nh << 16));
            }
        }
        int row = i >> 2, j = i & 3;
        int base = (SROW0 + row) * ASTRIDE + 4 * j;
        *(uint4*)(sAhi + base) = h;
        *(uint4*)(sAlo + base) = l;
    }
}

// S-plane epilogue: S_t[row] = sum_ch relu(acc)[row][ch] * wc[t][ch],
// computed from registers via 8 FMA + 2 bfly shuffles; only valid rows stored.
__device__ __forceinline__ void conv_s_planes(float* sS, const float* sWc,
                                              float acc1[2][4][4], float acc2[2][4][4],
                                              int u1, int u2, bool has2, int q, int c)
{
#pragma unroll
    for (int s = 0; s < 2; s++)
#pragma unroll
        for (int o = 0; o < 4; o++)
#pragma unroll
            for (int j = 0; j < 4; j++) {
                acc1[s][o][j] = fmaxf(acc1[s][o][j], 0.f);
                acc2[s][o][j] = fmaxf(acc2[s][o][j], 0.f);
            }
#pragma unroll 1
    for (int t = 0; t < 9; t++) {
        float2 w2[4];
#pragma unroll
        for (int o = 0; o < 4; o++)
            w2[o] = *(const float2*)(sWc + t * 32 + o * 8 + 2 * c);
#pragma unroll
        for (int uu = 0; uu < 2; uu++) {
            if (uu == 1 && !has2) break;
            int u = uu ? u2 : u1;
            float (*acc)[4][4] = uu ? acc2 : acc1;
#pragma unroll
            for (int s = 0; s < 2; s++) {
#pragma unroll
                for (int half = 0; half < 2; half++) {
                    float v = 0.f;
#pragma unroll
                    for (int o = 0; o < 4; o++) {
                        v += acc[s][o][half * 2 + 0] * w2[o].x;
                        v += acc[s][o][half * 2 + 1] * w2[o].y;
                    }
                    v += __shfl_xor_sync(0xffffffffu, v, 1);
                    v += __shfl_xor_sync(0xffffffffu, v, 2);
                    int grow = u * 32 + s * 16 + half * 8 + q;
                    int rr = grow / 44, cc = grow - rr * 44;
                    bool valid = (grow < NROWS) && rr >= 1 && rr <= 20 && cc >= 1 && cc <= 40;
                    if (valid && c == (t & 3))
                        sS[t * NROWS + grow] = v;
                }
            }
        }
    }
}

// ---------------- GEMMs ----------------

__global__ __launch_bounds__(256) void gemm_AtB(const float* __restrict__ A,
                                                const float* __restrict__ B,
                                                float* __restrict__ C,
                                                int K, int I, int J)
{
    __shared__ float As[16][68];
    __shared__ float Bs[16][68];
    int tid = threadIdx.x;
    int tx = tid & 15, ty = tid >> 4;
    int i0 = blockIdx.y * 64, j0 = blockIdx.x * 64;
    float acc[4][4];
#pragma unroll
    for (int a = 0; a < 4; a++)
#pragma unroll
        for (int b = 0; b < 4; b++) acc[a][b] = 0.f;

    int kr = tid >> 4, c4 = (tid & 15) * 4;
    for (int k0 = 0; k0 < K; k0 += 16) {
        bool kv = (k0 + kr) < K;
#pragma unroll
        for (int j = 0; j < 4; j++) {
            int ii = i0 + c4 + j;
            As[kr][c4 + j] = (kv && ii < I) ? A[(size_t)(k0 + kr) * I + ii] : 0.f;
            int jj = j0 + c4 + j;
            Bs[kr][c4 + j] = (kv && jj < J) ? B[(size_t)(k0 + kr) * J + jj] : 0.f;
        }
        __syncthreads();
#pragma unroll
        for (int kk = 0; kk < 16; kk++) {
            float a[4], b[4];
#pragma unroll
            for (int i = 0; i < 4; i++) a[i] = As[kk][ty * 4 + i];
#pragma unroll
            for (int j = 0; j < 4; j++) b[j] = Bs[kk][tx * 4 + j];
#pragma unroll
            for (int i = 0; i < 4; i++)
#pragma unroll
                for (int j = 0; j < 4; j++) acc[i][j] += a[i] * b[j];
        }
        __syncthreads();
    }
#pragma unroll
    for (int i = 0; i < 4; i++) {
        int r = i0 + ty * 4 + i;
        if (r < I) {
#pragma unroll
            for (int j = 0; j < 4; j++) {
                int n = j0 + tx * 4 + j;
                if (n < J) C[(size_t)r * J + n] = acc[i][j];
            }
        }
    }
}

// bf16 3-pass split GEMM: C[M,N] = A[M,K] * B[K,N], fp32 in/out.
__global__ __launch_bounds__(512) void gemm_mma(const float* __restrict__ A,
                                                const float* __restrict__ B,
                                                float* __restrict__ C,
                                                int M, int K, int N)
{
    __shared__ uint32_t sAhi[128 * GASTR];
    __shared__ uint32_t sAlo[128 * GASTR];
    __shared__ uint32_t sBhi[16 * GBSTR];
    __shared__ uint32_t sBlo[16 * GBSTR];

    int tid = threadIdx.x;
    int warp = tid >> 5, lane = tid & 31;
    int q = lane >> 2, c = lane & 3;
    int m0 = blockIdx.y * 128, n0 = blockIdx.x * 128;
    int wm = (warp >> 2) * 32, wn = (warp & 3) * 32;

    float acc[2][4][4];
#pragma unroll
    for (int s = 0; s < 2; s++)
#pragma unroll
        for (int o = 0; o < 4; o++)
#pragma unroll
            for (int j = 0; j < 4; j++) acc[s][o][j] = 0.f;

    for (int k0 = 0; k0 < K; k0 += 32) {
        for (int i = tid; i < 2048; i += 512) {
            int m = i >> 4, w = i & 15;
            int k = k0 + 2 * w;
            const float* ar = A + (size_t)(m0 + m) * K;
            float x0 = (k < K) ? ar[k] : 0.f;
            float x1 = (k + 1 < K) ? ar[k + 1] : 0.f;
            uint32_t hi = cvt2bf(x1, x0);
            float h0 = __uint_as_float(hi << 16);
            float h1 = __uint_as_float(hi & 0xFFFF0000u);
            uint32_t lo = cvt2bf(x1 - h1, x0 - h0);
            sAhi[m * GASTR + w] = hi;
            sAlo[m * GASTR + w] = lo;
        }
        for (int i = tid; i < 2048; i += 512) {
            int kp = i >> 7, n = i & 127;
            int k = k0 + 2 * kp;
            int nn = n0 + n;
            float x0 = (k < K && nn < N) ? B[(size_t)k * N + nn] : 0.f;
            float x1 = (k + 1 < K && nn < N) ? B[(size_t)(k + 1) * N + nn] : 0.f;
            uint32_t hi = cvt2bf(x1, x0);
            float h0 = __uint_as_float(hi << 16);
            float h1 = __uint_as_float(hi & 0xFFFF0000u);
            uint32_t lo = cvt2bf(x1 - h1, x0 - h0);
            sBhi[kp * GBSTR + n] = hi;
            sBlo[kp * GBSTR + n] = lo;
        }
        __syncthreads();

#pragma unroll 1
        for (int pass = 0; pass < 3; pass++) {
            const uint32_t* Aarr = (pass == 2) ? sAlo : sAhi;
            const uint32_t* Barr = (pass == 1) ? sBlo : sBhi;
#pragma unroll
            for (int ks = 0; ks < 2; ks++) {
                int icb = ks * 8;
                uint32_t Af[8], Bf[8];
#pragma unroll
                for (int s = 0; s < 2; s++) {
                    const uint32_t* Ap = Aarr + (wm + s * 16 + q) * GASTR + icb + c;
                    Af[s * 4 + 0] = Ap[0];
                    Af[s * 4 + 1] = Ap[8 * GASTR];
                    Af[s * 4 + 2] = Ap[4];
                    Af[s * 4 + 3] = Ap[8 * GASTR + 4];
                }
                const uint32_t* Bp = Barr + (icb + c) * GBSTR + wn + q;
#pragma unroll
                for (int o = 0; o < 4; o++) {
                    Bf[2 * o]     = Bp[o * 8];
                    Bf[2 * o + 1] = Bp[4 * GBSTR + o * 8];
                }
#pragma unroll
                for (int o = 0; o < 4; o++) {
                    mma_bf16(acc[0][o], Af + 0, Bf[2 * o], Bf[2 * o + 1]);
                    mma_bf16(acc[1][o], Af + 4, Bf[2 * o], Bf[2 * o + 1]);
                }
            }
        }
        __syncthreads();
    }

#pragma unroll
    for (int s = 0; s < 2; s++) {
#pragma unroll
        for (int half = 0; half < 2; half++) {
            int row = m0 + wm + s * 16 + q + half * 8;
            float* crow = C + (size_t)row * N;
#pragma unroll
            for (int o = 0; o < 4; o++) {
                int col = n0 + wn + o * 8 + c * 2;
                if (col < N)
                    *(float2*)(crow + col) =
                        make_float2(acc[s][o][half * 2 + 0], acc[s][o][half * 2 + 1]);
            }
        }
    }
}

// X-step GEMM: A = hatx computed on the fly; epilogue = full xepi update.
__global__ __launch_bounds__(512) void gemm_xstep(const float* __restrict__ Xc,
                                                  const float* __restrict__ Xp,
                                                  const float* __restrict__ B,
                                                  const float* __restrict__ PhiTb,
                                                  const float* __restrict__ Zg,
                                                  const float* __restrict__ Lg,
                                                  const float* __restrict__ Zc,
                                                  const float* __restrict__ Zp,
                                                  const float* __restrict__ Lz,
                                                  float* __restrict__ Xn,
                                                  float* __restrict__ zf,
                                                  const float* __restrict__ b1a,
                                                  const float* __restrict__ b2a,
                                                  const float* __restrict__ ha,
                                                  const float* __restrict__ tza,
                                                  const float* __restrict__ txa,
                                                  int layer)
{
    __shared__ uint32_t sAhi[128 * GASTR];
    __shared__ uint32_t sAlo[128 * GASTR];
    __shared__ uint32_t sBhi[16 * GBSTR];
    __shared__ uint32_t sBlo[16 * GBSTR];

    const int K = NN, N = NN;
    int tid = threadIdx.x;
    int warp = tid >> 5, lane = tid & 31;
    int q = lane >> 2, c = lane & 3;
    int m0 = blockIdx.y * 128, n0 = blockIdx.x * 128;
    int wm = (warp >> 2) * 32, wn = (warp & 3) * 32;
    float tx = txa[layer];

    float acc[2][4][4];
#pragma unroll
    for (int s = 0; s < 2; s++)
#pragma unroll
        for (int o = 0; o < 4; o++)
#pragma unroll
            for (int j = 0; j < 4; j++) acc[s][o][j] = 0.f;

    for (int k0 = 0; k0 < K; k0 += 32) {
        for (int i = tid; i < 2048; i += 512) {
            int m = i >> 4, w = i & 15;
            int k = k0 + 2 * w;
            size_t rb = (size_t)(m0 + m) * K;
            float x0 = 0.f, x1 = 0.f;
            if (k < K) {
                float xc = Xc[rb + k];
                x0 = xc + tx * (xc - Xp[rb + k]);
            }
            if (k + 1 < K) {
                float xc = Xc[rb + k + 1];
                x1 = xc + tx * (xc - Xp[rb + k + 1]);
            }
            uint32_t hi = cvt2bf(x1, x0);
            float h0 = __uint_as_float(hi << 16);
            float h1 = __uint_as_float(hi & 0xFFFF0000u);
            uint32_t lo = cvt2bf(x1 - h1, x0 - h0);
            sAhi[m * GASTR + w] = hi;
            sAlo[m * GASTR + w] = lo;
        }
        for (int i = tid; i < 2048; i += 512) {
            int kp = i >> 7, n = i & 127;
            int k = k0 + 2 * kp;
            int nn = n0 + n;
            float x0 = (k < K && nn < N) ? B[(size_t)k * N + nn] : 0.f;
            float x1 = (k + 1 < K && nn < N) ? B[(size_t)(k + 1) * N + nn] : 0.f;
            uint32_t hi = cvt2bf(x1, x0);
            float h0 = __uint_as_float(hi << 16);
            float h1 = __uint_as_float(hi & 0xFFFF0000u);
            uint32_t lo = cvt2bf(x1 - h1, x0 - h0);
            sBhi[kp * GBSTR + n] = hi;
            sBlo[kp * GBSTR + n] = lo;
        }
        __syncthreads();

#pragma unroll 1
        for (int pass = 0; pass < 3; pass++) {
            const uint32_t* Aarr = (pass == 2) ? sAlo : sAhi;
            const uint32_t* Barr = (pass == 1) ? sBlo : sBhi;
#pragma unroll
            for (int ks = 0; ks < 2; ks++) {
                int icb = ks * 8;
                uint32_t Af[8], Bf[8];
#pragma unroll
                for (int s = 0; s < 2; s++) {
                    const uint32_t* Ap = Aarr + (wm + s * 16 + q) * GASTR + icb + c;
                    Af[s * 4 + 0] = Ap[0];
                    Af[s * 4 + 1] = Ap[8 * GASTR];
                    Af[s * 4 + 2] = Ap[4];
                    Af[s * 4 + 3] = Ap[8 * GASTR + 4];
                }
                const uint32_t* Bp = Barr + (icb + c) * GBSTR + wn + q;
#pragma unroll
                for (int o = 0; o < 4; o++) {
                    Bf[2 * o]     = Bp[o * 8];
                    Bf[2 * o + 1] = Bp[4 * GBSTR + o * 8];
                }
#pragma unroll
                for (int o = 0; o < 4; o++) {
                    mma_bf16(acc[0][o], Af + 0, Bf[2 * o], Bf[2 * o + 1]);
                    mma_bf16(acc[1][o], Af + 4, Bf[2 * o], Bf[2 * o + 1]);
                }
            }
        }
        __syncthreads();
    }

    float b1 = b1a[layer], b2 = b2a[layer], hh = ha[layer], tz = tza[layer];
#pragma unroll
    for (int s = 0; s < 2; s++) {
#pragma unroll
        for (int half = 0; half < 2; half++) {
            int row = m0 + wm + s * 16 + q + half * 8;
            size_t rb = (size_t)row * N;
#pragma unroll
            for (int o = 0; o < 4; o++) {
                int col = n0 + wn + o * 8 + c * 2;
                if (col < N) {
                    size_t idx = rb + col;
#pragma unroll
                    for (int e = 0; e < 2; e++) {
                        size_t i2 = idx + e;
                        float gm = acc[s][o][half * 2 + e];
                        float xc = Xc[i2];
                        float hxv = xc + tx * (xc - Xp[i2]);
                        float grad = PhiTb[i2] - gm + b1 * (Zg[i2] - hxv) - Lg[i2];
                        float xn = hxv + hh * grad;
                        Xn[i2] = xn;
                        float zc = Zc[i2];
                        float hz = zc + tz * (zc - Zp[i2]);
                        zf[i2] = hz + hh * (Lz[i2] + b2 * (xn - hz));
                    }
                }
            }
        }
    }
}

__global__ void k_wloss(const float* __restrict__ W, float* __restrict__ C)
{
    __shared__ float sA[16][17];
    __shared__ float sB[16][17];
    int tx = threadIdx.x, ty = threadIdx.y;
    int i0 = blockIdx.y * 16, j0 = blockIdx.x * 16;
    float acc = 0.f;
    for (int k0 = 0; k0 < 800; k0 += 16) {
        sA[ty][tx] = (i0 + ty < MM) ? W[(size_t)(i0 + ty) * NN + k0 + tx] : 0.f;
        sB[ty][tx] = (j0 + ty < MM) ? W[(size_t)(j0 + ty) * NN + k0 + tx] : 0.f;
        __syncthreads();
#pragma unroll
        for (int kk = 0; kk < 16; kk++) acc += sA[ty][kk] * sB[tx][kk];
        __syncthreads();
    }
    int i = i0 + ty, j = j0 + tx;
    if (i < MM && j < MM) C[i * MM + j] = acc - (i == j ? 1.f : 0.f);
}

// ---------------- elementwise / prep ----------------

__global__ void k_layer0(const float* __restrict__ PhiTb, float* __restrict__ X1,
                         float* __restrict__ zf,
                         const float* __restrict__ h_arr, const float* __restrict__ b2_arr)
{
    int i = blockIdx.x * blockDim.x + threadIdx.x;
    if (i >= NB) return;
    float h0 = h_arr[0], b2 = b2_arr[0];
    float x = h0 * PhiTb[i];
    X1[i] = x;
    zf[i] = h0 * b2 * x;
}

__global__ __launch_bounds__(128) void k_prep(const float* __restrict__ c2f,
                                              const float* __restrict__ c1b,
                                              uint32_t* __restrict__ wpk)
{
    int base = blockIdx.x * 128 + threadIdx.x;
    for (int i = base; i < 2 * BWORDS; i += WBF_BLOCKS * 128) {
        int set = i / BWORDS, rem = i - set * BWORDS;
        int tap = rem / (16 * BSTRIDE), rem2 = rem - tap * (16 * BSTRIDE);
        int icp = rem2 / BSTRIDE, oc = rem2 - icp * BSTRIDE;
        const float* src = set ? c1b : c2f;
        uint32_t whi = 0u, wlo = 0u;
        if (oc < 32) {
            float w0 = src[oc * 288 + (2 * icp) * 9 + tap];
            float w1 = src[oc * 288 + (2 * icp + 1) * 9 + tap];
            __nv_bfloat16 h0 = __float2bfloat16_rn(w0), h1 = __float2bfloat16_rn(w1);
            __nv_bfloat16 l0 = __float2bfloat16_rn(w0 - __bfloat162float(h0));
            __nv_bfloat16 l1 = __float2bfloat16_rn(w1 - __bfloat162float(h1));
            whi = pkbf2(h0, h1);
            wlo = pkbf2(l0, l1);
        }
        int off = tap * (16 * BSTRIDE) + icp * BSTRIDE + oc;
        wpk[set * 2 * BWORDS + off] = whi;
        wpk[set * 2 * BWORDS + BWORDS + off] = wlo;
    }
}

// ---------------- conv kernels ----------------

// x_fwd: fused 1->32 conv (from zf, relu, weights in regs) + 32->32 mma conv.
// Writes PRE-SPLIT bf16 hi/lo word arrays. Guards never zeroed (only invalid
// outputs read them).
__global__ __launch_bounds__(512) void conv32_fwd(const uint32_t* __restrict__ wpk,
                                                  uint32_t* __restrict__ xh,
                                                  uint32_t* __restrict__ xl,
                                                  const float* __restrict__ w1,
                                                  const float* __restrict__ zf_in)
{
    extern __shared__ uint32_t smw[];
    uint32_t* sAhi = smw;
    uint32_t* sAlo = smw + SROWS * ASTRIDE;
    uint32_t* sBhi = smw + 2 * SROWS * ASTRIDE;
    uint32_t* sBlo = sBhi + BWORDS;
    float* sZf = (float*)(sBlo + BWORDS);       // NROWS
    float* sW1 = sZf + NROWS;                   // 288
    int img = blockIdx.x, tid = threadIdx.x;

    for (int i = tid; i < BWORDS; i += 512) { sBhi[i] = wpk[i]; sBlo[i] = wpk[BWORDS + i]; }

    // zero all data rows (padding pixels must be 0 for valid outputs)
    uint4 z4 = make_uint4(0u, 0u, 0u, 0u);
    for (int i = tid; i < NROWS * 4 * 2; i += 512) {
        int arr = (i >= NROWS * 4);
        int j = arr ? i - NROWS * 4 : i;
        int row = j >> 2, qq = j & 3;
        uint32_t* basep = (arr ? sAlo : sAhi) + (SROW0 + row) * ASTRIDE + qq * 4;
        *(uint4*)basep = z4;
    }
    for (int i = tid; i < NROWS; i += 512) sZf[i] = 0.f;
    for (int i = tid; i < 288; i += 512) {
        int oc = i / 9, tap = i - oc * 9;
        sW1[tap * 32 + oc] = w1[i];
    }
    __syncthreads();
    const float* gz = zf_in + (size_t)img * NN;
    for (int i = tid; i < NN; i += 512) {
        int r = i / 40, c0 = i - r * 40;
        sZf[(r + 1) * 44 + c0 + 1] = gz[i];
    }
    __syncthreads();

    {
        int qq = tid & 15, pxb = tid >> 4;
        float wr[18];
#pragma unroll
        for (int t = 0; t < 9; t++) {
            wr[2 * t]     = sW1[t * 32 + 2 * qq];
            wr[2 * t + 1] = sW1[t * 32 + 2 * qq + 1];
        }
#pragma unroll 1
        for (int k2 = 0; k2 < 25; k2++) {
            int px = pxb + 32 * k2;
            int r = px / 40, c0 = px - r * 40;
            int pp = (r + 1) * 44 + (c0 + 1);
            float a0 = 0.f, a1 = 0.f;
#pragma unroll
            for (int t = 0; t < 9; t++) {
                float zv = sZf[pp + c_dtap[t]];
                a0 += wr[2 * t] * zv;
                a1 += wr[2 * t + 1] * zv;
            }
            a0 = fmaxf(a0, 0.f);
            a1 = fmaxf(a1, 0.f);
            uint32_t hi = cvt2bf(a1, a0);
            float h0 = __uint_as_float(hi << 16);
            float h1 = __uint_as_float(hi & 0xFFFF0000u);
            uint32_t lo = cvt2bf(a1 - h1, a0 - h0);
            int base = (SROW0 + pp) * ASTRIDE + qq;
            sAhi[base] = hi;
            sAlo[base] = lo;
        }
    }
    __syncthreads();

    int warp = tid >> 5, lane = tid & 31;
    int q = lane >> 2, c = lane & 3;
    uint32_t* oh = xh + (size_t)img * XSTRIDE;
    uint32_t* ol = xl + (size_t)img * XSTRIDE;

    int u1 = warp, u2 = warp + 16;
    bool has2 = (u2 < 31);
    int r1 = SROW0 + u1 * 32;
    int r2 = SROW0 + (has2 ? u2 : u1) * 32;

    float acc1[2][4][4], acc2[2][4][4];
    conv_mma_loop(sAhi, sAlo, sBhi, sBlo, r1, r2, has2, q, c, acc1, acc2);

#pragma unroll
    for (int uu = 0; uu < 2; uu++) {
        if (uu == 1 && !has2) break;
        int u = uu ? u2 : u1;
        float (*acc)[4][4] = uu ? acc2 : acc1;
#pragma unroll
        for (int s = 0; s < 2; s++) {
            int grow0 = u * 32 + s * 16 + q;
#pragma unroll
            for (int half = 0; half < 2; half++) {
                int grow = grow0 + half * 8;
                int rr = grow / 44, cc = grow - rr * 44;
                bool valid = (grow < NROWS) && rr >= 1 && rr <= 20 && cc >= 1 && cc <= 40;
                if (valid) {
                    int wbase = grow * 16 + c;
#pragma unroll
                    for (int o = 0; o < 4; o++) {
                        float x0 = acc[s][o][half * 2 + 0];
                        float x1 = acc[s][o][half * 2 + 1];
                        uint32_t hi = cvt2bf(x1, x0);
                        float h0 = __uint_as_float(hi << 16);
                        float h1 = __uint_as_float(hi & 0xFFFF0000u);
                        uint32_t lo = cvt2bf(x1 - h1, x0 - h0);
                        oh[wbase + o * 4] = hi;
                        ol[wbase + o * 4] = lo;
                    }
                }
            }
        }
    }
}

// t1 + t2 fused, reading pre-split x_fwd. S-plane epilogue replaces the
// fp32 smem feature tile: S_t computed from registers, 9-read gather per px.
__global__ __launch_bounds__(512) void conv32_t1t2(const uint32_t* __restrict__ xh,
                                                   const uint32_t* __restrict__ xl,
                                                   const uint32_t* __restrict__ wpk,
                                                   const float* __restrict__ thr_arr,
                                                   int layer,
                                                   float* __restrict__ Zout,
                                                   float* __restrict__ Sout,
                                                   const float* __restrict__ zf,
                                                   float* __restrict__ Ln,
                                                   const float* __restrict__ Lc,
                                                   const float* __restrict__ Lp,
                                                   const float* __restrict__ Xn,
                                                   const float* __restrict__ h_arr,
                                                   const float* __restrict__ b1_arr,
                                                   const float* __restrict__ tL_arr,
                                                   const float* __restrict__ w288)
{
    extern __shared__ uint32_t smw[];
    uint32_t* sAhi = smw;
    uint32_t* sAlo = smw + SROWS * ASTRIDE;
    uint32_t* sBhi = smw + 2 * SROWS * ASTRIDE;
    uint32_t* sBlo = sBhi + BWORDS;
    float* sWc = (float*)(sBlo + BWORDS);       // 288 ([tap][ic])
    float* sS = (float*)smw;                    // S planes overlay A region (9*NROWS)
    int img = blockIdx.x, tid = threadIdx.x;

    for (int i = tid; i < BWORDS; i += 512) { sBhi[i] = wpk[i]; sBlo[i] = wpk[BWORDS + i]; }
    for (int i = tid; i < 288; i += 512) {
        int ic = i / 9, tap = i - ic * 9;
        sWc[tap * 32 + ic] = w288[i];
    }

    float sthr = fabsf(thr_arr[layer]);
    fill_from_split(sAhi, sAlo, xh, xl, img, tid, 1, sthr);
    __syncthreads();

    int warp = tid >> 5, lane = tid & 31;
    int q = lane >> 2, c = lane & 3;
    int u1 = warp, u2 = warp + 16;
    bool has2 = (u2 < 31);
    int r1 = SROW0 + u1 * 32;
    int r2 = SROW0 + (has2 ? u2 : u1) * 32;
    size_t base = (size_t)img * NN;

    float acc1[2][4][4], acc2[2][4][4];

    // ============ t1 ============
    conv_mma_loop(sAhi, sAlo, sBhi, sBlo, r1, r2, has2, q, c, acc1, acc2);
    __syncthreads();   // all mma reads of sA done; S overlays it now

    {
        float4 z = make_float4(0.f, 0.f, 0.f, 0.f);
        for (int i = tid; i < (9 * NROWS) / 4; i += 512) ((float4*)sS)[i] = z;
    }
    __syncthreads();
    conv_s_planes(sS, sWc, acc1, acc2, u1, u2, has2, q, c);
    __syncthreads();

    for (int p = tid; p < NN; p += 512) {
        int r = p / 40, c0 = p - r * 40;
        int pp = (r + 1) * 44 + (c0 + 1);
        float acc = 0.f;
#pragma unroll
        for (int t = 0; t < 9; t++)
            acc += sS[t * NROWS + pp + c_dtap[t]];
        Zout[base + p] = acc;
        float lc = Lc[base + p], lp = Lp[base + p];
        float hatL = lc + tL_arr[layer] * (lc - lp);
        Ln[base + p] = hatL + h_arr[layer] * b1_arr[layer] * (Xn[base + p] - acc);
    }
    __syncthreads();   // gather done before refill overwrites the overlay

    // ============ t2 ============
    fill_from_split(sAhi, sAlo, xh, xl, img, tid, 0, 0.f);
    __syncthreads();

    conv_mma_loop(sAhi, sAlo, sBhi, sBlo, r1, r2, has2, q, c, acc1, acc2);
    __syncthreads();

    {
        float4 z = make_float4(0.f, 0.f, 0.f, 0.f);
        for (int i = tid; i < (9 * NROWS) / 4; i += 512) ((float4*)sS)[i] = z;
    }
    __syncthreads();
    conv_s_planes(sS, sWc, acc1, acc2, u1, u2, has2, q, c);
    __syncthreads();

    for (int p = tid; p < NN; p += 512) {
        int r = p / 40, c0 = p - r * 40;
        int pp = (r + 1) * 44 + (c0 + 1);
        float acc = 0.f;
#pragma unroll
        for (int t = 0; t < 9; t++)
            acc += sS[t * NROWS + pp + c_dtap[t]];
        Sout[base + p] = acc - zf[base + p];
    }
}

// ---------------- host ----------------

extern "C" void kernel_launch(void* const* d_in, const int* in_sizes, int n_in,
                              void* d_out, int out_size)
{
    const float* y    = (const float*)d_in[0];
    const float* W    = (const float*)d_in[2];
    const float* beta1 = (const float*)d_in[3];
    const float* beta2 = (const float*)d_in[4];
    const float* h_   = (const float*)d_in[5];
    const float* sthr = (const float*)d_in[6];
    const float* thx  = (const float*)d_in[7];
    const float* thz  = (const float*)d_in[8];
    const float* thL  = (const float*)d_in[9];
    const float* c1f  = (const float*)d_in[10];
    const float* c2f  = (const float*)d_in[11];
    const float* c1b  = (const float*)d_in[12];
    const float* c2b  = (const float*)d_in[13];

    float* out = (float*)d_out;
    float* Zs = out;
    float* syms = out + (size_t)9 * NB;
    float* wlo = out + (size_t)18 * NB;

    float *pPhiTPhi, *pPhiTb, *pX, *pL, *pZero, *pZf;
    uint32_t *pWPK, *pXH, *pXL;
    cudaGetSymbolAddress((void**)&pPhiTPhi, g_PhiTPhi);
    cudaGetSymbolAddress((void**)&pPhiTb, g_PhiTb);
    cudaGetSymbolAddress((void**)&pX, g_Xbuf);
    cudaGetSymbolAddress((void**)&pL, g_Lbuf);
    cudaGetSymbolAddress((void**)&pZero, g_zerobuf);
    cudaGetSymbolAddress((void**)&pZf, g_zflat);
    cudaGetSymbolAddress((void**)&pXH, g_xh);
    cudaGetSymbolAddress((void**)&pXL, g_xl);
    cudaGetSymbolAddress((void**)&pWPK, g_wpk);

    const int SMMAW = (2 * SROWS * ASTRIDE + 2 * BWORDS + NROWS + 288) * 4;  // 224,864 B
    cudaFuncSetAttribute(conv32_fwd, cudaFuncAttributeMaxDynamicSharedMemorySize, SMMAW);
    cudaFuncSetAttribute(conv32_t1t2, cudaFuncAttributeMaxDynamicSharedMemorySize, SMMAW);

    cudaMemsetAsync(pZero, 0, (size_t)NB * 4);

    float* Xslot[3] = {pX, pX + NB, pX + 2 * (size_t)NB};
    float* Lslot[2] = {pL, pL + NB};

    k_prep<<<WBF_BLOCKS, 128>>>(c2f, c1b, pWPK);
    gemm_mma<<<dim3(7, 32), 512>>>(y, W, pPhiTb, BB, MM, NN);

    int xcur = 0, xprev = -1;
    int lcur = 0, lprev = -1;

    for (int i = 0; i < 9; i++) {
        float* Xn;
        if (i == 0) {
            Xn = Xslot[0];
            k_layer0<<<NB / 256, 256>>>(pPhiTb, Xn, pZf, h_, beta2);
            xcur = 0; xprev = -1;
        } else {
            const float* Xc = Xslot[xcur];
            const float* Xp = (xprev < 0) ? pZero : Xslot[xprev];
            const float* Lc_ = Lslot[lcur];
            const float* Zc = Zs + (size_t)(i - 1) * NB;
            const float* Zp = (i >= 2) ? Zs + (size_t)(i - 2) * NB : pZero;
            const float* Zg = (i >= 2) ? Zc : pZero;
            const float* Lg = (i >= 2) ? Lc_ : pZero;
            const float* Lz = (i >= 2) ? Lc_ : pZero;
            int xnew = (xprev < 0) ? 1 : (3 - xcur - xprev);
            Xn = Xslot[xnew];
            gemm_xstep<<<dim3(7, 32), 512>>>(Xc, Xp, pPhiTPhi,
                                             pPhiTb, Zg, Lg, Zc, Zp, Lz,
                                             Xn, pZf,
                                             beta1, beta2, h_, thz, thx, i);
            xprev = xcur; xcur = xnew;
        }

        conv32_fwd<<<BB, 512, SMMAW>>>(pWPK, pXH, pXL, c1f, pZf);

        {
            const float* Lc_ = (i == 0) ? pZero : Lslot[lcur];
            const float* Lp_ = (i == 0) ? pZero : ((lprev < 0) ? pZero : Lslot[lprev]);
            int lnew = (i == 0) ? 0 : ((lprev < 0) ? 1 : lprev);
            conv32_t1t2<<<BB, 512, SMMAW>>>(pXH, pXL, pWPK + 2 * BWORDS, sthr, i,
                                            Zs + (size_t)i * NB,
                                            syms + (size_t)i * NB, pZf,
                                            Lslot[lnew], Lc_, Lp_, Xn,
                                            h_, beta1, thL, c2b);
            if (i > 0) { lprev = lcur; lcur = lnew; }
            else { lcur = 0; lprev = -1; }
        }

        if (i == 0) {
            gemm_AtB<<<dim3(13, 13), 256>>>(W, W, pPhiTPhi, MM, NN, NN);
        }
    }

    k_wloss<<<dim3(21, 21), dim3(16, 16)>>>(W, wlo);
}